// round 1
// baseline (speedup 1.0000x reference)
#include <cuda_runtime.h>
#include <math.h>

#define C_DIM 768
#define T_DIM 1024
#define B_DIM 8
#define H_NUM 12
#define HD    64
#define M_TOT 8192
#define S_ELE 6291456   /* 8*1024*768 */

// Scratch (device globals: allocation-free per harness rules)
static __device__ float g_q [S_ELE];  // raw q, (B,T,C)
static __device__ float g_k [S_ELE];  // raw k, (B,T,C)
static __device__ float g_qr[S_ELE];  // rope+norm q, (B,H,T,Hd)
static __device__ float g_y [S_ELE];  // attention out, (B,T,C)

// ---------------------------------------------------------------------------
// Tiled fp32 GEMM core: C[m,n] = sum_k A[m,k] * W[n,k]   (both K-major)
// BM=BN=128, BK=16, 256 threads, 8x8 per-thread micro tile.
// ---------------------------------------------------------------------------
#define BM 128
#define BN 128
#define BK 16

__device__ __forceinline__ void gemm_core(const float* __restrict__ A,
                                          const float* __restrict__ W,
                                          float acc[8][8], int m0, int n0,
                                          float (*As)[BM], float (*Bs)[BN])
{
    const int tid  = threadIdx.x;
    const int arow = tid >> 2;         // 0..63
    const int ac4  = (tid & 3) << 2;   // 0,4,8,12
    const int ty   = tid >> 4;
    const int tx   = tid & 15;

    for (int k0 = 0; k0 < C_DIM; k0 += BK) {
#pragma unroll
        for (int rr = 0; rr < 2; rr++) {
            int r = arow + rr * 64;
            float4 av = *(const float4*)(A + (size_t)(m0 + r) * C_DIM + k0 + ac4);
            As[ac4 + 0][r] = av.x; As[ac4 + 1][r] = av.y;
            As[ac4 + 2][r] = av.z; As[ac4 + 3][r] = av.w;
            float4 bv = *(const float4*)(W + (size_t)(n0 + r) * C_DIM + k0 + ac4);
            Bs[ac4 + 0][r] = bv.x; Bs[ac4 + 1][r] = bv.y;
            Bs[ac4 + 2][r] = bv.z; Bs[ac4 + 3][r] = bv.w;
        }
        __syncthreads();
#pragma unroll
        for (int kk = 0; kk < BK; kk++) {
            float a[8], b[8];
#pragma unroll
            for (int i = 0; i < 8; i++) a[i] = As[kk][ty * 8 + i];
#pragma unroll
            for (int j = 0; j < 8; j++) b[j] = Bs[kk][tx * 8 + j];
#pragma unroll
            for (int i = 0; i < 8; i++)
#pragma unroll
                for (int j = 0; j < 8; j++)
                    acc[i][j] = fmaf(a[i], b[j], acc[i][j]);
        }
        __syncthreads();
    }
}

// ---------------------------------------------------------------------------
// QKV projection: z=0 -> g_q (BTC), z=1 -> g_k (BTC), z=2 -> v_out (BHTD)
// ---------------------------------------------------------------------------
__global__ void qkv_gemm(const float* __restrict__ x,
                         const float* __restrict__ Wq,
                         const float* __restrict__ Wk,
                         const float* __restrict__ Wv,
                         float* __restrict__ v_out)
{
    __shared__ float As[BK][BM];
    __shared__ float Bs[BK][BN];
    float acc[8][8] = {};

    const int m0 = blockIdx.y * BM;
    const int n0 = blockIdx.x * BN;
    const int z  = blockIdx.z;
    const float* W = (z == 0) ? Wq : (z == 1) ? Wk : Wv;

    gemm_core(x, W, acc, m0, n0, As, Bs);

    const int ty = threadIdx.x >> 4, tx = threadIdx.x & 15;
#pragma unroll
    for (int i = 0; i < 8; i++) {
        const int m = m0 + ty * 8 + i;
#pragma unroll
        for (int j = 0; j < 8; j++) {
            const int n = n0 + tx * 8 + j;
            const float v = acc[i][j];
            if (z == 0) {
                g_q[(size_t)m * C_DIM + n] = v;
            } else if (z == 1) {
                g_k[(size_t)m * C_DIM + n] = v;
            } else {
                const int b = m >> 10, t = m & (T_DIM - 1);
                const int h = n >> 6,  hd = n & (HD - 1);
                v_out[(((size_t)(b * H_NUM + h)) * T_DIM + t) * HD + hd] = v;
            }
        }
    }
}

// ---------------------------------------------------------------------------
// Output projection: y = g_y @ Wo^T -> y_out (BTC)
// ---------------------------------------------------------------------------
__global__ void proj_gemm(const float* __restrict__ Wo, float* __restrict__ y_out)
{
    __shared__ float As[BK][BM];
    __shared__ float Bs[BK][BN];
    float acc[8][8] = {};

    const int m0 = blockIdx.y * BM;
    const int n0 = blockIdx.x * BN;
    gemm_core(g_y, Wo, acc, m0, n0, As, Bs);

    const int ty = threadIdx.x >> 4, tx = threadIdx.x & 15;
#pragma unroll
    for (int i = 0; i < 8; i++)
#pragma unroll
        for (int j = 0; j < 8; j++)
            y_out[(size_t)(m0 + ty * 8 + i) * C_DIM + n0 + tx * 8 + j] = acc[i][j];
}

// ---------------------------------------------------------------------------
// RoPE + qk RMSNorm. One warp per (b,h,t) vector of 64; lane owns pair (j, j+32).
// blockIdx.y: 0 -> q (g_q -> g_qr BHTD), 1 -> k (g_k -> k_out BHTD)
// ---------------------------------------------------------------------------
__global__ void rope_norm_kernel(float* __restrict__ k_out)
{
    const int lane = threadIdx.x & 31;
    const int vec  = blockIdx.x * 8 + (threadIdx.x >> 5);   // 0 .. B*H*T-1
    const int t  = vec & (T_DIM - 1);
    const int bh = vec >> 10;
    const int b  = bh / H_NUM;
    const int h  = bh - b * H_NUM;
    const bool is_q = (blockIdx.y == 0);

    const float* src = (is_q ? g_q : g_k) +
                       ((size_t)(b * T_DIM + t)) * C_DIM + h * HD;
    const float x1 = src[lane];
    const float x2 = src[lane + 32];

    // inv_freq = 10000^(-lane/32) computed in double for stability
    const float inv = (float)exp((double)lane * -0.28782313662425575); // -ln(1e4)/32
    const float f = (float)t * inv;
    float s, c;
    sincosf(f, &s, &c);
    const float o1 = x1 * c - x2 * s;
    const float o2 = x1 * s + x2 * c;

    float ss = o1 * o1 + o2 * o2;
#pragma unroll
    for (int off = 16; off; off >>= 1)
        ss += __shfl_xor_sync(0xffffffffu, ss, off);
    const float rn = rsqrtf(ss * (1.0f / 64.0f) + 1e-6f);

    float* dst = (is_q ? g_qr : k_out) + ((size_t)bh * T_DIM + t) * HD;
    dst[lane]      = o1 * rn;
    dst[lane + 32] = o2 * rn;
}

// ---------------------------------------------------------------------------
// Flash attention (fp32, causal). 64 q-rows per block, 64-wide K/V tiles.
// 128 threads: warp w, lane = rg*8+cg; thread owns rows r0..r0+3, col lanes
// cg, cg+8, ..., cg+56 (strided -> conflict-free smem reads).
// K smem buffer is reused to hold P between the two GEMMs.
// ---------------------------------------------------------------------------
__global__ void attn_kernel(const float* __restrict__ Kn,
                            const float* __restrict__ Vn)
{
    extern __shared__ float sm[];
    float (*Qs)[65]  = (float(*)[65])(sm);
    float (*KPs)[65] = (float(*)[65])(sm + 64 * 65);
    float (*Vs)[65]  = (float(*)[65])(sm + 2 * 64 * 65);

    const int qt = blockIdx.x;          // 0..15
    const int bh = blockIdx.y;          // 0..95
    const int b  = bh / H_NUM;
    const int h  = bh - b * H_NUM;
    const int tid  = threadIdx.x;
    const int lane = tid & 31;
    const int w    = tid >> 5;
    const int rg   = lane >> 3;
    const int cg   = lane & 7;
    const int r0   = w * 16 + rg * 4;
    const int q0   = qt * 64;

    const float* Qb = g_qr + ((size_t)bh * T_DIM + q0) * HD;
    const float* Kb = Kn + (size_t)bh * T_DIM * HD;
    const float* Vb = Vn + (size_t)bh * T_DIM * HD;

#pragma unroll
    for (int it = 0; it < 8; it++) {
        int idx = tid + it * 128;
        int r = idx >> 4, c4 = (idx & 15) << 2;
        float4 qv = *(const float4*)(Qb + r * HD + c4);
        Qs[r][c4] = qv.x; Qs[r][c4 + 1] = qv.y; Qs[r][c4 + 2] = qv.z; Qs[r][c4 + 3] = qv.w;
    }

    float m_i[4], l_i[4], acc[4][8];
#pragma unroll
    for (int i = 0; i < 4; i++) {
        m_i[i] = -INFINITY; l_i[i] = 0.0f;
#pragma unroll
        for (int dd = 0; dd < 8; dd++) acc[i][dd] = 0.0f;
    }

    for (int kt = 0; kt <= qt; kt++) {
        const int k0 = kt * 64;
        __syncthreads();   // previous iteration done with KPs/Vs
#pragma unroll
        for (int it = 0; it < 8; it++) {
            int idx = tid + it * 128;
            int r = idx >> 4, c4 = (idx & 15) << 2;
            float4 kv = *(const float4*)(Kb + (size_t)(k0 + r) * HD + c4);
            KPs[r][c4] = kv.x; KPs[r][c4 + 1] = kv.y; KPs[r][c4 + 2] = kv.z; KPs[r][c4 + 3] = kv.w;
            float4 vv = *(const float4*)(Vb + (size_t)(k0 + r) * HD + c4);
            Vs[r][c4] = vv.x; Vs[r][c4 + 1] = vv.y; Vs[r][c4 + 2] = vv.z; Vs[r][c4 + 3] = vv.w;
        }
        __syncthreads();

        // S = Q @ K^T
        float sv[4][8];
#pragma unroll
        for (int i = 0; i < 4; i++)
#pragma unroll
            for (int j = 0; j < 8; j++) sv[i][j] = 0.0f;

        for (int d = 0; d < 64; d++) {
            float qr_[4], kr_[8];
#pragma unroll
            for (int i = 0; i < 4; i++) qr_[i] = Qs[r0 + i][d];
#pragma unroll
            for (int j = 0; j < 8; j++) kr_[j] = KPs[cg + j * 8][d];
#pragma unroll
            for (int i = 0; i < 4; i++)
#pragma unroll
                for (int j = 0; j < 8; j++)
                    sv[i][j] = fmaf(qr_[i], kr_[j], sv[i][j]);
        }

        // scale + causal mask (only the diagonal tile needs masking)
        const bool diag = (kt == qt);
#pragma unroll
        for (int i = 0; i < 4; i++)
#pragma unroll
            for (int j = 0; j < 8; j++) {
                float s = sv[i][j] * 0.125f;
                if (diag && (cg + j * 8 > r0 + i)) s = -INFINITY;
                sv[i][j] = s;
            }

        // online softmax update
#pragma unroll
        for (int i = 0; i < 4; i++) {
            float rm = sv[i][0];
#pragma unroll
            for (int j = 1; j < 8; j++) rm = fmaxf(rm, sv[i][j]);
            rm = fmaxf(rm, __shfl_xor_sync(0xffffffffu, rm, 1));
            rm = fmaxf(rm, __shfl_xor_sync(0xffffffffu, rm, 2));
            rm = fmaxf(rm, __shfl_xor_sync(0xffffffffu, rm, 4));

            const float mnew = fmaxf(m_i[i], rm);
            const float corr = expf(m_i[i] - mnew);
            m_i[i] = mnew;
            l_i[i] *= corr;
#pragma unroll
            for (int dd = 0; dd < 8; dd++) acc[i][dd] *= corr;

            float rs = 0.0f;
#pragma unroll
            for (int j = 0; j < 8; j++) {
                float p = expf(sv[i][j] - mnew);
                sv[i][j] = p;
                rs += p;
            }
            rs += __shfl_xor_sync(0xffffffffu, rs, 1);
            rs += __shfl_xor_sync(0xffffffffu, rs, 2);
            rs += __shfl_xor_sync(0xffffffffu, rs, 4);
            l_i[i] += rs;
        }

        __syncthreads();   // done reading KPs as K
#pragma unroll
        for (int i = 0; i < 4; i++)
#pragma unroll
            for (int j = 0; j < 8; j++)
                KPs[r0 + i][cg + j * 8] = sv[i][j];
        __syncthreads();

        // O += P @ V
        for (int j2 = 0; j2 < 64; j2++) {
            float pr[4], vr[8];
#pragma unroll
            for (int i = 0; i < 4; i++) pr[i] = KPs[r0 + i][j2];
#pragma unroll
            for (int dd = 0; dd < 8; dd++) vr[dd] = Vs[j2][cg + dd * 8];
#pragma unroll
            for (int i = 0; i < 4; i++)
#pragma unroll
                for (int dd = 0; dd < 8; dd++)
                    acc[i][dd] = fmaf(pr[i], vr[dd], acc[i][dd]);
        }
    }

    // normalize + write to g_y in (B,T,C)
    float* Yb = g_y + ((size_t)b * T_DIM + q0) * C_DIM + (size_t)h * HD;
#pragma unroll
    for (int i = 0; i < 4; i++) {
        const float invl = 1.0f / l_i[i];
#pragma unroll
        for (int dd = 0; dd < 8; dd++)
            Yb[(size_t)(r0 + i) * C_DIM + cg + dd * 8] = acc[i][dd] * invl;
    }
}

// ---------------------------------------------------------------------------
extern "C" void kernel_launch(void* const* d_in, const int* in_sizes, int n_in,
                              void* d_out, int out_size)
{
    const float* x  = (const float*)d_in[0];
    const float* Wq = (const float*)d_in[1];
    const float* Wk = (const float*)d_in[2];
    const float* Wv = (const float*)d_in[3];
    const float* Wo = (const float*)d_in[4];

    float* out   = (float*)d_out;
    float* y_out = out;                 // (B,T,C)
    float* k_out = out + S_ELE;         // (B,H,T,Hd)
    float* v_out = out + 2 * (size_t)S_ELE; // (B,H,T,Hd)

    // 1) QKV projections
    dim3 g1(C_DIM / BN, M_TOT / BM, 3);
    qkv_gemm<<<g1, 256>>>(x, Wq, Wk, Wv, v_out);

    // 2) RoPE + RMSNorm on q and k
    rope_norm_kernel<<<dim3((B_DIM * H_NUM * T_DIM) / 8, 2), 256>>>(k_out);

    // 3) causal flash attention
    const size_t smem = 3 * 64 * 65 * sizeof(float);
    cudaFuncSetAttribute(attn_kernel, cudaFuncAttributeMaxDynamicSharedMemorySize,
                         (int)smem);
    attn_kernel<<<dim3(T_DIM / 64, B_DIM * H_NUM), 128, smem>>>(k_out, v_out);

    // 4) output projection
    proj_gemm<<<dim3(C_DIM / BN, M_TOT / BM), 256>>>(Wo, y_out);
}

// round 3
// speedup vs baseline: 1.2876x; 1.2876x over previous
#include <cuda_runtime.h>
#include <cuda_bf16.h>
#include <math.h>
#include <stdint.h>

#define C_DIM 768
#define T_DIM 1024
#define B_DIM 8
#define H_NUM 12
#define HD    64
#define M_TOT 8192
#define S_ELE 6291456   /* 8*1024*768 */

// Scratch (device globals: allocation-free per harness rules)
static __device__ float g_q [S_ELE];  // raw q, (B,T,C)
static __device__ float g_k [S_ELE];  // raw k, (B,T,C)
static __device__ float g_qr[S_ELE];  // rope+norm q, (B,H,T,Hd)
static __device__ float g_y [S_ELE];  // attention out, (B,T,C)

__device__ __forceinline__ uint32_t smem_u32(const void* p) {
    uint32_t a;
    asm("{ .reg .u64 t; cvta.to.shared.u64 t, %1; cvt.u32.u64 %0, t; }"
        : "=r"(a) : "l"(p));
    return a;
}
__device__ __forceinline__ uint32_t pack_bf2(float lo, float hi) {
    __nv_bfloat16 a = __float2bfloat16(lo);
    __nv_bfloat16 b = __float2bfloat16(hi);
    return ((uint32_t)__bfloat16_as_ushort(b) << 16) | __bfloat16_as_ushort(a);
}
__device__ __forceinline__ void ldmx4(uint32_t& r0, uint32_t& r1,
                                      uint32_t& r2, uint32_t& r3, uint32_t addr) {
    asm volatile("ldmatrix.sync.aligned.m8n8.x4.shared.b16 {%0,%1,%2,%3}, [%4];"
                 : "=r"(r0), "=r"(r1), "=r"(r2), "=r"(r3) : "r"(addr));
}
__device__ __forceinline__ void mma_bf16(float* c, const uint32_t* a,
                                         const uint32_t* b) {
    asm volatile(
        "mma.sync.aligned.m16n8k16.row.col.f32.bf16.bf16.f32 "
        "{%0,%1,%2,%3},{%4,%5,%6,%7},{%8,%9},{%0,%1,%2,%3};"
        : "+f"(c[0]), "+f"(c[1]), "+f"(c[2]), "+f"(c[3])
        : "r"(a[0]), "r"(a[1]), "r"(a[2]), "r"(a[3]), "r"(b[0]), "r"(b[1]));
}

// ===========================================================================
// bf16 hi/lo split GEMM: C[m,n] = sum_k A[m,k]*W[n,k]
// 128x128 CTA tile, 8 warps (2 x 4), per-warp 64x32, K chunks of 32.
// Smem planes (bf16, 64B rows, swizzled): Ah, Al, Bh, Bl; double buffered.
// modes: 0 -> g_q (BTC), 1 -> g_k (BTC), 2 -> dst (v, BHTD), 3 -> dst (y, BTC)
// ===========================================================================
#define NCHUNK 24
#define PLANE  8192      /* 128 rows * 64 bytes */
#define STAGE  32768
#define GSMEM  (2*STAGE + 1024)

// swizzled byte offset within a plane for (row, kcol4) where kcol4 = 4-elem group
__device__ __forceinline__ uint32_t swz(int row, int c4) {
    int seg = c4 >> 3;                       // 16B segment index (0..3)
    int slot = seg ^ ((row >> 1) & 3);
    return (uint32_t)(row * 64 + slot * 16 + ((c4 & 4) << 1));
}

__global__ __launch_bounds__(256, 1)
void split_gemm(const float* __restrict__ Ain,
                const float* __restrict__ W0, const float* __restrict__ W1,
                const float* __restrict__ W2,
                float* __restrict__ dst, int is_qkv)
{
    extern __shared__ unsigned char sm8[];
    const int tid  = threadIdx.x;
    const int lane = tid & 31;
    const int wid  = tid >> 5;
    const int wm   = wid >> 2;      // 0..1
    const int wn   = wid & 3;       // 0..3

    const int n0 = blockIdx.x * 128;
    const int m0 = blockIdx.y * 128;
    int mode;
    const float* A;
    const float* W;
    if (is_qkv) {
        mode = blockIdx.z;
        A = Ain;
        W = (mode == 0) ? W0 : (mode == 1) ? W1 : W2;
    } else {
        mode = 3;
        A = g_y;                    // device-side select (host can't pass g_y)
        W = W0;
    }

    uint32_t base = (smem_u32(sm8) + 1023u) & ~1023u;

    const float* Arow = A + (size_t)m0 * C_DIM;
    const float* Wrow = W + (size_t)n0 * C_DIM;

    float4 aR[4], bR[4];
    const int ldr = tid >> 3;            // row 0..31 (of 128? no: idx>>3 below)
    (void)ldr;

    // accumulators: [mt][nt][4]
    float acc[16][4];
#pragma unroll
    for (int i = 0; i < 16; i++)
#pragma unroll
        for (int j = 0; j < 4; j++) acc[i][j] = 0.0f;

    // prologue LDG chunk 0
#pragma unroll
    for (int i = 0; i < 4; i++) {
        int idx = tid + i * 256;
        int r = idx >> 3, c4 = (idx & 7) << 2;
        aR[i] = *(const float4*)(Arow + (size_t)r * C_DIM + c4);
        bR[i] = *(const float4*)(Wrow + (size_t)r * C_DIM + c4);
    }

    for (int c = 0; c < NCHUNK; c++) {
        const uint32_t st = base + (uint32_t)(c & 1) * STAGE;
        // convert + store to smem
#pragma unroll
        for (int i = 0; i < 4; i++) {
            int idx = tid + i * 256;
            int r = idx >> 3, c4 = (idx & 7) << 2;
            uint32_t off = swz(r, c4);

            float4 a = aR[i];
            float hx = __bfloat162float(__float2bfloat16(a.x));
            float hy = __bfloat162float(__float2bfloat16(a.y));
            float hz = __bfloat162float(__float2bfloat16(a.z));
            float hw = __bfloat162float(__float2bfloat16(a.w));
            uint32_t ah0 = pack_bf2(hx, hy), ah1 = pack_bf2(hz, hw);
            uint32_t al0 = pack_bf2(a.x - hx, a.y - hy);
            uint32_t al1 = pack_bf2(a.z - hz, a.w - hw);
            asm volatile("st.shared.v2.b32 [%0], {%1,%2};" ::
                         "r"(st + off), "r"(ah0), "r"(ah1) : "memory");
            asm volatile("st.shared.v2.b32 [%0], {%1,%2};" ::
                         "r"(st + PLANE + off), "r"(al0), "r"(al1) : "memory");

            float4 b = bR[i];
            float gx = __bfloat162float(__float2bfloat16(b.x));
            float gy = __bfloat162float(__float2bfloat16(b.y));
            float gz = __bfloat162float(__float2bfloat16(b.z));
            float gw = __bfloat162float(__float2bfloat16(b.w));
            uint32_t bh0 = pack_bf2(gx, gy), bh1 = pack_bf2(gz, gw);
            uint32_t bl0 = pack_bf2(b.x - gx, b.y - gy);
            uint32_t bl1 = pack_bf2(b.z - gz, b.w - gw);
            asm volatile("st.shared.v2.b32 [%0], {%1,%2};" ::
                         "r"(st + 2 * PLANE + off), "r"(bh0), "r"(bh1) : "memory");
            asm volatile("st.shared.v2.b32 [%0], {%1,%2};" ::
                         "r"(st + 3 * PLANE + off), "r"(bl0), "r"(bl1) : "memory");
        }
        __syncthreads();

        // prefetch next chunk while computing
        if (c + 1 < NCHUNK) {
            const int k0 = (c + 1) * 32;
#pragma unroll
            for (int i = 0; i < 4; i++) {
                int idx = tid + i * 256;
                int r = idx >> 3, c4 = (idx & 7) << 2;
                aR[i] = *(const float4*)(Arow + (size_t)r * C_DIM + k0 + c4);
                bR[i] = *(const float4*)(Wrow + (size_t)r * C_DIM + k0 + c4);
            }
        }

#pragma unroll
        for (int ks = 0; ks < 2; ks++) {
            // B fragments: [nt][2] for hi and lo
            uint32_t bh[4][2], bl[4][2];
#pragma unroll
            for (int g = 0; g < 2; g++) {
                int row = wn * 32 + g * 16 + (lane & 15);
                int c4 = (2 * ks + (lane >> 4)) * 8;   // 16B segment -> c4 units
                uint32_t off = swz(row, c4);
                uint32_t r0, r1, r2, r3;
                ldmx4(r0, r1, r2, r3, st + 2 * PLANE + off);
                bh[2 * g][0] = r0; bh[2 * g + 1][0] = r1;
                bh[2 * g][1] = r2; bh[2 * g + 1][1] = r3;
                ldmx4(r0, r1, r2, r3, st + 3 * PLANE + off);
                bl[2 * g][0] = r0; bl[2 * g + 1][0] = r1;
                bl[2 * g][1] = r2; bl[2 * g + 1][1] = r3;
            }
#pragma unroll
            for (int mt = 0; mt < 4; mt++) {
                int row = wm * 64 + mt * 16 + (lane & 15);
                int c4 = (2 * ks + (lane >> 4)) * 8;
                uint32_t off = swz(row, c4);
                uint32_t ah[4], al[4];
                ldmx4(ah[0], ah[1], ah[2], ah[3], st + off);
                ldmx4(al[0], al[1], al[2], al[3], st + PLANE + off);
#pragma unroll
                for (int nt = 0; nt < 4; nt++) {
                    mma_bf16(acc[mt * 4 + nt], ah, bh[nt]);
                    mma_bf16(acc[mt * 4 + nt], ah, bl[nt]);
                    mma_bf16(acc[mt * 4 + nt], al, bh[nt]);
                }
            }
        }
        __syncthreads();
    }

    // epilogue
#pragma unroll
    for (int mt = 0; mt < 4; mt++) {
#pragma unroll
        for (int nt = 0; nt < 4; nt++) {
            const float* cc = acc[mt * 4 + nt];
            int r  = m0 + wm * 64 + mt * 16 + (lane >> 2);
            int cl = n0 + wn * 32 + nt * 8 + ((lane & 3) << 1);
#pragma unroll
            for (int h2 = 0; h2 < 2; h2++) {
                int rr = r + h2 * 8;
                float2 v = make_float2(cc[h2 * 2], cc[h2 * 2 + 1]);
                if (mode == 0) {
                    *(float2*)(g_q + (size_t)rr * C_DIM + cl) = v;
                } else if (mode == 1) {
                    *(float2*)(g_k + (size_t)rr * C_DIM + cl) = v;
                } else if (mode == 3) {
                    *(float2*)(dst + (size_t)rr * C_DIM + cl) = v;
                } else {
                    const int bb = rr >> 10, t = rr & (T_DIM - 1);
                    const int h = cl >> 6, hd0 = cl & (HD - 1);
                    *(float2*)(dst + (((size_t)(bb * H_NUM + h)) * T_DIM + t) * HD + hd0) = v;
                }
            }
        }
    }
}

// ---------------------------------------------------------------------------
// RoPE + qk RMSNorm (unchanged from R1)
// ---------------------------------------------------------------------------
__global__ void rope_norm_kernel(float* __restrict__ k_out)
{
    const int lane = threadIdx.x & 31;
    const int vec  = blockIdx.x * 8 + (threadIdx.x >> 5);
    const int t  = vec & (T_DIM - 1);
    const int bh = vec >> 10;
    const int b  = bh / H_NUM;
    const int h  = bh - b * H_NUM;
    const bool is_q = (blockIdx.y == 0);

    const float* src = (is_q ? g_q : g_k) +
                       ((size_t)(b * T_DIM + t)) * C_DIM + h * HD;
    const float x1 = src[lane];
    const float x2 = src[lane + 32];

    const float inv = (float)exp((double)lane * -0.28782313662425575);
    const float f = (float)t * inv;
    float s, c;
    sincosf(f, &s, &c);
    const float o1 = x1 * c - x2 * s;
    const float o2 = x1 * s + x2 * c;

    float ss = o1 * o1 + o2 * o2;
#pragma unroll
    for (int off = 16; off; off >>= 1)
        ss += __shfl_xor_sync(0xffffffffu, ss, off);
    const float rn = rsqrtf(ss * (1.0f / 64.0f) + 1e-6f);

    float* dst = (is_q ? g_qr : k_out) + ((size_t)bh * T_DIM + t) * HD;
    dst[lane]      = o1 * rn;
    dst[lane + 32] = o2 * rn;
}

// ---------------------------------------------------------------------------
// Flash attention (fp32, causal), unchanged from R1 (known good).
// ---------------------------------------------------------------------------
__global__ void attn_kernel(const float* __restrict__ Kn,
                            const float* __restrict__ Vn)
{
    extern __shared__ float sm[];
    float (*Qs)[65]  = (float(*)[65])(sm);
    float (*KPs)[65] = (float(*)[65])(sm + 64 * 65);
    float (*Vs)[65]  = (float(*)[65])(sm + 2 * 64 * 65);

    const int qt = blockIdx.x;
    const int bh = blockIdx.y;
    const int b  = bh / H_NUM;
    const int h  = bh - b * H_NUM;
    const int tid  = threadIdx.x;
    const int lane = tid & 31;
    const int w    = tid >> 5;
    const int rg   = lane >> 3;
    const int cg   = lane & 7;
    const int r0   = w * 16 + rg * 4;
    const int q0   = qt * 64;

    const float* Qb = g_qr + ((size_t)bh * T_DIM + q0) * HD;
    const float* Kb = Kn + (size_t)bh * T_DIM * HD;
    const float* Vb = Vn + (size_t)bh * T_DIM * HD;

#pragma unroll
    for (int it = 0; it < 8; it++) {
        int idx = tid + it * 128;
        int r = idx >> 4, c4 = (idx & 15) << 2;
        float4 qv = *(const float4*)(Qb + r * HD + c4);
        Qs[r][c4] = qv.x; Qs[r][c4 + 1] = qv.y; Qs[r][c4 + 2] = qv.z; Qs[r][c4 + 3] = qv.w;
    }

    float m_i[4], l_i[4], acc[4][8];
#pragma unroll
    for (int i = 0; i < 4; i++) {
        m_i[i] = -INFINITY; l_i[i] = 0.0f;
#pragma unroll
        for (int dd = 0; dd < 8; dd++) acc[i][dd] = 0.0f;
    }

    for (int kt = 0; kt <= qt; kt++) {
        const int k0 = kt * 64;
        __syncthreads();
#pragma unroll
        for (int it = 0; it < 8; it++) {
            int idx = tid + it * 128;
            int r = idx >> 4, c4 = (idx & 15) << 2;
            float4 kv = *(const float4*)(Kb + (size_t)(k0 + r) * HD + c4);
            KPs[r][c4] = kv.x; KPs[r][c4 + 1] = kv.y; KPs[r][c4 + 2] = kv.z; KPs[r][c4 + 3] = kv.w;
            float4 vv = *(const float4*)(Vb + (size_t)(k0 + r) * HD + c4);
            Vs[r][c4] = vv.x; Vs[r][c4 + 1] = vv.y; Vs[r][c4 + 2] = vv.z; Vs[r][c4 + 3] = vv.w;
        }
        __syncthreads();

        float sv[4][8];
#pragma unroll
        for (int i = 0; i < 4; i++)
#pragma unroll
            for (int j = 0; j < 8; j++) sv[i][j] = 0.0f;

        for (int d = 0; d < 64; d++) {
            float qr_[4], kr_[8];
#pragma unroll
            for (int i = 0; i < 4; i++) qr_[i] = Qs[r0 + i][d];
#pragma unroll
            for (int j = 0; j < 8; j++) kr_[j] = KPs[cg + j * 8][d];
#pragma unroll
            for (int i = 0; i < 4; i++)
#pragma unroll
                for (int j = 0; j < 8; j++)
                    sv[i][j] = fmaf(qr_[i], kr_[j], sv[i][j]);
        }

        const bool diag = (kt == qt);
#pragma unroll
        for (int i = 0; i < 4; i++)
#pragma unroll
            for (int j = 0; j < 8; j++) {
                float s = sv[i][j] * 0.125f;
                if (diag && (cg + j * 8 > r0 + i)) s = -INFINITY;
                sv[i][j] = s;
            }

#pragma unroll
        for (int i = 0; i < 4; i++) {
            float rm = sv[i][0];
#pragma unroll
            for (int j = 1; j < 8; j++) rm = fmaxf(rm, sv[i][j]);
            rm = fmaxf(rm, __shfl_xor_sync(0xffffffffu, rm, 1));
            rm = fmaxf(rm, __shfl_xor_sync(0xffffffffu, rm, 2));
            rm = fmaxf(rm, __shfl_xor_sync(0xffffffffu, rm, 4));

            const float mnew = fmaxf(m_i[i], rm);
            const float corr = expf(m_i[i] - mnew);
            m_i[i] = mnew;
            l_i[i] *= corr;
#pragma unroll
            for (int dd = 0; dd < 8; dd++) acc[i][dd] *= corr;

            float rs = 0.0f;
#pragma unroll
            for (int j = 0; j < 8; j++) {
                float p = expf(sv[i][j] - mnew);
                sv[i][j] = p;
                rs += p;
            }
            rs += __shfl_xor_sync(0xffffffffu, rs, 1);
            rs += __shfl_xor_sync(0xffffffffu, rs, 2);
            rs += __shfl_xor_sync(0xffffffffu, rs, 4);
            l_i[i] += rs;
        }

        __syncthreads();
#pragma unroll
        for (int i = 0; i < 4; i++)
#pragma unroll
            for (int j = 0; j < 8; j++)
                KPs[r0 + i][cg + j * 8] = sv[i][j];
        __syncthreads();

        for (int j2 = 0; j2 < 64; j2++) {
            float pr[4], vr[8];
#pragma unroll
            for (int i = 0; i < 4; i++) pr[i] = KPs[r0 + i][j2];
#pragma unroll
            for (int dd = 0; dd < 8; dd++) vr[dd] = Vs[j2][cg + dd * 8];
#pragma unroll
            for (int i = 0; i < 4; i++)
#pragma unroll
                for (int dd = 0; dd < 8; dd++)
                    acc[i][dd] = fmaf(pr[i], vr[dd], acc[i][dd]);
        }
    }

    float* Yb = g_y + ((size_t)b * T_DIM + q0) * C_DIM + (size_t)h * HD;
#pragma unroll
    for (int i = 0; i < 4; i++) {
        const float invl = 1.0f / l_i[i];
#pragma unroll
        for (int dd = 0; dd < 8; dd++)
            Yb[(size_t)(r0 + i) * C_DIM + cg + dd * 8] = acc[i][dd] * invl;
    }
}

// ---------------------------------------------------------------------------
extern "C" void kernel_launch(void* const* d_in, const int* in_sizes, int n_in,
                              void* d_out, int out_size)
{
    const float* x  = (const float*)d_in[0];
    const float* Wq = (const float*)d_in[1];
    const float* Wk = (const float*)d_in[2];
    const float* Wv = (const float*)d_in[3];
    const float* Wo = (const float*)d_in[4];

    float* out   = (float*)d_out;
    float* y_out = out;                     // (B,T,C)
    float* k_out = out + S_ELE;             // (B,H,T,Hd)
    float* v_out = out + 2 * (size_t)S_ELE; // (B,H,T,Hd)

    cudaFuncSetAttribute(split_gemm, cudaFuncAttributeMaxDynamicSharedMemorySize,
                         GSMEM);

    // 1) QKV projections (bf16 hi/lo split, mma.sync tensor path)
    split_gemm<<<dim3(C_DIM / 128, M_TOT / 128, 3), 256, GSMEM>>>(
        x, Wq, Wk, Wv, v_out, 1);

    // 2) RoPE + RMSNorm on q and k
    rope_norm_kernel<<<dim3((B_DIM * H_NUM * T_DIM) / 8, 2), 256>>>(k_out);

    // 3) causal flash attention
    const size_t smem = 3 * 64 * 65 * sizeof(float);
    cudaFuncSetAttribute(attn_kernel, cudaFuncAttributeMaxDynamicSharedMemorySize,
                         (int)smem);
    attn_kernel<<<dim3(T_DIM / 64, B_DIM * H_NUM), 128, smem>>>(k_out, v_out);

    // 4) output projection (A = g_y selected device-side via is_qkv=0)
    split_gemm<<<dim3(C_DIM / 128, M_TOT / 128, 1), 256, GSMEM>>>(
        nullptr, Wo, Wo, Wo, y_out, 0);
}

// round 6
// speedup vs baseline: 1.6545x; 1.2850x over previous
#include <cuda_runtime.h>
#include <cuda_bf16.h>
#include <math.h>
#include <stdint.h>

#define C_DIM 768
#define T_DIM 1024
#define B_DIM 8
#define H_NUM 12
#define HD    64
#define M_TOT 8192
#define S_ELE 6291456   /* 8*1024*768 */

// Scratch (device globals: allocation-free per harness rules)
static __device__ float g_q [S_ELE];  // raw q, (B,T,C)
static __device__ float g_k [S_ELE];  // raw k, (B,T,C)
static __device__ float g_qr[S_ELE];  // rope+norm q, (B,H,T,Hd)
static __device__ float g_y [S_ELE];  // attention out, (B,T,C)

__device__ __forceinline__ uint32_t smem_u32(const void* p) {
    uint32_t a;
    asm("{ .reg .u64 t; cvta.to.shared.u64 t, %1; cvt.u32.u64 %0, t; }"
        : "=r"(a) : "l"(p));
    return a;
}
__device__ __forceinline__ float ex2f(float x) {
    float r;
    asm("ex2.approx.ftz.f32 %0, %1;" : "=f"(r) : "f"(x));
    return r;
}
__device__ __forceinline__ uint32_t pack_bf2(float lo, float hi) {
    __nv_bfloat16 a = __float2bfloat16(lo);
    __nv_bfloat16 b = __float2bfloat16(hi);
    return ((uint32_t)__bfloat16_as_ushort(b) << 16) | __bfloat16_as_ushort(a);
}
__device__ __forceinline__ float bf16rt(float x) {   // round-trip through bf16
    return __bfloat162float(__float2bfloat16(x));
}
__device__ __forceinline__ void ldmx4(uint32_t& r0, uint32_t& r1,
                                      uint32_t& r2, uint32_t& r3, uint32_t addr) {
    asm volatile("ldmatrix.sync.aligned.m8n8.x4.shared.b16 {%0,%1,%2,%3}, [%4];"
                 : "=r"(r0), "=r"(r1), "=r"(r2), "=r"(r3) : "r"(addr));
}
__device__ __forceinline__ void ldmx4t(uint32_t& r0, uint32_t& r1,
                                       uint32_t& r2, uint32_t& r3, uint32_t addr) {
    asm volatile("ldmatrix.sync.aligned.m8n8.x4.trans.shared.b16 {%0,%1,%2,%3}, [%4];"
                 : "=r"(r0), "=r"(r1), "=r"(r2), "=r"(r3) : "r"(addr));
}
__device__ __forceinline__ void mma_bf16(float* c, const uint32_t* a,
                                         const uint32_t* b) {
    asm volatile(
        "mma.sync.aligned.m16n8k16.row.col.f32.bf16.bf16.f32 "
        "{%0,%1,%2,%3},{%4,%5,%6,%7},{%8,%9},{%0,%1,%2,%3};"
        : "+f"(c[0]), "+f"(c[1]), "+f"(c[2]), "+f"(c[3])
        : "r"(a[0]), "r"(a[1]), "r"(a[2]), "r"(a[3]), "r"(b[0]), "r"(b[1]));
}

// ===========================================================================
// bf16 hi/lo split GEMM (unchanged from R3, passing)
// ===========================================================================
#define NCHUNK 24
#define PLANE  8192
#define STAGE  32768
#define GSMEM  (2*STAGE + 1024)

__device__ __forceinline__ uint32_t swz(int row, int c4) {
    int seg = c4 >> 3;
    int slot = seg ^ ((row >> 1) & 3);
    return (uint32_t)(row * 64 + slot * 16 + ((c4 & 4) << 1));
}

__global__ __launch_bounds__(256, 1)
void split_gemm(const float* __restrict__ Ain,
                const float* __restrict__ W0, const float* __restrict__ W1,
                const float* __restrict__ W2,
                float* __restrict__ dst, int is_qkv)
{
    extern __shared__ unsigned char sm8[];
    const int tid  = threadIdx.x;
    const int lane = tid & 31;
    const int wid  = tid >> 5;
    const int wm   = wid >> 2;
    const int wn   = wid & 3;

    const int n0 = blockIdx.x * 128;
    const int m0 = blockIdx.y * 128;
    int mode;
    const float* A;
    const float* W;
    if (is_qkv) {
        mode = blockIdx.z;
        A = Ain;
        W = (mode == 0) ? W0 : (mode == 1) ? W1 : W2;
    } else {
        mode = 3;
        A = g_y;
        W = W0;
    }

    uint32_t base = (smem_u32(sm8) + 1023u) & ~1023u;
    const float* Arow = A + (size_t)m0 * C_DIM;
    const float* Wrow = W + (size_t)n0 * C_DIM;

    float4 aR[4], bR[4];
    float acc[16][4];
#pragma unroll
    for (int i = 0; i < 16; i++)
#pragma unroll
        for (int j = 0; j < 4; j++) acc[i][j] = 0.0f;

#pragma unroll
    for (int i = 0; i < 4; i++) {
        int idx = tid + i * 256;
        int r = idx >> 3, c4 = (idx & 7) << 2;
        aR[i] = *(const float4*)(Arow + (size_t)r * C_DIM + c4);
        bR[i] = *(const float4*)(Wrow + (size_t)r * C_DIM + c4);
    }

    for (int c = 0; c < NCHUNK; c++) {
        const uint32_t st = base + (uint32_t)(c & 1) * STAGE;
#pragma unroll
        for (int i = 0; i < 4; i++) {
            int idx = tid + i * 256;
            int r = idx >> 3, c4 = (idx & 7) << 2;
            uint32_t off = swz(r, c4);

            float4 a = aR[i];
            float hx = bf16rt(a.x), hy = bf16rt(a.y), hz = bf16rt(a.z), hw = bf16rt(a.w);
            uint32_t ah0 = pack_bf2(hx, hy), ah1 = pack_bf2(hz, hw);
            uint32_t al0 = pack_bf2(a.x - hx, a.y - hy);
            uint32_t al1 = pack_bf2(a.z - hz, a.w - hw);
            asm volatile("st.shared.v2.b32 [%0], {%1,%2};" ::
                         "r"(st + off), "r"(ah0), "r"(ah1) : "memory");
            asm volatile("st.shared.v2.b32 [%0], {%1,%2};" ::
                         "r"(st + PLANE + off), "r"(al0), "r"(al1) : "memory");

            float4 b = bR[i];
            float gx = bf16rt(b.x), gy = bf16rt(b.y), gz = bf16rt(b.z), gw = bf16rt(b.w);
            uint32_t bh0 = pack_bf2(gx, gy), bh1 = pack_bf2(gz, gw);
            uint32_t bl0 = pack_bf2(b.x - gx, b.y - gy);
            uint32_t bl1 = pack_bf2(b.z - gz, b.w - gw);
            asm volatile("st.shared.v2.b32 [%0], {%1,%2};" ::
                         "r"(st + 2 * PLANE + off), "r"(bh0), "r"(bh1) : "memory");
            asm volatile("st.shared.v2.b32 [%0], {%1,%2};" ::
                         "r"(st + 3 * PLANE + off), "r"(bl0), "r"(bl1) : "memory");
        }
        __syncthreads();

        if (c + 1 < NCHUNK) {
            const int k0 = (c + 1) * 32;
#pragma unroll
            for (int i = 0; i < 4; i++) {
                int idx = tid + i * 256;
                int r = idx >> 3, c4 = (idx & 7) << 2;
                aR[i] = *(const float4*)(Arow + (size_t)r * C_DIM + k0 + c4);
                bR[i] = *(const float4*)(Wrow + (size_t)r * C_DIM + k0 + c4);
            }
        }

#pragma unroll
        for (int ks = 0; ks < 2; ks++) {
            uint32_t bh[4][2], bl[4][2];
#pragma unroll
            for (int g = 0; g < 2; g++) {
                int row = wn * 32 + g * 16 + (lane & 15);
                int c4 = (2 * ks + (lane >> 4)) * 8;
                uint32_t off = swz(row, c4);
                uint32_t r0, r1, r2, r3;
                ldmx4(r0, r1, r2, r3, st + 2 * PLANE + off);
                bh[2 * g][0] = r0; bh[2 * g + 1][0] = r1;
                bh[2 * g][1] = r2; bh[2 * g + 1][1] = r3;
                ldmx4(r0, r1, r2, r3, st + 3 * PLANE + off);
                bl[2 * g][0] = r0; bl[2 * g + 1][0] = r1;
                bl[2 * g][1] = r2; bl[2 * g + 1][1] = r3;
            }
#pragma unroll
            for (int mt = 0; mt < 4; mt++) {
                int row = wm * 64 + mt * 16 + (lane & 15);
                int c4 = (2 * ks + (lane >> 4)) * 8;
                uint32_t off = swz(row, c4);
                uint32_t ah[4], al[4];
                ldmx4(ah[0], ah[1], ah[2], ah[3], st + off);
                ldmx4(al[0], al[1], al[2], al[3], st + PLANE + off);
#pragma unroll
                for (int nt = 0; nt < 4; nt++) {
                    mma_bf16(acc[mt * 4 + nt], ah, bh[nt]);
                    mma_bf16(acc[mt * 4 + nt], ah, bl[nt]);
                    mma_bf16(acc[mt * 4 + nt], al, bh[nt]);
                }
            }
        }
        __syncthreads();
    }

#pragma unroll
    for (int mt = 0; mt < 4; mt++) {
#pragma unroll
        for (int nt = 0; nt < 4; nt++) {
            const float* cc = acc[mt * 4 + nt];
            int r  = m0 + wm * 64 + mt * 16 + (lane >> 2);
            int cl = n0 + wn * 32 + nt * 8 + ((lane & 3) << 1);
#pragma unroll
            for (int h2 = 0; h2 < 2; h2++) {
                int rr = r + h2 * 8;
                float2 v = make_float2(cc[h2 * 2], cc[h2 * 2 + 1]);
                if (mode == 0) {
                    *(float2*)(g_q + (size_t)rr * C_DIM + cl) = v;
                } else if (mode == 1) {
                    *(float2*)(g_k + (size_t)rr * C_DIM + cl) = v;
                } else if (mode == 3) {
                    *(float2*)(dst + (size_t)rr * C_DIM + cl) = v;
                } else {
                    const int bb = rr >> 10, t = rr & (T_DIM - 1);
                    const int h = cl >> 6, hd0 = cl & (HD - 1);
                    *(float2*)(dst + (((size_t)(bb * H_NUM + h)) * T_DIM + t) * HD + hd0) = v;
                }
            }
        }
    }
}

// ---------------------------------------------------------------------------
// RoPE + qk RMSNorm (unchanged)
// ---------------------------------------------------------------------------
__global__ void rope_norm_kernel(float* __restrict__ k_out)
{
    const int lane = threadIdx.x & 31;
    const int vec  = blockIdx.x * 8 + (threadIdx.x >> 5);
    const int t  = vec & (T_DIM - 1);
    const int bh = vec >> 10;
    const int b  = bh / H_NUM;
    const int h  = bh - b * H_NUM;
    const bool is_q = (blockIdx.y == 0);

    const float* src = (is_q ? g_q : g_k) +
                       ((size_t)(b * T_DIM + t)) * C_DIM + h * HD;
    const float x1 = src[lane];
    const float x2 = src[lane + 32];

    const float inv = (float)exp((double)lane * -0.28782313662425575);
    const float f = (float)t * inv;
    float s, c;
    sincosf(f, &s, &c);
    const float o1 = x1 * c - x2 * s;
    const float o2 = x1 * s + x2 * c;

    float ss = o1 * o1 + o2 * o2;
#pragma unroll
    for (int off = 16; off; off >>= 1)
        ss += __shfl_xor_sync(0xffffffffu, ss, off);
    const float rn = rsqrtf(ss * (1.0f / 64.0f) + 1e-6f);

    float* dst = (is_q ? g_qr : k_out) + ((size_t)bh * T_DIM + t) * HD;
    dst[lane]      = o1 * rn;
    dst[lane + 32] = o2 * rn;
}

// ===========================================================================
// Tensor-core flash attention. 128 q-rows x 128 k-cols per tile, 256 threads,
// warp owns 16 rows (row-local softmax). bf16 hi/lo split for QK^T and PV.
// smem planes (128 rows x 64 cols bf16 = 16KB each): Qh Ql Kh Kl Vh Vl.
// ===========================================================================
#define APLANE 16384
#define ASMEM  (6 * APLANE)

// 128B rows: seg = 16B unit (0..7); swizzled offset
__device__ __forceinline__ uint32_t aswz(int row, int seg) {
    return (uint32_t)(row * 128 + ((seg ^ (row & 7)) << 4));
}

__global__ __launch_bounds__(256, 1)
void attn_mma(const float* __restrict__ Kn, const float* __restrict__ Vn)
{
    extern __shared__ unsigned char sm8[];
    const uint32_t base = smem_u32(sm8);
    const uint32_t Qh = base,            Ql = base + APLANE;
    const uint32_t Kh = base + 2*APLANE, Kl = base + 3*APLANE;
    const uint32_t Vh = base + 4*APLANE, Vl = base + 5*APLANE;

    const int tid  = threadIdx.x;
    const int lane = tid & 31;
    const int wid  = tid >> 5;
    const int qt   = 7 - blockIdx.x;        // heavy tiles first
    const int bh   = blockIdx.y;
    const int b    = bh / H_NUM;
    const int h    = bh - b * H_NUM;
    const int q0   = qt * 128;
    const int wr0  = wid * 16;

    const float QSC = 0.125f * 1.4426950408889634f;  // (1/sqrt(64)) * log2(e)

    // ---- load Q (scaled) into Qh/Ql ----
    const float* Qg = g_qr + ((size_t)bh * T_DIM + q0) * HD;
#pragma unroll
    for (int it = 0; it < 4; it++) {
        int id = tid + it * 256;
        int r = id >> 3, seg = id & 7;
        const float* s = Qg + (size_t)r * HD + seg * 8;
        float4 v0 = *(const float4*)(s);
        float4 v1 = *(const float4*)(s + 4);
        float e[8] = {v0.x*QSC, v0.y*QSC, v0.z*QSC, v0.w*QSC,
                      v1.x*QSC, v1.y*QSC, v1.z*QSC, v1.w*QSC};
        float hf[8];
        uint32_t hi[4], lo[4];
#pragma unroll
        for (int j = 0; j < 8; j++) hf[j] = bf16rt(e[j]);
#pragma unroll
        for (int j = 0; j < 4; j++) {
            hi[j] = pack_bf2(hf[2*j], hf[2*j+1]);
            lo[j] = pack_bf2(e[2*j] - hf[2*j], e[2*j+1] - hf[2*j+1]);
        }
        uint32_t off = aswz(r, seg);
        asm volatile("st.shared.v4.b32 [%0], {%1,%2,%3,%4};" ::
            "r"(Qh + off), "r"(hi[0]), "r"(hi[1]), "r"(hi[2]), "r"(hi[3]) : "memory");
        asm volatile("st.shared.v4.b32 [%0], {%1,%2,%3,%4};" ::
            "r"(Ql + off), "r"(lo[0]), "r"(lo[1]), "r"(lo[2]), "r"(lo[3]) : "memory");
    }

    // ---- state ----
    float o[8][4];
#pragma unroll
    for (int i = 0; i < 8; i++)
#pragma unroll
        for (int j = 0; j < 4; j++) o[i][j] = 0.0f;
    float m_a = -INFINITY, m_b = -INFINITY, l_a = 0.0f, l_b = 0.0f;

    const float* Kg = Kn + (size_t)bh * T_DIM * HD;
    const float* Vg = Vn + (size_t)bh * T_DIM * HD;

    for (int kt = 0; kt <= qt; kt++) {
        const int k0 = kt * 128;
        __syncthreads();   // previous iteration done reading K/V (and Q stored, iter 0)
        // ---- load K/V tile, convert hi/lo ----
#pragma unroll
        for (int it = 0; it < 4; it++) {
            int id = tid + it * 256;
            int r = id >> 3, seg = id & 7;
            uint32_t off = aswz(r, seg);
            {
                const float* s = Kg + (size_t)(k0 + r) * HD + seg * 8;
                float4 v0 = *(const float4*)(s);
                float4 v1 = *(const float4*)(s + 4);
                float e[8] = {v0.x, v0.y, v0.z, v0.w, v1.x, v1.y, v1.z, v1.w};
                float hf[8]; uint32_t hi[4], lo[4];
#pragma unroll
                for (int j = 0; j < 8; j++) hf[j] = bf16rt(e[j]);
#pragma unroll
                for (int j = 0; j < 4; j++) {
                    hi[j] = pack_bf2(hf[2*j], hf[2*j+1]);
                    lo[j] = pack_bf2(e[2*j] - hf[2*j], e[2*j+1] - hf[2*j+1]);
                }
                asm volatile("st.shared.v4.b32 [%0], {%1,%2,%3,%4};" ::
                    "r"(Kh + off), "r"(hi[0]), "r"(hi[1]), "r"(hi[2]), "r"(hi[3]) : "memory");
                asm volatile("st.shared.v4.b32 [%0], {%1,%2,%3,%4};" ::
                    "r"(Kl + off), "r"(lo[0]), "r"(lo[1]), "r"(lo[2]), "r"(lo[3]) : "memory");
            }
            {
                const float* s = Vg + (size_t)(k0 + r) * HD + seg * 8;
                float4 v0 = *(const float4*)(s);
                float4 v1 = *(const float4*)(s + 4);
                float e[8] = {v0.x, v0.y, v0.z, v0.w, v1.x, v1.y, v1.z, v1.w};
                float hf[8]; uint32_t hi[4], lo[4];
#pragma unroll
                for (int j = 0; j < 8; j++) hf[j] = bf16rt(e[j]);
#pragma unroll
                for (int j = 0; j < 4; j++) {
                    hi[j] = pack_bf2(hf[2*j], hf[2*j+1]);
                    lo[j] = pack_bf2(e[2*j] - hf[2*j], e[2*j+1] - hf[2*j+1]);
                }
                asm volatile("st.shared.v4.b32 [%0], {%1,%2,%3,%4};" ::
                    "r"(Vh + off), "r"(hi[0]), "r"(hi[1]), "r"(hi[2]), "r"(hi[3]) : "memory");
                asm volatile("st.shared.v4.b32 [%0], {%1,%2,%3,%4};" ::
                    "r"(Vl + off), "r"(lo[0]), "r"(lo[1]), "r"(lo[2]), "r"(lo[3]) : "memory");
            }
        }
        __syncthreads();

        // ---- S = Qs @ K^T  (16 x 128 per warp) ----
        float s[16][4];
#pragma unroll
        for (int i = 0; i < 16; i++)
#pragma unroll
            for (int j = 0; j < 4; j++) s[i][j] = 0.0f;

#pragma unroll
        for (int ks = 0; ks < 4; ks++) {
            int arow = wr0 + (lane & 15);
            int aseg = ks * 2 + (lane >> 4);
            uint32_t aoff = aswz(arow, aseg);
            uint32_t ah[4], al[4];
            ldmx4(ah[0], ah[1], ah[2], ah[3], Qh + aoff);
            ldmx4(al[0], al[1], al[2], al[3], Ql + aoff);
#pragma unroll
            for (int np = 0; np < 8; np++) {
                int brow = np * 16 + (lane & 15);
                uint32_t boff = aswz(brow, aseg);
                uint32_t r0, r1, r2, r3;
                uint32_t bhf[2][2], blf[2][2];
                ldmx4(r0, r1, r2, r3, Kh + boff);
                bhf[0][0] = r0; bhf[0][1] = r2; bhf[1][0] = r1; bhf[1][1] = r3;
                ldmx4(r0, r1, r2, r3, Kl + boff);
                blf[0][0] = r0; blf[0][1] = r2; blf[1][0] = r1; blf[1][1] = r3;
#pragma unroll
                for (int g = 0; g < 2; g++) {
                    mma_bf16(s[np*2+g], ah, bhf[g]);
                    mma_bf16(s[np*2+g], ah, blf[g]);
                    mma_bf16(s[np*2+g], al, bhf[g]);
                }
            }
        }

        // ---- causal mask on diagonal tile ----
        if (kt == qt) {
            const int ra = (lane >> 2), cb = ((lane & 3) << 1);
#pragma unroll
            for (int nt = 0; nt < 16; nt++) {
#pragma unroll
                for (int j = 0; j < 4; j++) {
                    int col = nt * 8 + cb + (j & 1);
                    int row = wr0 + ra + ((j >> 1) << 3);   // FIXED: include warp offset
                    if (col > row) s[nt][j] = -INFINITY;
                }
            }
        }

        // ---- online softmax (rows ra, ra+8 of warp tile) ----
        float mx_a = -INFINITY, mx_b = -INFINITY;
#pragma unroll
        for (int nt = 0; nt < 16; nt++) {
            mx_a = fmaxf(mx_a, fmaxf(s[nt][0], s[nt][1]));
            mx_b = fmaxf(mx_b, fmaxf(s[nt][2], s[nt][3]));
        }
        mx_a = fmaxf(mx_a, __shfl_xor_sync(0xffffffffu, mx_a, 1));
        mx_a = fmaxf(mx_a, __shfl_xor_sync(0xffffffffu, mx_a, 2));
        mx_b = fmaxf(mx_b, __shfl_xor_sync(0xffffffffu, mx_b, 1));
        mx_b = fmaxf(mx_b, __shfl_xor_sync(0xffffffffu, mx_b, 2));

        const float mn_a = fmaxf(m_a, mx_a);
        const float mn_b = fmaxf(m_b, mx_b);
        const float ca = ex2f(m_a - mn_a);
        const float cbf = ex2f(m_b - mn_b);
        m_a = mn_a; m_b = mn_b;

        float sa = 0.0f, sb = 0.0f;
#pragma unroll
        for (int nt = 0; nt < 16; nt++) {
            s[nt][0] = ex2f(s[nt][0] - mn_a);
            s[nt][1] = ex2f(s[nt][1] - mn_a);
            s[nt][2] = ex2f(s[nt][2] - mn_b);
            s[nt][3] = ex2f(s[nt][3] - mn_b);
            sa += s[nt][0] + s[nt][1];
            sb += s[nt][2] + s[nt][3];
        }
        sa += __shfl_xor_sync(0xffffffffu, sa, 1);
        sa += __shfl_xor_sync(0xffffffffu, sa, 2);
        sb += __shfl_xor_sync(0xffffffffu, sb, 1);
        sb += __shfl_xor_sync(0xffffffffu, sb, 2);
        l_a = l_a * ca + sa;
        l_b = l_b * cbf + sb;
#pragma unroll
        for (int i = 0; i < 8; i++) {
            o[i][0] *= ca; o[i][1] *= ca; o[i][2] *= cbf; o[i][3] *= cbf;
        }

        // ---- O += P @ V  (hi/lo split, P converted in registers) ----
#pragma unroll
        for (int kc = 0; kc < 8; kc++) {
            float p0h = bf16rt(s[2*kc][0]),   p1h = bf16rt(s[2*kc][1]);
            float p2h = bf16rt(s[2*kc][2]),   p3h = bf16rt(s[2*kc][3]);
            float q0h = bf16rt(s[2*kc+1][0]), q1h = bf16rt(s[2*kc+1][1]);
            float q2h = bf16rt(s[2*kc+1][2]), q3h = bf16rt(s[2*kc+1][3]);
            uint32_t pa[4], pl[4];
            pa[0] = pack_bf2(p0h, p1h);
            pa[1] = pack_bf2(p2h, p3h);
            pa[2] = pack_bf2(q0h, q1h);
            pa[3] = pack_bf2(q2h, q3h);
            pl[0] = pack_bf2(s[2*kc][0]-p0h,   s[2*kc][1]-p1h);
            pl[1] = pack_bf2(s[2*kc][2]-p2h,   s[2*kc][3]-p3h);
            pl[2] = pack_bf2(s[2*kc+1][0]-q0h, s[2*kc+1][1]-q1h);
            pl[3] = pack_bf2(s[2*kc+1][2]-q2h, s[2*kc+1][3]-q3h);

            int vrow = kc * 16 + (lane & 15);
#pragma unroll
            for (int s2 = 0; s2 < 4; s2++) {
                int vseg = s2 * 2 + (lane >> 4);
                uint32_t voff = aswz(vrow, vseg);
                uint32_t r0, r1, r2, r3;
                uint32_t vhf[2][2], vlf[2][2];
                ldmx4t(r0, r1, r2, r3, Vh + voff);
                vhf[0][0] = r0; vhf[0][1] = r1; vhf[1][0] = r2; vhf[1][1] = r3;
                ldmx4t(r0, r1, r2, r3, Vl + voff);
                vlf[0][0] = r0; vlf[0][1] = r1; vlf[1][0] = r2; vlf[1][1] = r3;
#pragma unroll
                for (int g = 0; g < 2; g++) {
                    mma_bf16(o[s2*2+g], pa, vhf[g]);
                    mma_bf16(o[s2*2+g], pa, vlf[g]);
                    mma_bf16(o[s2*2+g], pl, vhf[g]);
                }
            }
        }
    }

    // ---- normalize + write (B,T,C) ----
    const float ia = 1.0f / l_a, ib = 1.0f / l_b;
    const int ra = lane >> 2, cb = (lane & 3) << 1;
    float* Yb = g_y + ((size_t)b * T_DIM + q0 + wr0) * C_DIM + (size_t)h * HD;
#pragma unroll
    for (int nt = 0; nt < 8; nt++) {
        *(float2*)(Yb + (size_t)ra * C_DIM + nt * 8 + cb) =
            make_float2(o[nt][0] * ia, o[nt][1] * ia);
        *(float2*)(Yb + (size_t)(ra + 8) * C_DIM + nt * 8 + cb) =
            make_float2(o[nt][2] * ib, o[nt][3] * ib);
    }
}

// ---------------------------------------------------------------------------
extern "C" void kernel_launch(void* const* d_in, const int* in_sizes, int n_in,
                              void* d_out, int out_size)
{
    const float* x  = (const float*)d_in[0];
    const float* Wq = (const float*)d_in[1];
    const float* Wk = (const float*)d_in[2];
    const float* Wv = (const float*)d_in[3];
    const float* Wo = (const float*)d_in[4];

    float* out   = (float*)d_out;
    float* y_out = out;
    float* k_out = out + S_ELE;
    float* v_out = out + 2 * (size_t)S_ELE;

    cudaFuncSetAttribute(split_gemm, cudaFuncAttributeMaxDynamicSharedMemorySize,
                         GSMEM);
    cudaFuncSetAttribute(attn_mma, cudaFuncAttributeMaxDynamicSharedMemorySize,
                         ASMEM);

    split_gemm<<<dim3(C_DIM / 128, M_TOT / 128, 3), 256, GSMEM>>>(
        x, Wq, Wk, Wv, v_out, 1);

    rope_norm_kernel<<<dim3((B_DIM * H_NUM * T_DIM) / 8, 2), 256>>>(k_out);

    attn_mma<<<dim3(T_DIM / 128, B_DIM * H_NUM), 256, ASMEM>>>(k_out, v_out);

    split_gemm<<<dim3(C_DIM / 128, M_TOT / 128, 1), 256, GSMEM>>>(
        nullptr, Wo, Wo, Wo, y_out, 0);
}

// round 7
// speedup vs baseline: 2.3513x; 1.4211x over previous
#include <cuda_runtime.h>
#include <cuda_bf16.h>
#include <math.h>
#include <stdint.h>

#define C_DIM 768
#define T_DIM 1024
#define B_DIM 8
#define H_NUM 12
#define HD    64
#define M_TOT 8192
#define S_ELE 6291456   /* 8*1024*768 */
#define X_ELE 6291456
#define W_ELE 589824    /* 768*768 */

// fp32 scratch (raw q/k for rope input)
static __device__ float g_q[S_ELE];
static __device__ float g_k[S_ELE];
// bf16 hi/lo planes
static __device__ __align__(16) __nv_bfloat16 g_xh[X_ELE], g_xl[X_ELE];
static __device__ __align__(16) __nv_bfloat16 g_wh[4 * W_ELE], g_wl[4 * W_ELE];
static __device__ __align__(16) __nv_bfloat16 g_qh[S_ELE], g_ql[S_ELE];
static __device__ __align__(16) __nv_bfloat16 g_kh[S_ELE], g_kl[S_ELE];
static __device__ __align__(16) __nv_bfloat16 g_vh[S_ELE], g_vl[S_ELE];
static __device__ __align__(16) __nv_bfloat16 g_yh[S_ELE], g_yl[S_ELE];

__device__ __forceinline__ uint32_t smem_u32(const void* p) {
    uint32_t a;
    asm("{ .reg .u64 t; cvta.to.shared.u64 t, %1; cvt.u32.u64 %0, t; }"
        : "=r"(a) : "l"(p));
    return a;
}
__device__ __forceinline__ float ex2f(float x) {
    float r;
    asm("ex2.approx.ftz.f32 %0, %1;" : "=f"(r) : "f"(x));
    return r;
}
__device__ __forceinline__ uint32_t pack_bf2(float lo, float hi) {
    __nv_bfloat16 a = __float2bfloat16(lo);
    __nv_bfloat16 b = __float2bfloat16(hi);
    return ((uint32_t)__bfloat16_as_ushort(b) << 16) | __bfloat16_as_ushort(a);
}
__device__ __forceinline__ float bf16rt(float x) {
    return __bfloat162float(__float2bfloat16(x));
}
__device__ __forceinline__ void cpa16(uint32_t dst, const void* src) {
    asm volatile("cp.async.cg.shared.global [%0], [%1], 16;"
                 :: "r"(dst), "l"(src) : "memory");
}
#define CP_COMMIT()  asm volatile("cp.async.commit_group;" ::: "memory")
#define CP_WAIT(n)   asm volatile("cp.async.wait_group %0;" :: "n"(n) : "memory")
__device__ __forceinline__ void ldmx4(uint32_t& r0, uint32_t& r1,
                                      uint32_t& r2, uint32_t& r3, uint32_t addr) {
    asm volatile("ldmatrix.sync.aligned.m8n8.x4.shared.b16 {%0,%1,%2,%3}, [%4];"
                 : "=r"(r0), "=r"(r1), "=r"(r2), "=r"(r3) : "r"(addr));
}
__device__ __forceinline__ void ldmx4t(uint32_t& r0, uint32_t& r1,
                                       uint32_t& r2, uint32_t& r3, uint32_t addr) {
    asm volatile("ldmatrix.sync.aligned.m8n8.x4.trans.shared.b16 {%0,%1,%2,%3}, [%4];"
                 : "=r"(r0), "=r"(r1), "=r"(r2), "=r"(r3) : "r"(addr));
}
__device__ __forceinline__ void mma_bf16(float* c, const uint32_t* a,
                                         const uint32_t* b) {
    asm volatile(
        "mma.sync.aligned.m16n8k16.row.col.f32.bf16.bf16.f32 "
        "{%0,%1,%2,%3},{%4,%5,%6,%7},{%8,%9},{%0,%1,%2,%3};"
        : "+f"(c[0]), "+f"(c[1]), "+f"(c[2]), "+f"(c[3])
        : "r"(a[0]), "r"(a[1]), "r"(a[2]), "r"(a[3]), "r"(b[0]), "r"(b[1]));
}

// ===========================================================================
// prep: convert x + 4 weights to bf16 hi/lo planes (one float4 per thread)
// ===========================================================================
#define PREP_F4 ((X_ELE + 4 * W_ELE) / 4)
__global__ void prep_convert(const float* __restrict__ x,
                             const float* __restrict__ Wq,
                             const float* __restrict__ Wk,
                             const float* __restrict__ Wv,
                             const float* __restrict__ Wo)
{
    size_t i4 = (size_t)blockIdx.x * 256 + threadIdx.x;
    if (i4 >= PREP_F4) return;
    size_t e = i4 * 4;
    const float* src;
    __nv_bfloat16 *dh, *dl;
    size_t off;
    if (e < X_ELE) { src = x; off = e; dh = g_xh; dl = g_xl; }
    else {
        size_t r = e - X_ELE;
        int w = (int)(r / W_ELE);
        off = r - (size_t)w * W_ELE;
        src = (w == 0) ? Wq : (w == 1) ? Wk : (w == 2) ? Wv : Wo;
        dh = g_wh + (size_t)w * W_ELE;
        dl = g_wl + (size_t)w * W_ELE;
    }
    float4 v = *(const float4*)(src + off);
    float h0 = bf16rt(v.x), h1 = bf16rt(v.y), h2 = bf16rt(v.z), h3 = bf16rt(v.w);
    uint2 ph = make_uint2(pack_bf2(h0, h1), pack_bf2(h2, h3));
    uint2 pl = make_uint2(pack_bf2(v.x - h0, v.y - h1), pack_bf2(v.z - h2, v.w - h3));
    *(uint2*)(dh + off) = ph;
    *(uint2*)(dl + off) = pl;
}

// ===========================================================================
// bf16 hi/lo split GEMM with cp.async (planes pre-converted).
// 128x128 CTA tile, 8 warps, K chunks of 32, 2-stage cp.async pipeline.
// modes: 0 -> g_q, 1 -> g_k, 2 -> dst (v BHTD), 3 -> dst (y BTC)
// ===========================================================================
#define NCHUNK 24
#define PLANE  8192
#define STAGE  32768
#define GSMEM  (2 * STAGE)

__device__ __forceinline__ uint32_t swz16(int row, int seg) {
    return (uint32_t)(row * 64 + ((seg ^ ((row >> 1) & 3)) << 4));
}

__global__ __launch_bounds__(256, 2)
void split_gemm2(float* __restrict__ dst, int is_qkv)
{
    extern __shared__ __align__(1024) unsigned char sm8[];
    const uint32_t base = smem_u32(sm8);
    const int tid  = threadIdx.x;
    const int lane = tid & 31;
    const int wid  = tid >> 5;
    const int wm   = wid >> 2;
    const int wn   = wid & 3;
    const int n0 = blockIdx.x * 128;
    const int m0 = blockIdx.y * 128;

    int mode;
    const __nv_bfloat16 *Ah, *Al, *Bh, *Bl;
    if (is_qkv) {
        mode = blockIdx.z;
        Ah = g_xh; Al = g_xl;
        Bh = g_wh + (size_t)mode * W_ELE;
        Bl = g_wl + (size_t)mode * W_ELE;
    } else {
        mode = 3;
        Ah = g_yh; Al = g_yl;
        Bh = g_wh + 3 * (size_t)W_ELE;
        Bl = g_wl + 3 * (size_t)W_ELE;
    }
    Ah += (size_t)m0 * C_DIM; Al += (size_t)m0 * C_DIM;
    Bh += (size_t)n0 * C_DIM; Bl += (size_t)n0 * C_DIM;

    float acc[16][4];
#pragma unroll
    for (int i = 0; i < 16; i++)
#pragma unroll
        for (int j = 0; j < 4; j++) acc[i][j] = 0.0f;

    // copy lambda: chunk c into stage buffer
    auto copy_chunk = [&](int c, uint32_t st) {
        const int k0 = c * 32;
#pragma unroll
        for (int i = 0; i < 2; i++) {
            int idx = tid + i * 256;
            int r = idx >> 2, sg = idx & 3;
            uint32_t so = swz16(r, sg);
            size_t go = (size_t)r * C_DIM + k0 + sg * 8;
            cpa16(st + so,             Ah + go);
            cpa16(st + PLANE + so,     Al + go);
            cpa16(st + 2 * PLANE + so, Bh + go);
            cpa16(st + 3 * PLANE + so, Bl + go);
        }
    };

    copy_chunk(0, base);
    CP_COMMIT();

    for (int c = 0; c < NCHUNK; c++) {
        const uint32_t st = base + (uint32_t)(c & 1) * STAGE;
        if (c + 1 < NCHUNK) {
            copy_chunk(c + 1, base + (uint32_t)((c + 1) & 1) * STAGE);
            CP_COMMIT();
            CP_WAIT(1);
        } else {
            CP_WAIT(0);
        }
        __syncthreads();

#pragma unroll
        for (int ks = 0; ks < 2; ks++) {
            uint32_t bh[4][2], bl[4][2];
#pragma unroll
            for (int g = 0; g < 2; g++) {
                int row = wn * 32 + g * 16 + (lane & 15);
                int sg = 2 * ks + (lane >> 4);
                uint32_t off = swz16(row, sg);
                uint32_t r0, r1, r2, r3;
                ldmx4(r0, r1, r2, r3, st + 2 * PLANE + off);
                bh[2 * g][0] = r0; bh[2 * g + 1][0] = r1;
                bh[2 * g][1] = r2; bh[2 * g + 1][1] = r3;
                ldmx4(r0, r1, r2, r3, st + 3 * PLANE + off);
                bl[2 * g][0] = r0; bl[2 * g + 1][0] = r1;
                bl[2 * g][1] = r2; bl[2 * g + 1][1] = r3;
            }
#pragma unroll
            for (int mt = 0; mt < 4; mt++) {
                int row = wm * 64 + mt * 16 + (lane & 15);
                int sg = 2 * ks + (lane >> 4);
                uint32_t off = swz16(row, sg);
                uint32_t ah[4], al[4];
                ldmx4(ah[0], ah[1], ah[2], ah[3], st + off);
                ldmx4(al[0], al[1], al[2], al[3], st + PLANE + off);
#pragma unroll
                for (int nt = 0; nt < 4; nt++) {
                    mma_bf16(acc[mt * 4 + nt], ah, bh[nt]);
                    mma_bf16(acc[mt * 4 + nt], ah, bl[nt]);
                    mma_bf16(acc[mt * 4 + nt], al, bh[nt]);
                }
            }
        }
        __syncthreads();
    }

#pragma unroll
    for (int mt = 0; mt < 4; mt++) {
#pragma unroll
        for (int nt = 0; nt < 4; nt++) {
            const float* cc = acc[mt * 4 + nt];
            int r  = m0 + wm * 64 + mt * 16 + (lane >> 2);
            int cl = n0 + wn * 32 + nt * 8 + ((lane & 3) << 1);
#pragma unroll
            for (int h2 = 0; h2 < 2; h2++) {
                int rr = r + h2 * 8;
                float2 v = make_float2(cc[h2 * 2], cc[h2 * 2 + 1]);
                if (mode == 0) {
                    *(float2*)(g_q + (size_t)rr * C_DIM + cl) = v;
                } else if (mode == 1) {
                    *(float2*)(g_k + (size_t)rr * C_DIM + cl) = v;
                } else if (mode == 3) {
                    *(float2*)(dst + (size_t)rr * C_DIM + cl) = v;
                } else {
                    const int bb = rr >> 10, t = rr & (T_DIM - 1);
                    const int h = cl >> 6, hd0 = cl & (HD - 1);
                    *(float2*)(dst + (((size_t)(bb * H_NUM + h)) * T_DIM + t) * HD + hd0) = v;
                }
            }
        }
    }
}

// ===========================================================================
// RoPE + RMSNorm + hi/lo conversion. y=0: q (scale folded), y=1: k (fp32 out
// + planes), y=2: v (planes from v_out).
// ===========================================================================
__global__ void rope_norm_kernel(float* __restrict__ k_out,
                                 const float* __restrict__ v_out)
{
    const int lane = threadIdx.x & 31;
    const int vec  = blockIdx.x * 8 + (threadIdx.x >> 5);
    const int t  = vec & (T_DIM - 1);
    const int bh = vec >> 10;
    const int b  = bh / H_NUM;
    const int h  = bh - b * H_NUM;
    const int iy = blockIdx.y;
    const size_t doff = ((size_t)bh * T_DIM + t) * HD;

    if (iy == 2) {
        const float x1 = v_out[doff + lane];
        const float x2 = v_out[doff + lane + 32];
        float h1 = bf16rt(x1), h2 = bf16rt(x2);
        g_vh[doff + lane]      = __float2bfloat16(h1);
        g_vh[doff + lane + 32] = __float2bfloat16(h2);
        g_vl[doff + lane]      = __float2bfloat16(x1 - h1);
        g_vl[doff + lane + 32] = __float2bfloat16(x2 - h2);
        return;
    }

    const bool is_q = (iy == 0);
    const float* src = (is_q ? g_q : g_k) +
                       ((size_t)(b * T_DIM + t)) * C_DIM + h * HD;
    const float x1 = src[lane];
    const float x2 = src[lane + 32];

    const float inv = (float)exp((double)lane * -0.28782313662425575);
    const float f = (float)t * inv;
    float s, c;
    sincosf(f, &s, &c);
    const float o1 = x1 * c - x2 * s;
    const float o2 = x1 * s + x2 * c;

    float ss = o1 * o1 + o2 * o2;
#pragma unroll
    for (int off = 16; off; off >>= 1)
        ss += __shfl_xor_sync(0xffffffffu, ss, off);
    const float rn = rsqrtf(ss * (1.0f / 64.0f) + 1e-6f);

    if (is_q) {
        const float QSC = 0.125f * 1.4426950408889634f;
        float q1 = o1 * rn * QSC, q2 = o2 * rn * QSC;
        float h1 = bf16rt(q1), h2 = bf16rt(q2);
        g_qh[doff + lane]      = __float2bfloat16(h1);
        g_qh[doff + lane + 32] = __float2bfloat16(h2);
        g_ql[doff + lane]      = __float2bfloat16(q1 - h1);
        g_ql[doff + lane + 32] = __float2bfloat16(q2 - h2);
    } else {
        float k1 = o1 * rn, k2 = o2 * rn;
        k_out[doff + lane]      = k1;
        k_out[doff + lane + 32] = k2;
        float h1 = bf16rt(k1), h2 = bf16rt(k2);
        g_kh[doff + lane]      = __float2bfloat16(h1);
        g_kh[doff + lane + 32] = __float2bfloat16(h2);
        g_kl[doff + lane]      = __float2bfloat16(k1 - h1);
        g_kl[doff + lane + 32] = __float2bfloat16(k2 - h2);
    }
}

// ===========================================================================
// Tensor-core flash attention, cp.async K/V double buffer.
// smem: Q planes 32KB + 2 KV stages x 64KB = 160KB.
// ===========================================================================
#define APLANE  16384
#define KVSTAGE (4 * APLANE)
#define ASMEM   (2 * APLANE + 2 * KVSTAGE)

__device__ __forceinline__ uint32_t aswz(int row, int seg) {
    return (uint32_t)(row * 128 + ((seg ^ (row & 7)) << 4));
}

__global__ __launch_bounds__(256, 1)
void attn_mma(void)
{
    extern __shared__ __align__(1024) unsigned char sm8[];
    const uint32_t base = smem_u32(sm8);
    const uint32_t Qh = base, Ql = base + APLANE;
    const uint32_t kvbase = base + 2 * APLANE;

    const int tid  = threadIdx.x;
    const int lane = tid & 31;
    const int wid  = tid >> 5;
    const int qt   = 7 - blockIdx.x;
    const int bh   = blockIdx.y;
    const int b    = bh / H_NUM;
    const int h    = bh - b * H_NUM;
    const int q0   = qt * 128;
    const int wr0  = wid * 16;

    const __nv_bfloat16* qh_g = g_qh + (size_t)bh * T_DIM * HD;
    const __nv_bfloat16* ql_g = g_ql + (size_t)bh * T_DIM * HD;
    const __nv_bfloat16* kh_g = g_kh + (size_t)bh * T_DIM * HD;
    const __nv_bfloat16* kl_g = g_kl + (size_t)bh * T_DIM * HD;
    const __nv_bfloat16* vh_g = g_vh + (size_t)bh * T_DIM * HD;
    const __nv_bfloat16* vl_g = g_vl + (size_t)bh * T_DIM * HD;

    auto copy_kv = [&](int kt, uint32_t st) {
        const int k0 = kt * 128;
#pragma unroll
        for (int i = 0; i < 4; i++) {
            int idx = tid + i * 256;
            int r = idx >> 3, sg = idx & 7;
            uint32_t so = aswz(r, sg);
            size_t go = (size_t)(k0 + r) * HD + sg * 8;
            cpa16(st + so,              kh_g + go);
            cpa16(st + APLANE + so,     kl_g + go);
            cpa16(st + 2 * APLANE + so, vh_g + go);
            cpa16(st + 3 * APLANE + so, vl_g + go);
        }
    };

    // Q copies + KV stage 0 (group 0)
#pragma unroll
    for (int i = 0; i < 4; i++) {
        int idx = tid + i * 256;
        int r = idx >> 3, sg = idx & 7;
        uint32_t so = aswz(r, sg);
        size_t go = (size_t)(q0 + r) * HD + sg * 8;
        cpa16(Qh + so, qh_g + go);
        cpa16(Ql + so, ql_g + go);
    }
    copy_kv(0, kvbase);
    CP_COMMIT();

    float o[8][4];
#pragma unroll
    for (int i = 0; i < 8; i++)
#pragma unroll
        for (int j = 0; j < 4; j++) o[i][j] = 0.0f;
    float m_a = -INFINITY, m_b = -INFINITY, l_a = 0.0f, l_b = 0.0f;

    for (int kt = 0; kt <= qt; kt++) {
        const uint32_t st = kvbase + (uint32_t)(kt & 1) * KVSTAGE;
        if (kt < qt) {
            copy_kv(kt + 1, kvbase + (uint32_t)((kt + 1) & 1) * KVSTAGE);
            CP_COMMIT();
            CP_WAIT(1);
        } else {
            CP_WAIT(0);
        }
        __syncthreads();
        const uint32_t sKh = st, sKl = st + APLANE;
        const uint32_t sVh = st + 2 * APLANE, sVl = st + 3 * APLANE;

        // ---- S = Qs @ K^T ----
        float s[16][4];
#pragma unroll
        for (int i = 0; i < 16; i++)
#pragma unroll
            for (int j = 0; j < 4; j++) s[i][j] = 0.0f;

#pragma unroll
        for (int ks = 0; ks < 4; ks++) {
            int arow = wr0 + (lane & 15);
            int aseg = ks * 2 + (lane >> 4);
            uint32_t aoff = aswz(arow, aseg);
            uint32_t ah[4], al[4];
            ldmx4(ah[0], ah[1], ah[2], ah[3], Qh + aoff);
            ldmx4(al[0], al[1], al[2], al[3], Ql + aoff);
#pragma unroll
            for (int np = 0; np < 8; np++) {
                int brow = np * 16 + (lane & 15);
                uint32_t boff = aswz(brow, aseg);
                uint32_t r0, r1, r2, r3;
                uint32_t bhf[2][2], blf[2][2];
                ldmx4(r0, r1, r2, r3, sKh + boff);
                bhf[0][0] = r0; bhf[0][1] = r2; bhf[1][0] = r1; bhf[1][1] = r3;
                ldmx4(r0, r1, r2, r3, sKl + boff);
                blf[0][0] = r0; blf[0][1] = r2; blf[1][0] = r1; blf[1][1] = r3;
#pragma unroll
                for (int g = 0; g < 2; g++) {
                    mma_bf16(s[np * 2 + g], ah, bhf[g]);
                    mma_bf16(s[np * 2 + g], ah, blf[g]);
                    mma_bf16(s[np * 2 + g], al, bhf[g]);
                }
            }
        }

        // ---- causal mask on diagonal tile ----
        if (kt == qt) {
            const int ra = (lane >> 2), cb = ((lane & 3) << 1);
#pragma unroll
            for (int nt = 0; nt < 16; nt++) {
#pragma unroll
                for (int j = 0; j < 4; j++) {
                    int col = nt * 8 + cb + (j & 1);
                    int row = wr0 + ra + ((j >> 1) << 3);
                    if (col > row) s[nt][j] = -INFINITY;
                }
            }
        }

        // ---- online softmax ----
        float mx_a = -INFINITY, mx_b = -INFINITY;
#pragma unroll
        for (int nt = 0; nt < 16; nt++) {
            mx_a = fmaxf(mx_a, fmaxf(s[nt][0], s[nt][1]));
            mx_b = fmaxf(mx_b, fmaxf(s[nt][2], s[nt][3]));
        }
        mx_a = fmaxf(mx_a, __shfl_xor_sync(0xffffffffu, mx_a, 1));
        mx_a = fmaxf(mx_a, __shfl_xor_sync(0xffffffffu, mx_a, 2));
        mx_b = fmaxf(mx_b, __shfl_xor_sync(0xffffffffu, mx_b, 1));
        mx_b = fmaxf(mx_b, __shfl_xor_sync(0xffffffffu, mx_b, 2));

        const float mn_a = fmaxf(m_a, mx_a);
        const float mn_b = fmaxf(m_b, mx_b);
        const float ca = ex2f(m_a - mn_a);
        const float cbf = ex2f(m_b - mn_b);
        m_a = mn_a; m_b = mn_b;

        float sa = 0.0f, sb = 0.0f;
#pragma unroll
        for (int nt = 0; nt < 16; nt++) {
            s[nt][0] = ex2f(s[nt][0] - mn_a);
            s[nt][1] = ex2f(s[nt][1] - mn_a);
            s[nt][2] = ex2f(s[nt][2] - mn_b);
            s[nt][3] = ex2f(s[nt][3] - mn_b);
            sa += s[nt][0] + s[nt][1];
            sb += s[nt][2] + s[nt][3];
        }
        sa += __shfl_xor_sync(0xffffffffu, sa, 1);
        sa += __shfl_xor_sync(0xffffffffu, sa, 2);
        sb += __shfl_xor_sync(0xffffffffu, sb, 1);
        sb += __shfl_xor_sync(0xffffffffu, sb, 2);
        l_a = l_a * ca + sa;
        l_b = l_b * cbf + sb;
#pragma unroll
        for (int i = 0; i < 8; i++) {
            o[i][0] *= ca; o[i][1] *= ca; o[i][2] *= cbf; o[i][3] *= cbf;
        }

        // ---- O += P @ V ----
#pragma unroll
        for (int kc = 0; kc < 8; kc++) {
            float p0h = bf16rt(s[2*kc][0]),   p1h = bf16rt(s[2*kc][1]);
            float p2h = bf16rt(s[2*kc][2]),   p3h = bf16rt(s[2*kc][3]);
            float q0h = bf16rt(s[2*kc+1][0]), q1h = bf16rt(s[2*kc+1][1]);
            float q2h = bf16rt(s[2*kc+1][2]), q3h = bf16rt(s[2*kc+1][3]);
            uint32_t pa[4], pl[4];
            pa[0] = pack_bf2(p0h, p1h);
            pa[1] = pack_bf2(p2h, p3h);
            pa[2] = pack_bf2(q0h, q1h);
            pa[3] = pack_bf2(q2h, q3h);
            pl[0] = pack_bf2(s[2*kc][0]-p0h,   s[2*kc][1]-p1h);
            pl[1] = pack_bf2(s[2*kc][2]-p2h,   s[2*kc][3]-p3h);
            pl[2] = pack_bf2(s[2*kc+1][0]-q0h, s[2*kc+1][1]-q1h);
            pl[3] = pack_bf2(s[2*kc+1][2]-q2h, s[2*kc+1][3]-q3h);

            int vrow = kc * 16 + (lane & 15);
#pragma unroll
            for (int s2 = 0; s2 < 4; s2++) {
                int vseg = s2 * 2 + (lane >> 4);
                uint32_t voff = aswz(vrow, vseg);
                uint32_t r0, r1, r2, r3;
                uint32_t vhf[2][2], vlf[2][2];
                ldmx4t(r0, r1, r2, r3, sVh + voff);
                vhf[0][0] = r0; vhf[0][1] = r1; vhf[1][0] = r2; vhf[1][1] = r3;
                ldmx4t(r0, r1, r2, r3, sVl + voff);
                vlf[0][0] = r0; vlf[0][1] = r1; vlf[1][0] = r2; vlf[1][1] = r3;
#pragma unroll
                for (int g = 0; g < 2; g++) {
                    mma_bf16(o[s2*2+g], pa, vhf[g]);
                    mma_bf16(o[s2*2+g], pa, vlf[g]);
                    mma_bf16(o[s2*2+g], pl, vhf[g]);
                }
            }
        }
        __syncthreads();
    }

    // ---- normalize + write y hi/lo planes (B,T,C row-major) ----
    const float ia = 1.0f / l_a, ib = 1.0f / l_b;
    const int ra = lane >> 2, cb = (lane & 3) << 1;
    const size_t ybase = ((size_t)(b * T_DIM + q0 + wr0 + ra)) * C_DIM + h * HD;
#pragma unroll
    for (int nt = 0; nt < 8; nt++) {
        int col = nt * 8 + cb;
        float y0 = o[nt][0] * ia, y1 = o[nt][1] * ia;
        float h0 = bf16rt(y0), h1 = bf16rt(y1);
        *(uint32_t*)(g_yh + ybase + col) = pack_bf2(h0, h1);
        *(uint32_t*)(g_yl + ybase + col) = pack_bf2(y0 - h0, y1 - h1);
        float y2 = o[nt][2] * ib, y3 = o[nt][3] * ib;
        float h2 = bf16rt(y2), h3 = bf16rt(y3);
        *(uint32_t*)(g_yh + ybase + 8 * C_DIM + col) = pack_bf2(h2, h3);
        *(uint32_t*)(g_yl + ybase + 8 * C_DIM + col) = pack_bf2(y2 - h2, y3 - h3);
    }
}

// ---------------------------------------------------------------------------
extern "C" void kernel_launch(void* const* d_in, const int* in_sizes, int n_in,
                              void* d_out, int out_size)
{
    const float* x  = (const float*)d_in[0];
    const float* Wq = (const float*)d_in[1];
    const float* Wk = (const float*)d_in[2];
    const float* Wv = (const float*)d_in[3];
    const float* Wo = (const float*)d_in[4];

    float* out   = (float*)d_out;
    float* y_out = out;
    float* k_out = out + S_ELE;
    float* v_out = out + 2 * (size_t)S_ELE;

    cudaFuncSetAttribute(split_gemm2, cudaFuncAttributeMaxDynamicSharedMemorySize,
                         GSMEM);
    cudaFuncSetAttribute(attn_mma, cudaFuncAttributeMaxDynamicSharedMemorySize,
                         ASMEM);

    // 0) convert x + weights to bf16 hi/lo planes
    prep_convert<<<(PREP_F4 + 255) / 256, 256>>>(x, Wq, Wk, Wv, Wo);

    // 1) QKV projections
    split_gemm2<<<dim3(C_DIM / 128, M_TOT / 128, 3), 256, GSMEM>>>(v_out, 1);

    // 2) RoPE + RMSNorm (+ hi/lo plane emission for q,k,v)
    rope_norm_kernel<<<dim3((B_DIM * H_NUM * T_DIM) / 8, 3), 256>>>(k_out, v_out);

    // 3) flash attention (writes y hi/lo planes)
    attn_mma<<<dim3(T_DIM / 128, B_DIM * H_NUM), 256, ASMEM>>>();

    // 4) output projection
    split_gemm2<<<dim3(C_DIM / 128, M_TOT / 128, 1), 256, GSMEM>>>(y_out, 0);
}

// round 8
// speedup vs baseline: 2.4040x; 1.0224x over previous
#include <cuda_runtime.h>
#include <cuda_bf16.h>
#include <math.h>
#include <stdint.h>

#define C_DIM 768
#define T_DIM 1024
#define B_DIM 8
#define H_NUM 12
#define HD    64
#define M_TOT 8192
#define S_ELE 6291456   /* 8*1024*768 */
#define X_ELE 6291456
#define W_ELE 589824    /* 768*768 */

// fp32 scratch (raw q/k for rope input)
static __device__ float g_q[S_ELE];
static __device__ float g_k[S_ELE];
// bf16 hi/lo planes
static __device__ __align__(16) __nv_bfloat16 g_xh[X_ELE], g_xl[X_ELE];
static __device__ __align__(16) __nv_bfloat16 g_wh[4 * W_ELE], g_wl[4 * W_ELE];
static __device__ __align__(16) __nv_bfloat16 g_qh[S_ELE], g_ql[S_ELE];
static __device__ __align__(16) __nv_bfloat16 g_kh[S_ELE], g_kl[S_ELE];
static __device__ __align__(16) __nv_bfloat16 g_vh[S_ELE], g_vl[S_ELE];
static __device__ __align__(16) __nv_bfloat16 g_yh[S_ELE], g_yl[S_ELE];

__device__ __forceinline__ uint32_t smem_u32(const void* p) {
    uint32_t a;
    asm("{ .reg .u64 t; cvta.to.shared.u64 t, %1; cvt.u32.u64 %0, t; }"
        : "=r"(a) : "l"(p));
    return a;
}
__device__ __forceinline__ float ex2f(float x) {
    float r;
    asm("ex2.approx.ftz.f32 %0, %1;" : "=f"(r) : "f"(x));
    return r;
}
__device__ __forceinline__ uint32_t pack_bf2(float lo, float hi) {
    __nv_bfloat16 a = __float2bfloat16(lo);
    __nv_bfloat16 b = __float2bfloat16(hi);
    return ((uint32_t)__bfloat16_as_ushort(b) << 16) | __bfloat16_as_ushort(a);
}
__device__ __forceinline__ float bf16rt(float x) {
    return __bfloat162float(__float2bfloat16(x));
}
__device__ __forceinline__ void cpa16(uint32_t dst, const void* src) {
    asm volatile("cp.async.cg.shared.global [%0], [%1], 16;"
                 :: "r"(dst), "l"(src) : "memory");
}
#define CP_COMMIT()  asm volatile("cp.async.commit_group;" ::: "memory")
#define CP_WAIT(n)   asm volatile("cp.async.wait_group %0;" :: "n"(n) : "memory")
__device__ __forceinline__ void ldmx4(uint32_t& r0, uint32_t& r1,
                                      uint32_t& r2, uint32_t& r3, uint32_t addr) {
    asm volatile("ldmatrix.sync.aligned.m8n8.x4.shared.b16 {%0,%1,%2,%3}, [%4];"
                 : "=r"(r0), "=r"(r1), "=r"(r2), "=r"(r3) : "r"(addr));
}
__device__ __forceinline__ void ldmx4t(uint32_t& r0, uint32_t& r1,
                                       uint32_t& r2, uint32_t& r3, uint32_t addr) {
    asm volatile("ldmatrix.sync.aligned.m8n8.x4.trans.shared.b16 {%0,%1,%2,%3}, [%4];"
                 : "=r"(r0), "=r"(r1), "=r"(r2), "=r"(r3) : "r"(addr));
}
__device__ __forceinline__ void mma_bf16(float* c, const uint32_t* a,
                                         const uint32_t* b) {
    asm volatile(
        "mma.sync.aligned.m16n8k16.row.col.f32.bf16.bf16.f32 "
        "{%0,%1,%2,%3},{%4,%5,%6,%7},{%8,%9},{%0,%1,%2,%3};"
        : "+f"(c[0]), "+f"(c[1]), "+f"(c[2]), "+f"(c[3])
        : "r"(a[0]), "r"(a[1]), "r"(a[2]), "r"(a[3]), "r"(b[0]), "r"(b[1]));
}

// ===========================================================================
// prep: convert x + 4 weights to bf16 hi/lo planes (one float4 per thread)
// ===========================================================================
#define PREP_F4 ((X_ELE + 4 * W_ELE) / 4)
__global__ void prep_convert(const float* __restrict__ x,
                             const float* __restrict__ Wq,
                             const float* __restrict__ Wk,
                             const float* __restrict__ Wv,
                             const float* __restrict__ Wo)
{
    size_t i4 = (size_t)blockIdx.x * 256 + threadIdx.x;
    if (i4 >= PREP_F4) return;
    size_t e = i4 * 4;
    const float* src;
    __nv_bfloat16 *dh, *dl;
    size_t off;
    if (e < X_ELE) { src = x; off = e; dh = g_xh; dl = g_xl; }
    else {
        size_t r = e - X_ELE;
        int w = (int)(r / W_ELE);
        off = r - (size_t)w * W_ELE;
        src = (w == 0) ? Wq : (w == 1) ? Wk : (w == 2) ? Wv : Wo;
        dh = g_wh + (size_t)w * W_ELE;
        dl = g_wl + (size_t)w * W_ELE;
    }
    float4 v = *(const float4*)(src + off);
    float h0 = bf16rt(v.x), h1 = bf16rt(v.y), h2 = bf16rt(v.z), h3 = bf16rt(v.w);
    uint2 ph = make_uint2(pack_bf2(h0, h1), pack_bf2(h2, h3));
    uint2 pl = make_uint2(pack_bf2(v.x - h0, v.y - h1), pack_bf2(v.z - h2, v.w - h3));
    *(uint2*)(dh + off) = ph;
    *(uint2*)(dl + off) = pl;
}

// ===========================================================================
// bf16 hi/lo split GEMM with cp.async (planes pre-converted).
// 128x128 CTA tile, 8 warps, K chunks of 32, 2-stage cp.async pipeline.
// modes: 0 -> g_q, 1 -> g_k, 2 -> dst (v BHTD), 3 -> dst (y BTC)
// ===========================================================================
#define NCHUNK 24
#define PLANE  8192
#define STAGE  32768
#define GSMEM  (2 * STAGE)

__device__ __forceinline__ uint32_t swz16(int row, int seg) {
    return (uint32_t)(row * 64 + ((seg ^ ((row >> 1) & 3)) << 4));
}

__global__ __launch_bounds__(256, 2)
void split_gemm2(float* __restrict__ dst, int is_qkv)
{
    extern __shared__ __align__(1024) unsigned char sm8[];
    const uint32_t base = smem_u32(sm8);
    const int tid  = threadIdx.x;
    const int lane = tid & 31;
    const int wid  = tid >> 5;
    const int wm   = wid >> 2;
    const int wn   = wid & 3;
    const int n0 = blockIdx.x * 128;
    const int m0 = blockIdx.y * 128;

    int mode;
    const __nv_bfloat16 *Ah, *Al, *Bh, *Bl;
    if (is_qkv) {
        mode = blockIdx.z;
        Ah = g_xh; Al = g_xl;
        Bh = g_wh + (size_t)mode * W_ELE;
        Bl = g_wl + (size_t)mode * W_ELE;
    } else {
        mode = 3;
        Ah = g_yh; Al = g_yl;
        Bh = g_wh + 3 * (size_t)W_ELE;
        Bl = g_wl + 3 * (size_t)W_ELE;
    }
    Ah += (size_t)m0 * C_DIM; Al += (size_t)m0 * C_DIM;
    Bh += (size_t)n0 * C_DIM; Bl += (size_t)n0 * C_DIM;

    float acc[16][4];
#pragma unroll
    for (int i = 0; i < 16; i++)
#pragma unroll
        for (int j = 0; j < 4; j++) acc[i][j] = 0.0f;

    // copy lambda: chunk c into stage buffer
    auto copy_chunk = [&](int c, uint32_t st) {
        const int k0 = c * 32;
#pragma unroll
        for (int i = 0; i < 2; i++) {
            int idx = tid + i * 256;
            int r = idx >> 2, sg = idx & 3;
            uint32_t so = swz16(r, sg);
            size_t go = (size_t)r * C_DIM + k0 + sg * 8;
            cpa16(st + so,             Ah + go);
            cpa16(st + PLANE + so,     Al + go);
            cpa16(st + 2 * PLANE + so, Bh + go);
            cpa16(st + 3 * PLANE + so, Bl + go);
        }
    };

    copy_chunk(0, base);
    CP_COMMIT();

    for (int c = 0; c < NCHUNK; c++) {
        const uint32_t st = base + (uint32_t)(c & 1) * STAGE;
        if (c + 1 < NCHUNK) {
            copy_chunk(c + 1, base + (uint32_t)((c + 1) & 1) * STAGE);
            CP_COMMIT();
            CP_WAIT(1);
        } else {
            CP_WAIT(0);
        }
        __syncthreads();

#pragma unroll
        for (int ks = 0; ks < 2; ks++) {
            uint32_t bh[4][2], bl[4][2];
#pragma unroll
            for (int g = 0; g < 2; g++) {
                int row = wn * 32 + g * 16 + (lane & 15);
                int sg = 2 * ks + (lane >> 4);
                uint32_t off = swz16(row, sg);
                uint32_t r0, r1, r2, r3;
                ldmx4(r0, r1, r2, r3, st + 2 * PLANE + off);
                bh[2 * g][0] = r0; bh[2 * g + 1][0] = r1;
                bh[2 * g][1] = r2; bh[2 * g + 1][1] = r3;
                ldmx4(r0, r1, r2, r3, st + 3 * PLANE + off);
                bl[2 * g][0] = r0; bl[2 * g + 1][0] = r1;
                bl[2 * g][1] = r2; bl[2 * g + 1][1] = r3;
            }
#pragma unroll
            for (int mt = 0; mt < 4; mt++) {
                int row = wm * 64 + mt * 16 + (lane & 15);
                int sg = 2 * ks + (lane >> 4);
                uint32_t off = swz16(row, sg);
                uint32_t ah[4], al[4];
                ldmx4(ah[0], ah[1], ah[2], ah[3], st + off);
                ldmx4(al[0], al[1], al[2], al[3], st + PLANE + off);
#pragma unroll
                for (int nt = 0; nt < 4; nt++) {
                    mma_bf16(acc[mt * 4 + nt], ah, bh[nt]);
                    mma_bf16(acc[mt * 4 + nt], ah, bl[nt]);
                    mma_bf16(acc[mt * 4 + nt], al, bh[nt]);
                }
            }
        }
        __syncthreads();
    }

#pragma unroll
    for (int mt = 0; mt < 4; mt++) {
#pragma unroll
        for (int nt = 0; nt < 4; nt++) {
            const float* cc = acc[mt * 4 + nt];
            int r  = m0 + wm * 64 + mt * 16 + (lane >> 2);
            int cl = n0 + wn * 32 + nt * 8 + ((lane & 3) << 1);
#pragma unroll
            for (int h2 = 0; h2 < 2; h2++) {
                int rr = r + h2 * 8;
                float2 v = make_float2(cc[h2 * 2], cc[h2 * 2 + 1]);
                if (mode == 0) {
                    *(float2*)(g_q + (size_t)rr * C_DIM + cl) = v;
                } else if (mode == 1) {
                    *(float2*)(g_k + (size_t)rr * C_DIM + cl) = v;
                } else if (mode == 3) {
                    *(float2*)(dst + (size_t)rr * C_DIM + cl) = v;
                } else {
                    const int bb = rr >> 10, t = rr & (T_DIM - 1);
                    const int h = cl >> 6, hd0 = cl & (HD - 1);
                    *(float2*)(dst + (((size_t)(bb * H_NUM + h)) * T_DIM + t) * HD + hd0) = v;
                }
            }
        }
    }
}

// ===========================================================================
// RoPE + RMSNorm + hi/lo conversion. y=0: q (scale folded), y=1: k (fp32 out
// + planes), y=2: v (planes from v_out).
// ===========================================================================
__global__ void rope_norm_kernel(float* __restrict__ k_out,
                                 const float* __restrict__ v_out)
{
    const int lane = threadIdx.x & 31;
    const int vec  = blockIdx.x * 8 + (threadIdx.x >> 5);
    const int t  = vec & (T_DIM - 1);
    const int bh = vec >> 10;
    const int b  = bh / H_NUM;
    const int h  = bh - b * H_NUM;
    const int iy = blockIdx.y;
    const size_t doff = ((size_t)bh * T_DIM + t) * HD;

    if (iy == 2) {
        const float x1 = v_out[doff + lane];
        const float x2 = v_out[doff + lane + 32];
        float h1 = bf16rt(x1), h2 = bf16rt(x2);
        g_vh[doff + lane]      = __float2bfloat16(h1);
        g_vh[doff + lane + 32] = __float2bfloat16(h2);
        g_vl[doff + lane]      = __float2bfloat16(x1 - h1);
        g_vl[doff + lane + 32] = __float2bfloat16(x2 - h2);
        return;
    }

    const bool is_q = (iy == 0);
    const float* src = (is_q ? g_q : g_k) +
                       ((size_t)(b * T_DIM + t)) * C_DIM + h * HD;
    const float x1 = src[lane];
    const float x2 = src[lane + 32];

    const float inv = (float)exp((double)lane * -0.28782313662425575);
    const float f = (float)t * inv;
    float s, c;
    sincosf(f, &s, &c);
    const float o1 = x1 * c - x2 * s;
    const float o2 = x1 * s + x2 * c;

    float ss = o1 * o1 + o2 * o2;
#pragma unroll
    for (int off = 16; off; off >>= 1)
        ss += __shfl_xor_sync(0xffffffffu, ss, off);
    const float rn = rsqrtf(ss * (1.0f / 64.0f) + 1e-6f);

    if (is_q) {
        const float QSC = 0.125f * 1.4426950408889634f;
        float q1 = o1 * rn * QSC, q2 = o2 * rn * QSC;
        float h1 = bf16rt(q1), h2 = bf16rt(q2);
        g_qh[doff + lane]      = __float2bfloat16(h1);
        g_qh[doff + lane + 32] = __float2bfloat16(h2);
        g_ql[doff + lane]      = __float2bfloat16(q1 - h1);
        g_ql[doff + lane + 32] = __float2bfloat16(q2 - h2);
    } else {
        float k1 = o1 * rn, k2 = o2 * rn;
        k_out[doff + lane]      = k1;
        k_out[doff + lane + 32] = k2;
        float h1 = bf16rt(k1), h2 = bf16rt(k2);
        g_kh[doff + lane]      = __float2bfloat16(h1);
        g_kh[doff + lane + 32] = __float2bfloat16(h2);
        g_kl[doff + lane]      = __float2bfloat16(k1 - h1);
        g_kl[doff + lane + 32] = __float2bfloat16(k2 - h2);
    }
}

// ===========================================================================
// Tensor-core flash attention, cp.async K/V double buffer.
// smem: Q planes 32KB + 2 KV stages x 64KB = 160KB.
// ===========================================================================
#define APLANE  16384
#define KVSTAGE (4 * APLANE)
#define ASMEM   (2 * APLANE + 2 * KVSTAGE)

__device__ __forceinline__ uint32_t aswz(int row, int seg) {
    return (uint32_t)(row * 128 + ((seg ^ (row & 7)) << 4));
}

__global__ __launch_bounds__(256, 1)
void attn_mma(void)
{
    extern __shared__ __align__(1024) unsigned char sm8[];
    const uint32_t base = smem_u32(sm8);
    const uint32_t Qh = base, Ql = base + APLANE;
    const uint32_t kvbase = base + 2 * APLANE;

    const int tid  = threadIdx.x;
    const int lane = tid & 31;
    const int wid  = tid >> 5;
    const int qt   = 7 - blockIdx.x;
    const int bh   = blockIdx.y;
    const int b    = bh / H_NUM;
    const int h    = bh - b * H_NUM;
    const int q0   = qt * 128;
    const int wr0  = wid * 16;

    const __nv_bfloat16* qh_g = g_qh + (size_t)bh * T_DIM * HD;
    const __nv_bfloat16* ql_g = g_ql + (size_t)bh * T_DIM * HD;
    const __nv_bfloat16* kh_g = g_kh + (size_t)bh * T_DIM * HD;
    const __nv_bfloat16* kl_g = g_kl + (size_t)bh * T_DIM * HD;
    const __nv_bfloat16* vh_g = g_vh + (size_t)bh * T_DIM * HD;
    const __nv_bfloat16* vl_g = g_vl + (size_t)bh * T_DIM * HD;

    auto copy_kv = [&](int kt, uint32_t st) {
        const int k0 = kt * 128;
#pragma unroll
        for (int i = 0; i < 4; i++) {
            int idx = tid + i * 256;
            int r = idx >> 3, sg = idx & 7;
            uint32_t so = aswz(r, sg);
            size_t go = (size_t)(k0 + r) * HD + sg * 8;
            cpa16(st + so,              kh_g + go);
            cpa16(st + APLANE + so,     kl_g + go);
            cpa16(st + 2 * APLANE + so, vh_g + go);
            cpa16(st + 3 * APLANE + so, vl_g + go);
        }
    };

    // Q copies + KV stage 0 (group 0)
#pragma unroll
    for (int i = 0; i < 4; i++) {
        int idx = tid + i * 256;
        int r = idx >> 3, sg = idx & 7;
        uint32_t so = aswz(r, sg);
        size_t go = (size_t)(q0 + r) * HD + sg * 8;
        cpa16(Qh + so, qh_g + go);
        cpa16(Ql + so, ql_g + go);
    }
    copy_kv(0, kvbase);
    CP_COMMIT();

    float o[8][4];
#pragma unroll
    for (int i = 0; i < 8; i++)
#pragma unroll
        for (int j = 0; j < 4; j++) o[i][j] = 0.0f;
    float m_a = -INFINITY, m_b = -INFINITY, l_a = 0.0f, l_b = 0.0f;

    for (int kt = 0; kt <= qt; kt++) {
        const uint32_t st = kvbase + (uint32_t)(kt & 1) * KVSTAGE;
        if (kt < qt) {
            copy_kv(kt + 1, kvbase + (uint32_t)((kt + 1) & 1) * KVSTAGE);
            CP_COMMIT();
            CP_WAIT(1);
        } else {
            CP_WAIT(0);
        }
        __syncthreads();
        const uint32_t sKh = st, sKl = st + APLANE;
        const uint32_t sVh = st + 2 * APLANE, sVl = st + 3 * APLANE;

        // ---- S = Qs @ K^T ----
        float s[16][4];
#pragma unroll
        for (int i = 0; i < 16; i++)
#pragma unroll
            for (int j = 0; j < 4; j++) s[i][j] = 0.0f;

#pragma unroll
        for (int ks = 0; ks < 4; ks++) {
            int arow = wr0 + (lane & 15);
            int aseg = ks * 2 + (lane >> 4);
            uint32_t aoff = aswz(arow, aseg);
            uint32_t ah[4], al[4];
            ldmx4(ah[0], ah[1], ah[2], ah[3], Qh + aoff);
            ldmx4(al[0], al[1], al[2], al[3], Ql + aoff);
#pragma unroll
            for (int np = 0; np < 8; np++) {
                int brow = np * 16 + (lane & 15);
                uint32_t boff = aswz(brow, aseg);
                uint32_t r0, r1, r2, r3;
                uint32_t bhf[2][2], blf[2][2];
                ldmx4(r0, r1, r2, r3, sKh + boff);
                bhf[0][0] = r0; bhf[0][1] = r2; bhf[1][0] = r1; bhf[1][1] = r3;
                ldmx4(r0, r1, r2, r3, sKl + boff);
                blf[0][0] = r0; blf[0][1] = r2; blf[1][0] = r1; blf[1][1] = r3;
#pragma unroll
                for (int g = 0; g < 2; g++) {
                    mma_bf16(s[np * 2 + g], ah, bhf[g]);
                    mma_bf16(s[np * 2 + g], ah, blf[g]);
                    mma_bf16(s[np * 2 + g], al, bhf[g]);
                }
            }
        }

        // ---- causal mask on diagonal tile ----
        if (kt == qt) {
            const int ra = (lane >> 2), cb = ((lane & 3) << 1);
#pragma unroll
            for (int nt = 0; nt < 16; nt++) {
#pragma unroll
                for (int j = 0; j < 4; j++) {
                    int col = nt * 8 + cb + (j & 1);
                    int row = wr0 + ra + ((j >> 1) << 3);
                    if (col > row) s[nt][j] = -INFINITY;
                }
            }
        }

        // ---- online softmax ----
        float mx_a = -INFINITY, mx_b = -INFINITY;
#pragma unroll
        for (int nt = 0; nt < 16; nt++) {
            mx_a = fmaxf(mx_a, fmaxf(s[nt][0], s[nt][1]));
            mx_b = fmaxf(mx_b, fmaxf(s[nt][2], s[nt][3]));
        }
        mx_a = fmaxf(mx_a, __shfl_xor_sync(0xffffffffu, mx_a, 1));
        mx_a = fmaxf(mx_a, __shfl_xor_sync(0xffffffffu, mx_a, 2));
        mx_b = fmaxf(mx_b, __shfl_xor_sync(0xffffffffu, mx_b, 1));
        mx_b = fmaxf(mx_b, __shfl_xor_sync(0xffffffffu, mx_b, 2));

        const float mn_a = fmaxf(m_a, mx_a);
        const float mn_b = fmaxf(m_b, mx_b);
        const float ca = ex2f(m_a - mn_a);
        const float cbf = ex2f(m_b - mn_b);
        m_a = mn_a; m_b = mn_b;

        float sa = 0.0f, sb = 0.0f;
#pragma unroll
        for (int nt = 0; nt < 16; nt++) {
            s[nt][0] = ex2f(s[nt][0] - mn_a);
            s[nt][1] = ex2f(s[nt][1] - mn_a);
            s[nt][2] = ex2f(s[nt][2] - mn_b);
            s[nt][3] = ex2f(s[nt][3] - mn_b);
            sa += s[nt][0] + s[nt][1];
            sb += s[nt][2] + s[nt][3];
        }
        sa += __shfl_xor_sync(0xffffffffu, sa, 1);
        sa += __shfl_xor_sync(0xffffffffu, sa, 2);
        sb += __shfl_xor_sync(0xffffffffu, sb, 1);
        sb += __shfl_xor_sync(0xffffffffu, sb, 2);
        l_a = l_a * ca + sa;
        l_b = l_b * cbf + sb;
#pragma unroll
        for (int i = 0; i < 8; i++) {
            o[i][0] *= ca; o[i][1] *= ca; o[i][2] *= cbf; o[i][3] *= cbf;
        }

        // ---- O += P @ V ----
#pragma unroll
        for (int kc = 0; kc < 8; kc++) {
            float p0h = bf16rt(s[2*kc][0]),   p1h = bf16rt(s[2*kc][1]);
            float p2h = bf16rt(s[2*kc][2]),   p3h = bf16rt(s[2*kc][3]);
            float q0h = bf16rt(s[2*kc+1][0]), q1h = bf16rt(s[2*kc+1][1]);
            float q2h = bf16rt(s[2*kc+1][2]), q3h = bf16rt(s[2*kc+1][3]);
            uint32_t pa[4], pl[4];
            pa[0] = pack_bf2(p0h, p1h);
            pa[1] = pack_bf2(p2h, p3h);
            pa[2] = pack_bf2(q0h, q1h);
            pa[3] = pack_bf2(q2h, q3h);
            pl[0] = pack_bf2(s[2*kc][0]-p0h,   s[2*kc][1]-p1h);
            pl[1] = pack_bf2(s[2*kc][2]-p2h,   s[2*kc][3]-p3h);
            pl[2] = pack_bf2(s[2*kc+1][0]-q0h, s[2*kc+1][1]-q1h);
            pl[3] = pack_bf2(s[2*kc+1][2]-q2h, s[2*kc+1][3]-q3h);

            int vrow = kc * 16 + (lane & 15);
#pragma unroll
            for (int s2 = 0; s2 < 4; s2++) {
                int vseg = s2 * 2 + (lane >> 4);
                uint32_t voff = aswz(vrow, vseg);
                uint32_t r0, r1, r2, r3;
                uint32_t vhf[2][2], vlf[2][2];
                ldmx4t(r0, r1, r2, r3, sVh + voff);
                vhf[0][0] = r0; vhf[0][1] = r1; vhf[1][0] = r2; vhf[1][1] = r3;
                ldmx4t(r0, r1, r2, r3, sVl + voff);
                vlf[0][0] = r0; vlf[0][1] = r1; vlf[1][0] = r2; vlf[1][1] = r3;
#pragma unroll
                for (int g = 0; g < 2; g++) {
                    mma_bf16(o[s2*2+g], pa, vhf[g]);
                    mma_bf16(o[s2*2+g], pa, vlf[g]);
                    mma_bf16(o[s2*2+g], pl, vhf[g]);
                }
            }
        }
        __syncthreads();
    }

    // ---- normalize + write y hi/lo planes (B,T,C row-major) ----
    const float ia = 1.0f / l_a, ib = 1.0f / l_b;
    const int ra = lane >> 2, cb = (lane & 3) << 1;
    const size_t ybase = ((size_t)(b * T_DIM + q0 + wr0 + ra)) * C_DIM + h * HD;
#pragma unroll
    for (int nt = 0; nt < 8; nt++) {
        int col = nt * 8 + cb;
        float y0 = o[nt][0] * ia, y1 = o[nt][1] * ia;
        float h0 = bf16rt(y0), h1 = bf16rt(y1);
        *(uint32_t*)(g_yh + ybase + col) = pack_bf2(h0, h1);
        *(uint32_t*)(g_yl + ybase + col) = pack_bf2(y0 - h0, y1 - h1);
        float y2 = o[nt][2] * ib, y3 = o[nt][3] * ib;
        float h2 = bf16rt(y2), h3 = bf16rt(y3);
        *(uint32_t*)(g_yh + ybase + 8 * C_DIM + col) = pack_bf2(h2, h3);
        *(uint32_t*)(g_yl + ybase + 8 * C_DIM + col) = pack_bf2(y2 - h2, y3 - h3);
    }
}

// ---------------------------------------------------------------------------
extern "C" void kernel_launch(void* const* d_in, const int* in_sizes, int n_in,
                              void* d_out, int out_size)
{
    const float* x  = (const float*)d_in[0];
    const float* Wq = (const float*)d_in[1];
    const float* Wk = (const float*)d_in[2];
    const float* Wv = (const float*)d_in[3];
    const float* Wo = (const float*)d_in[4];

    float* out   = (float*)d_out;
    float* y_out = out;
    float* k_out = out + S_ELE;
    float* v_out = out + 2 * (size_t)S_ELE;

    cudaFuncSetAttribute(split_gemm2, cudaFuncAttributeMaxDynamicSharedMemorySize,
                         GSMEM);
    cudaFuncSetAttribute(attn_mma, cudaFuncAttributeMaxDynamicSharedMemorySize,
                         ASMEM);

    // 0) convert x + weights to bf16 hi/lo planes
    prep_convert<<<(PREP_F4 + 255) / 256, 256>>>(x, Wq, Wk, Wv, Wo);

    // 1) QKV projections
    split_gemm2<<<dim3(C_DIM / 128, M_TOT / 128, 3), 256, GSMEM>>>(v_out, 1);

    // 2) RoPE + RMSNorm (+ hi/lo plane emission for q,k,v)
    rope_norm_kernel<<<dim3((B_DIM * H_NUM * T_DIM) / 8, 3), 256>>>(k_out, v_out);

    // 3) flash attention (writes y hi/lo planes)
    attn_mma<<<dim3(T_DIM / 128, B_DIM * H_NUM), 256, ASMEM>>>();

    // 4) output projection
    split_gemm2<<<dim3(C_DIM / 128, M_TOT / 128, 1), 256, GSMEM>>>(y_out, 0);
}

// round 9
// speedup vs baseline: 2.8900x; 1.2022x over previous
#include <cuda_runtime.h>
#include <cuda_fp16.h>
#include <math.h>
#include <stdint.h>

#define C_DIM 768
#define T_DIM 1024
#define B_DIM 8
#define H_NUM 12
#define HD    64
#define M_TOT 8192
#define S_ELE 6291456   /* 8*1024*768 */
#define X_ELE 6291456
#define W_ELE 589824    /* 768*768 */

// fp32 scratch (raw q/k for rope input)
static __device__ float g_q[S_ELE];
static __device__ float g_k[S_ELE];
// fp16 planes: A-operands hi/lo (exact), B-operands single (except K,V)
static __device__ __align__(16) __half g_xh[X_ELE], g_xl[X_ELE];
static __device__ __align__(16) __half g_w[4 * W_ELE];           // single
static __device__ __align__(16) __half g_qh[S_ELE], g_ql[S_ELE];
static __device__ __align__(16) __half g_kh[S_ELE], g_kl[S_ELE];
static __device__ __align__(16) __half g_vh[S_ELE], g_vl[S_ELE];
static __device__ __align__(16) __half g_yh[S_ELE], g_yl[S_ELE];

__device__ __forceinline__ uint32_t smem_u32(const void* p) {
    uint32_t a;
    asm("{ .reg .u64 t; cvta.to.shared.u64 t, %1; cvt.u32.u64 %0, t; }"
        : "=r"(a) : "l"(p));
    return a;
}
__device__ __forceinline__ float ex2f(float x) {
    float r;
    asm("ex2.approx.ftz.f32 %0, %1;" : "=f"(r) : "f"(x));
    return r;
}
// pack (first -> low half, second -> high half)
__device__ __forceinline__ uint32_t pack_h2(float lo, float hi) {
    uint32_t u;
    asm("cvt.rn.f16x2.f32 %0, %1, %2;" : "=r"(u) : "f"(hi), "f"(lo));
    return u;
}
__device__ __forceinline__ float h16rt(float x) {
    return __half2float(__float2half_rn(x));
}
__device__ __forceinline__ void cpa16(uint32_t dst, const void* src) {
    asm volatile("cp.async.cg.shared.global [%0], [%1], 16;"
                 :: "r"(dst), "l"(src) : "memory");
}
#define CP_COMMIT()  asm volatile("cp.async.commit_group;" ::: "memory")
#define CP_WAIT(n)   asm volatile("cp.async.wait_group %0;" :: "n"(n) : "memory")
__device__ __forceinline__ void ldmx4(uint32_t& r0, uint32_t& r1,
                                      uint32_t& r2, uint32_t& r3, uint32_t addr) {
    asm volatile("ldmatrix.sync.aligned.m8n8.x4.shared.b16 {%0,%1,%2,%3}, [%4];"
                 : "=r"(r0), "=r"(r1), "=r"(r2), "=r"(r3) : "r"(addr));
}
__device__ __forceinline__ void ldmx4t(uint32_t& r0, uint32_t& r1,
                                       uint32_t& r2, uint32_t& r3, uint32_t addr) {
    asm volatile("ldmatrix.sync.aligned.m8n8.x4.trans.shared.b16 {%0,%1,%2,%3}, [%4];"
                 : "=r"(r0), "=r"(r1), "=r"(r2), "=r"(r3) : "r"(addr));
}
__device__ __forceinline__ void mma_f16(float* c, const uint32_t* a,
                                        const uint32_t* b) {
    asm volatile(
        "mma.sync.aligned.m16n8k16.row.col.f32.f16.f16.f32 "
        "{%0,%1,%2,%3},{%4,%5,%6,%7},{%8,%9},{%0,%1,%2,%3};"
        : "+f"(c[0]), "+f"(c[1]), "+f"(c[2]), "+f"(c[3])
        : "r"(a[0]), "r"(a[1]), "r"(a[2]), "r"(a[3]), "r"(b[0]), "r"(b[1]));
}

// ===========================================================================
// prep: x -> fp16 hi/lo planes; weights -> single fp16 plane
// ===========================================================================
#define PREP_F4 ((X_ELE + 4 * W_ELE) / 4)
__global__ void prep_convert(const float* __restrict__ x,
                             const float* __restrict__ Wq,
                             const float* __restrict__ Wk,
                             const float* __restrict__ Wv,
                             const float* __restrict__ Wo)
{
    size_t i4 = (size_t)blockIdx.x * 256 + threadIdx.x;
    if (i4 >= PREP_F4) return;
    size_t e = i4 * 4;
    if (e < X_ELE) {
        float4 v = *(const float4*)(x + e);
        float h0 = h16rt(v.x), h1 = h16rt(v.y), h2 = h16rt(v.z), h3 = h16rt(v.w);
        *(uint2*)(g_xh + e) = make_uint2(pack_h2(h0, h1), pack_h2(h2, h3));
        *(uint2*)(g_xl + e) = make_uint2(pack_h2(v.x - h0, v.y - h1),
                                         pack_h2(v.z - h2, v.w - h3));
    } else {
        size_t r = e - X_ELE;
        int w = (int)(r / W_ELE);
        size_t off = r - (size_t)w * W_ELE;
        const float* src = (w == 0) ? Wq : (w == 1) ? Wk : (w == 2) ? Wv : Wo;
        float4 v = *(const float4*)(src + off);
        *(uint2*)(g_w + (size_t)w * W_ELE + off) =
            make_uint2(pack_h2(v.x, v.y), pack_h2(v.z, v.w));
    }
}

// ===========================================================================
// fp16 GEMM: A hi/lo (exact) x B single. 2 MMAs per tile-k.
// 128x128 CTA tile, 8 warps, K chunks 32, 2-stage cp.async pipeline.
// modes: 0 -> g_q, 1 -> g_k, 2 -> dst (v BHTD), 3 -> dst (y BTC)
// ===========================================================================
#define NCHUNK 24
#define PLANE  8192
#define STAGE  (3 * PLANE)
#define GSMEM  (2 * STAGE)

__device__ __forceinline__ uint32_t swz16(int row, int seg) {
    return (uint32_t)(row * 64 + ((seg ^ ((row >> 1) & 3)) << 4));
}

__global__ __launch_bounds__(256, 2)
void split_gemm2(float* __restrict__ dst, int is_qkv)
{
    extern __shared__ __align__(1024) unsigned char sm8[];
    const uint32_t base = smem_u32(sm8);
    const int tid  = threadIdx.x;
    const int lane = tid & 31;
    const int wid  = tid >> 5;
    const int wm   = wid >> 2;
    const int wn   = wid & 3;
    const int n0 = blockIdx.x * 128;
    const int m0 = blockIdx.y * 128;

    int mode;
    const __half *Ah, *Al, *Bs;
    if (is_qkv) {
        mode = blockIdx.z;
        Ah = g_xh; Al = g_xl;
        Bs = g_w + (size_t)mode * W_ELE;
    } else {
        mode = 3;
        Ah = g_yh; Al = g_yl;
        Bs = g_w + 3 * (size_t)W_ELE;
    }
    Ah += (size_t)m0 * C_DIM; Al += (size_t)m0 * C_DIM;
    Bs += (size_t)n0 * C_DIM;

    float acc[16][4];
#pragma unroll
    for (int i = 0; i < 16; i++)
#pragma unroll
        for (int j = 0; j < 4; j++) acc[i][j] = 0.0f;

    auto copy_chunk = [&](int c, uint32_t st) {
        const int k0 = c * 32;
#pragma unroll
        for (int i = 0; i < 2; i++) {
            int idx = tid + i * 256;
            int r = idx >> 2, sg = idx & 3;
            uint32_t so = swz16(r, sg);
            size_t go = (size_t)r * C_DIM + k0 + sg * 8;
            cpa16(st + so,             Ah + go);
            cpa16(st + PLANE + so,     Al + go);
            cpa16(st + 2 * PLANE + so, Bs + go);
        }
    };

    copy_chunk(0, base);
    CP_COMMIT();

    for (int c = 0; c < NCHUNK; c++) {
        const uint32_t st = base + (uint32_t)(c & 1) * STAGE;
        if (c + 1 < NCHUNK) {
            copy_chunk(c + 1, base + (uint32_t)((c + 1) & 1) * STAGE);
            CP_COMMIT();
            CP_WAIT(1);
        } else {
            CP_WAIT(0);
        }
        __syncthreads();

#pragma unroll
        for (int ks = 0; ks < 2; ks++) {
            uint32_t bf[4][2];
#pragma unroll
            for (int g = 0; g < 2; g++) {
                int row = wn * 32 + g * 16 + (lane & 15);
                int sg = 2 * ks + (lane >> 4);
                uint32_t off = swz16(row, sg);
                uint32_t r0, r1, r2, r3;
                ldmx4(r0, r1, r2, r3, st + 2 * PLANE + off);
                bf[2 * g][0] = r0; bf[2 * g + 1][0] = r1;
                bf[2 * g][1] = r2; bf[2 * g + 1][1] = r3;
            }
#pragma unroll
            for (int mt = 0; mt < 4; mt++) {
                int row = wm * 64 + mt * 16 + (lane & 15);
                int sg = 2 * ks + (lane >> 4);
                uint32_t off = swz16(row, sg);
                uint32_t ah[4], al[4];
                ldmx4(ah[0], ah[1], ah[2], ah[3], st + off);
                ldmx4(al[0], al[1], al[2], al[3], st + PLANE + off);
#pragma unroll
                for (int nt = 0; nt < 4; nt++) {
                    mma_f16(acc[mt * 4 + nt], ah, bf[nt]);
                    mma_f16(acc[mt * 4 + nt], al, bf[nt]);
                }
            }
        }
        __syncthreads();
    }

#pragma unroll
    for (int mt = 0; mt < 4; mt++) {
#pragma unroll
        for (int nt = 0; nt < 4; nt++) {
            const float* cc = acc[mt * 4 + nt];
            int r  = m0 + wm * 64 + mt * 16 + (lane >> 2);
            int cl = n0 + wn * 32 + nt * 8 + ((lane & 3) << 1);
#pragma unroll
            for (int h2 = 0; h2 < 2; h2++) {
                int rr = r + h2 * 8;
                float2 v = make_float2(cc[h2 * 2], cc[h2 * 2 + 1]);
                if (mode == 0) {
                    *(float2*)(g_q + (size_t)rr * C_DIM + cl) = v;
                } else if (mode == 1) {
                    *(float2*)(g_k + (size_t)rr * C_DIM + cl) = v;
                } else if (mode == 3) {
                    *(float2*)(dst + (size_t)rr * C_DIM + cl) = v;
                } else {
                    const int bb = rr >> 10, t = rr & (T_DIM - 1);
                    const int h = cl >> 6, hd0 = cl & (HD - 1);
                    *(float2*)(dst + (((size_t)(bb * H_NUM + h)) * T_DIM + t) * HD + hd0) = v;
                }
            }
        }
    }
}

// ===========================================================================
// RoPE + RMSNorm + fp16 plane emission. y=0: q (scale folded), y=1: k,
// y=2: v (from v_out).
// ===========================================================================
__global__ void rope_norm_kernel(float* __restrict__ k_out,
                                 const float* __restrict__ v_out)
{
    const int lane = threadIdx.x & 31;
    const int vec  = blockIdx.x * 8 + (threadIdx.x >> 5);
    const int t  = vec & (T_DIM - 1);
    const int bh = vec >> 10;
    const int b  = bh / H_NUM;
    const int h  = bh - b * H_NUM;
    const int iy = blockIdx.y;
    const size_t doff = ((size_t)bh * T_DIM + t) * HD;

    if (iy == 2) {
        const float x1 = v_out[doff + lane];
        const float x2 = v_out[doff + lane + 32];
        float h1 = h16rt(x1), h2 = h16rt(x2);
        g_vh[doff + lane]      = __float2half_rn(h1);
        g_vh[doff + lane + 32] = __float2half_rn(h2);
        g_vl[doff + lane]      = __float2half_rn(x1 - h1);
        g_vl[doff + lane + 32] = __float2half_rn(x2 - h2);
        return;
    }

    const bool is_q = (iy == 0);
    const float* src = (is_q ? g_q : g_k) +
                       ((size_t)(b * T_DIM + t)) * C_DIM + h * HD;
    const float x1 = src[lane];
    const float x2 = src[lane + 32];

    const float inv = (float)exp((double)lane * -0.28782313662425575);
    const float f = (float)t * inv;
    float s, c;
    sincosf(f, &s, &c);
    const float o1 = x1 * c - x2 * s;
    const float o2 = x1 * s + x2 * c;

    float ss = o1 * o1 + o2 * o2;
#pragma unroll
    for (int off = 16; off; off >>= 1)
        ss += __shfl_xor_sync(0xffffffffu, ss, off);
    const float rn = rsqrtf(ss * (1.0f / 64.0f) + 1e-6f);

    if (is_q) {
        const float QSC = 0.125f * 1.4426950408889634f;
        float q1 = o1 * rn * QSC, q2 = o2 * rn * QSC;
        float h1 = h16rt(q1), h2 = h16rt(q2);
        g_qh[doff + lane]      = __float2half_rn(h1);
        g_qh[doff + lane + 32] = __float2half_rn(h2);
        g_ql[doff + lane]      = __float2half_rn(q1 - h1);
        g_ql[doff + lane + 32] = __float2half_rn(q2 - h2);
    } else {
        float k1 = o1 * rn, k2 = o2 * rn;
        k_out[doff + lane]      = k1;
        k_out[doff + lane + 32] = k2;
        float h1 = h16rt(k1), h2 = h16rt(k2);
        g_kh[doff + lane]      = __float2half_rn(h1);
        g_kh[doff + lane + 32] = __float2half_rn(h2);
        g_kl[doff + lane]      = __float2half_rn(k1 - h1);
        g_kl[doff + lane + 32] = __float2half_rn(k2 - h2);
    }
}

// ===========================================================================
// fp16 flash attention. QK: Q-split x K-split (3 MMA); PV: P-single x V-split
// (2 MMA). cp.async K/V double buffer.
// ===========================================================================
#define APLANE  16384
#define KVSTAGE (4 * APLANE)
#define ASMEM   (2 * APLANE + 2 * KVSTAGE)

__device__ __forceinline__ uint32_t aswz(int row, int seg) {
    return (uint32_t)(row * 128 + ((seg ^ (row & 7)) << 4));
}

__global__ __launch_bounds__(256, 1)
void attn_mma(void)
{
    extern __shared__ __align__(1024) unsigned char sm8[];
    const uint32_t base = smem_u32(sm8);
    const uint32_t Qh = base, Ql = base + APLANE;
    const uint32_t kvbase = base + 2 * APLANE;

    const int tid  = threadIdx.x;
    const int lane = tid & 31;
    const int wid  = tid >> 5;
    const int qt   = 7 - blockIdx.x;
    const int bh   = blockIdx.y;
    const int b    = bh / H_NUM;
    const int h    = bh - b * H_NUM;
    const int q0   = qt * 128;
    const int wr0  = wid * 16;

    const __half* qh_g = g_qh + (size_t)bh * T_DIM * HD;
    const __half* ql_g = g_ql + (size_t)bh * T_DIM * HD;
    const __half* kh_g = g_kh + (size_t)bh * T_DIM * HD;
    const __half* kl_g = g_kl + (size_t)bh * T_DIM * HD;
    const __half* vh_g = g_vh + (size_t)bh * T_DIM * HD;
    const __half* vl_g = g_vl + (size_t)bh * T_DIM * HD;

    auto copy_kv = [&](int kt, uint32_t st) {
        const int k0 = kt * 128;
#pragma unroll
        for (int i = 0; i < 4; i++) {
            int idx = tid + i * 256;
            int r = idx >> 3, sg = idx & 7;
            uint32_t so = aswz(r, sg);
            size_t go = (size_t)(k0 + r) * HD + sg * 8;
            cpa16(st + so,              kh_g + go);
            cpa16(st + APLANE + so,     kl_g + go);
            cpa16(st + 2 * APLANE + so, vh_g + go);
            cpa16(st + 3 * APLANE + so, vl_g + go);
        }
    };

#pragma unroll
    for (int i = 0; i < 4; i++) {
        int idx = tid + i * 256;
        int r = idx >> 3, sg = idx & 7;
        uint32_t so = aswz(r, sg);
        size_t go = (size_t)(q0 + r) * HD + sg * 8;
        cpa16(Qh + so, qh_g + go);
        cpa16(Ql + so, ql_g + go);
    }
    copy_kv(0, kvbase);
    CP_COMMIT();

    float o[8][4];
#pragma unroll
    for (int i = 0; i < 8; i++)
#pragma unroll
        for (int j = 0; j < 4; j++) o[i][j] = 0.0f;
    float m_a = -INFINITY, m_b = -INFINITY, l_a = 0.0f, l_b = 0.0f;

    for (int kt = 0; kt <= qt; kt++) {
        const uint32_t st = kvbase + (uint32_t)(kt & 1) * KVSTAGE;
        if (kt < qt) {
            copy_kv(kt + 1, kvbase + (uint32_t)((kt + 1) & 1) * KVSTAGE);
            CP_COMMIT();
            CP_WAIT(1);
        } else {
            CP_WAIT(0);
        }
        __syncthreads();
        const uint32_t sKh = st, sKl = st + APLANE;
        const uint32_t sVh = st + 2 * APLANE, sVl = st + 3 * APLANE;

        // ---- S = Q @ K^T (Q-split x K-split, 3-term) ----
        float s[16][4];
#pragma unroll
        for (int i = 0; i < 16; i++)
#pragma unroll
            for (int j = 0; j < 4; j++) s[i][j] = 0.0f;

#pragma unroll
        for (int ks = 0; ks < 4; ks++) {
            int arow = wr0 + (lane & 15);
            int aseg = ks * 2 + (lane >> 4);
            uint32_t aoff = aswz(arow, aseg);
            uint32_t ah[4], al[4];
            ldmx4(ah[0], ah[1], ah[2], ah[3], Qh + aoff);
            ldmx4(al[0], al[1], al[2], al[3], Ql + aoff);
#pragma unroll
            for (int np = 0; np < 8; np++) {
                int brow = np * 16 + (lane & 15);
                uint32_t boff = aswz(brow, aseg);
                uint32_t r0, r1, r2, r3;
                uint32_t bhf[2][2], blf[2][2];
                ldmx4(r0, r1, r2, r3, sKh + boff);
                bhf[0][0] = r0; bhf[0][1] = r2; bhf[1][0] = r1; bhf[1][1] = r3;
                ldmx4(r0, r1, r2, r3, sKl + boff);
                blf[0][0] = r0; blf[0][1] = r2; blf[1][0] = r1; blf[1][1] = r3;
#pragma unroll
                for (int g = 0; g < 2; g++) {
                    mma_f16(s[np * 2 + g], ah, bhf[g]);
                    mma_f16(s[np * 2 + g], ah, blf[g]);
                    mma_f16(s[np * 2 + g], al, bhf[g]);
                }
            }
        }

        // ---- causal mask on diagonal tile ----
        if (kt == qt) {
            const int ra = (lane >> 2), cb = ((lane & 3) << 1);
#pragma unroll
            for (int nt = 0; nt < 16; nt++) {
#pragma unroll
                for (int j = 0; j < 4; j++) {
                    int col = nt * 8 + cb + (j & 1);
                    int row = wr0 + ra + ((j >> 1) << 3);
                    if (col > row) s[nt][j] = -INFINITY;
                }
            }
        }

        // ---- online softmax ----
        float mx_a = -INFINITY, mx_b = -INFINITY;
#pragma unroll
        for (int nt = 0; nt < 16; nt++) {
            mx_a = fmaxf(mx_a, fmaxf(s[nt][0], s[nt][1]));
            mx_b = fmaxf(mx_b, fmaxf(s[nt][2], s[nt][3]));
        }
        mx_a = fmaxf(mx_a, __shfl_xor_sync(0xffffffffu, mx_a, 1));
        mx_a = fmaxf(mx_a, __shfl_xor_sync(0xffffffffu, mx_a, 2));
        mx_b = fmaxf(mx_b, __shfl_xor_sync(0xffffffffu, mx_b, 1));
        mx_b = fmaxf(mx_b, __shfl_xor_sync(0xffffffffu, mx_b, 2));

        const float mn_a = fmaxf(m_a, mx_a);
        const float mn_b = fmaxf(m_b, mx_b);
        const float ca = ex2f(m_a - mn_a);
        const float cbf = ex2f(m_b - mn_b);
        m_a = mn_a; m_b = mn_b;

        float sa = 0.0f, sb = 0.0f;
#pragma unroll
        for (int nt = 0; nt < 16; nt++) {
            s[nt][0] = ex2f(s[nt][0] - mn_a);
            s[nt][1] = ex2f(s[nt][1] - mn_a);
            s[nt][2] = ex2f(s[nt][2] - mn_b);
            s[nt][3] = ex2f(s[nt][3] - mn_b);
            sa += s[nt][0] + s[nt][1];
            sb += s[nt][2] + s[nt][3];
        }
        sa += __shfl_xor_sync(0xffffffffu, sa, 1);
        sa += __shfl_xor_sync(0xffffffffu, sa, 2);
        sb += __shfl_xor_sync(0xffffffffu, sb, 1);
        sb += __shfl_xor_sync(0xffffffffu, sb, 2);
        l_a = l_a * ca + sa;
        l_b = l_b * cbf + sb;
#pragma unroll
        for (int i = 0; i < 8; i++) {
            o[i][0] *= ca; o[i][1] *= ca; o[i][2] *= cbf; o[i][3] *= cbf;
        }

        // ---- O += P @ V (P single fp16 x V-split) ----
#pragma unroll
        for (int kc = 0; kc < 8; kc++) {
            uint32_t pa[4];
            pa[0] = pack_h2(s[2*kc][0],   s[2*kc][1]);
            pa[1] = pack_h2(s[2*kc][2],   s[2*kc][3]);
            pa[2] = pack_h2(s[2*kc+1][0], s[2*kc+1][1]);
            pa[3] = pack_h2(s[2*kc+1][2], s[2*kc+1][3]);

            int vrow = kc * 16 + (lane & 15);
#pragma unroll
            for (int s2 = 0; s2 < 4; s2++) {
                int vseg = s2 * 2 + (lane >> 4);
                uint32_t voff = aswz(vrow, vseg);
                uint32_t r0, r1, r2, r3;
                uint32_t vhf[2][2], vlf[2][2];
                ldmx4t(r0, r1, r2, r3, sVh + voff);
                vhf[0][0] = r0; vhf[0][1] = r1; vhf[1][0] = r2; vhf[1][1] = r3;
                ldmx4t(r0, r1, r2, r3, sVl + voff);
                vlf[0][0] = r0; vlf[0][1] = r1; vlf[1][0] = r2; vlf[1][1] = r3;
#pragma unroll
                for (int g = 0; g < 2; g++) {
                    mma_f16(o[s2 * 2 + g], pa, vhf[g]);
                    mma_f16(o[s2 * 2 + g], pa, vlf[g]);
                }
            }
        }
        __syncthreads();
    }

    // ---- normalize + write y hi/lo fp16 planes (B,T,C) ----
    const float ia = 1.0f / l_a, ib = 1.0f / l_b;
    const int ra = lane >> 2, cb = (lane & 3) << 1;
    const size_t ybase = ((size_t)(b * T_DIM + q0 + wr0 + ra)) * C_DIM + h * HD;
#pragma unroll
    for (int nt = 0; nt < 8; nt++) {
        int col = nt * 8 + cb;
        float y0 = o[nt][0] * ia, y1 = o[nt][1] * ia;
        float h0 = h16rt(y0), h1 = h16rt(y1);
        *(uint32_t*)(g_yh + ybase + col) = pack_h2(h0, h1);
        *(uint32_t*)(g_yl + ybase + col) = pack_h2(y0 - h0, y1 - h1);
        float y2 = o[nt][2] * ib, y3 = o[nt][3] * ib;
        float h2 = h16rt(y2), h3 = h16rt(y3);
        *(uint32_t*)(g_yh + ybase + 8 * C_DIM + col) = pack_h2(h2, h3);
        *(uint32_t*)(g_yl + ybase + 8 * C_DIM + col) = pack_h2(y2 - h2, y3 - h3);
    }
}

// ---------------------------------------------------------------------------
extern "C" void kernel_launch(void* const* d_in, const int* in_sizes, int n_in,
                              void* d_out, int out_size)
{
    const float* x  = (const float*)d_in[0];
    const float* Wq = (const float*)d_in[1];
    const float* Wk = (const float*)d_in[2];
    const float* Wv = (const float*)d_in[3];
    const float* Wo = (const float*)d_in[4];

    float* out   = (float*)d_out;
    float* y_out = out;
    float* k_out = out + S_ELE;
    float* v_out = out + 2 * (size_t)S_ELE;

    cudaFuncSetAttribute(split_gemm2, cudaFuncAttributeMaxDynamicSharedMemorySize,
                         GSMEM);
    cudaFuncSetAttribute(attn_mma, cudaFuncAttributeMaxDynamicSharedMemorySize,
                         ASMEM);

    prep_convert<<<(PREP_F4 + 255) / 256, 256>>>(x, Wq, Wk, Wv, Wo);

    split_gemm2<<<dim3(C_DIM / 128, M_TOT / 128, 3), 256, GSMEM>>>(v_out, 1);

    rope_norm_kernel<<<dim3((B_DIM * H_NUM * T_DIM) / 8, 3), 256>>>(k_out, v_out);

    attn_mma<<<dim3(T_DIM / 128, B_DIM * H_NUM), 256, ASMEM>>>();

    split_gemm2<<<dim3(C_DIM / 128, M_TOT / 128, 1), 256, GSMEM>>>(y_out, 0);
}

// round 10
// speedup vs baseline: 3.8965x; 1.3483x over previous
#include <cuda_runtime.h>
#include <cuda_fp16.h>
#include <math.h>
#include <stdint.h>

#define C_DIM 768
#define T_DIM 1024
#define B_DIM 8
#define H_NUM 12
#define HD    64
#define M_TOT 8192
#define S_ELE 6291456   /* 8*1024*768 */
#define X_ELE 6291456
#define W_ELE 589824    /* 768*768 */

// fp32 scratch (raw q/k for rope input)
static __device__ float g_q[S_ELE];
static __device__ float g_k[S_ELE];
// fp16 single planes
static __device__ __align__(16) __half g_x[X_ELE];
static __device__ __align__(16) __half g_w[4 * W_ELE];
static __device__ __align__(16) __half g_qp[S_ELE];
static __device__ __align__(16) __half g_kp[S_ELE];
static __device__ __align__(16) __half g_vp[S_ELE];
static __device__ __align__(16) __half g_yp[S_ELE];

__device__ __forceinline__ uint32_t smem_u32(const void* p) {
    uint32_t a;
    asm("{ .reg .u64 t; cvta.to.shared.u64 t, %1; cvt.u32.u64 %0, t; }"
        : "=r"(a) : "l"(p));
    return a;
}
__device__ __forceinline__ float ex2f(float x) {
    float r;
    asm("ex2.approx.ftz.f32 %0, %1;" : "=f"(r) : "f"(x));
    return r;
}
__device__ __forceinline__ uint32_t pack_h2(float lo, float hi) {
    uint32_t u;
    asm("cvt.rn.f16x2.f32 %0, %1, %2;" : "=r"(u) : "f"(hi), "f"(lo));
    return u;
}
__device__ __forceinline__ void cpa16(uint32_t dst, const void* src) {
    asm volatile("cp.async.cg.shared.global [%0], [%1], 16;"
                 :: "r"(dst), "l"(src) : "memory");
}
#define CP_COMMIT()  asm volatile("cp.async.commit_group;" ::: "memory")
#define CP_WAIT(n)   asm volatile("cp.async.wait_group %0;" :: "n"(n) : "memory")
__device__ __forceinline__ void ldmx4(uint32_t& r0, uint32_t& r1,
                                      uint32_t& r2, uint32_t& r3, uint32_t addr) {
    asm volatile("ldmatrix.sync.aligned.m8n8.x4.shared.b16 {%0,%1,%2,%3}, [%4];"
                 : "=r"(r0), "=r"(r1), "=r"(r2), "=r"(r3) : "r"(addr));
}
__device__ __forceinline__ void ldmx4t(uint32_t& r0, uint32_t& r1,
                                       uint32_t& r2, uint32_t& r3, uint32_t addr) {
    asm volatile("ldmatrix.sync.aligned.m8n8.x4.trans.shared.b16 {%0,%1,%2,%3}, [%4];"
                 : "=r"(r0), "=r"(r1), "=r"(r2), "=r"(r3) : "r"(addr));
}
__device__ __forceinline__ void mma_f16(float* c, const uint32_t* a,
                                        const uint32_t* b) {
    asm volatile(
        "mma.sync.aligned.m16n8k16.row.col.f32.f16.f16.f32 "
        "{%0,%1,%2,%3},{%4,%5,%6,%7},{%8,%9},{%0,%1,%2,%3};"
        : "+f"(c[0]), "+f"(c[1]), "+f"(c[2]), "+f"(c[3])
        : "r"(a[0]), "r"(a[1]), "r"(a[2]), "r"(a[3]), "r"(b[0]), "r"(b[1]));
}

// ===========================================================================
// prep: x and weights -> single fp16 planes
// ===========================================================================
#define PREP_F4 ((X_ELE + 4 * W_ELE) / 4)
__global__ void prep_convert(const float* __restrict__ x,
                             const float* __restrict__ Wq,
                             const float* __restrict__ Wk,
                             const float* __restrict__ Wv,
                             const float* __restrict__ Wo)
{
    size_t i4 = (size_t)blockIdx.x * 256 + threadIdx.x;
    if (i4 >= PREP_F4) return;
    size_t e = i4 * 4;
    if (e < X_ELE) {
        float4 v = *(const float4*)(x + e);
        *(uint2*)(g_x + e) = make_uint2(pack_h2(v.x, v.y), pack_h2(v.z, v.w));
    } else {
        size_t r = e - X_ELE;
        int w = (int)(r / W_ELE);
        size_t off = r - (size_t)w * W_ELE;
        const float* src = (w == 0) ? Wq : (w == 1) ? Wk : (w == 2) ? Wv : Wo;
        float4 v = *(const float4*)(src + off);
        *(uint2*)(g_w + (size_t)w * W_ELE + off) =
            make_uint2(pack_h2(v.x, v.y), pack_h2(v.z, v.w));
    }
}

// ===========================================================================
// fp16 single GEMM: 1 MMA per k16. 128x128 CTA tile, 8 warps, K chunks 32,
// 3-stage cp.async pipeline, 2 CTAs/SM.
// modes: 0 -> g_q, 1 -> g_k, 2 -> dst (v BHTD), 3 -> dst (y BTC)
// ===========================================================================
#define NCHUNK 24
#define PLANE  8192
#define STAGE  (2 * PLANE)
#define GSMEM  (3 * STAGE)

__device__ __forceinline__ uint32_t swz16(int row, int seg) {
    return (uint32_t)(row * 64 + ((seg ^ ((row >> 1) & 3)) << 4));
}

__global__ __launch_bounds__(256, 2)
void split_gemm2(float* __restrict__ dst, int is_qkv)
{
    extern __shared__ __align__(1024) unsigned char sm8[];
    const uint32_t base = smem_u32(sm8);
    const int tid  = threadIdx.x;
    const int lane = tid & 31;
    const int wid  = tid >> 5;
    const int wm   = wid >> 2;
    const int wn   = wid & 3;
    const int n0 = blockIdx.x * 128;
    const int m0 = blockIdx.y * 128;

    int mode;
    const __half *As, *Bs;
    if (is_qkv) {
        mode = blockIdx.z;
        As = g_x;
        Bs = g_w + (size_t)mode * W_ELE;
    } else {
        mode = 3;
        As = g_yp;
        Bs = g_w + 3 * (size_t)W_ELE;
    }
    As += (size_t)m0 * C_DIM;
    Bs += (size_t)n0 * C_DIM;

    float acc[16][4];
#pragma unroll
    for (int i = 0; i < 16; i++)
#pragma unroll
        for (int j = 0; j < 4; j++) acc[i][j] = 0.0f;

    auto copy_chunk = [&](int c, uint32_t st) {
        const int k0 = c * 32;
#pragma unroll
        for (int i = 0; i < 2; i++) {
            int idx = tid + i * 256;
            int r = idx >> 2, sg = idx & 3;
            uint32_t so = swz16(r, sg);
            size_t go = (size_t)r * C_DIM + k0 + sg * 8;
            cpa16(st + so,         As + go);
            cpa16(st + PLANE + so, Bs + go);
        }
    };

    copy_chunk(0, base);
    CP_COMMIT();
    copy_chunk(1, base + STAGE);
    CP_COMMIT();

    for (int c = 0; c < NCHUNK; c++) {
        const uint32_t st = base + (uint32_t)(c % 3) * STAGE;
        if (c + 2 < NCHUNK) {
            copy_chunk(c + 2, base + (uint32_t)((c + 2) % 3) * STAGE);
            CP_COMMIT();
            CP_WAIT(2);
        } else if (c + 1 < NCHUNK) {
            CP_WAIT(1);
        } else {
            CP_WAIT(0);
        }
        __syncthreads();

#pragma unroll
        for (int ks = 0; ks < 2; ks++) {
            uint32_t bf[4][2];
#pragma unroll
            for (int g = 0; g < 2; g++) {
                int row = wn * 32 + g * 16 + (lane & 15);
                int sg = 2 * ks + (lane >> 4);
                uint32_t off = swz16(row, sg);
                uint32_t r0, r1, r2, r3;
                ldmx4(r0, r1, r2, r3, st + PLANE + off);
                bf[2 * g][0] = r0; bf[2 * g + 1][0] = r1;
                bf[2 * g][1] = r2; bf[2 * g + 1][1] = r3;
            }
#pragma unroll
            for (int mt = 0; mt < 4; mt++) {
                int row = wm * 64 + mt * 16 + (lane & 15);
                int sg = 2 * ks + (lane >> 4);
                uint32_t off = swz16(row, sg);
                uint32_t af[4];
                ldmx4(af[0], af[1], af[2], af[3], st + off);
#pragma unroll
                for (int nt = 0; nt < 4; nt++)
                    mma_f16(acc[mt * 4 + nt], af, bf[nt]);
            }
        }
        __syncthreads();
    }

#pragma unroll
    for (int mt = 0; mt < 4; mt++) {
#pragma unroll
        for (int nt = 0; nt < 4; nt++) {
            const float* cc = acc[mt * 4 + nt];
            int r  = m0 + wm * 64 + mt * 16 + (lane >> 2);
            int cl = n0 + wn * 32 + nt * 8 + ((lane & 3) << 1);
#pragma unroll
            for (int h2 = 0; h2 < 2; h2++) {
                int rr = r + h2 * 8;
                float2 v = make_float2(cc[h2 * 2], cc[h2 * 2 + 1]);
                if (mode == 0) {
                    *(float2*)(g_q + (size_t)rr * C_DIM + cl) = v;
                } else if (mode == 1) {
                    *(float2*)(g_k + (size_t)rr * C_DIM + cl) = v;
                } else if (mode == 3) {
                    *(float2*)(dst + (size_t)rr * C_DIM + cl) = v;
                } else {
                    const int bb = rr >> 10, t = rr & (T_DIM - 1);
                    const int h = cl >> 6, hd0 = cl & (HD - 1);
                    *(float2*)(dst + (((size_t)(bb * H_NUM + h)) * T_DIM + t) * HD + hd0) = v;
                }
            }
        }
    }
}

// ===========================================================================
// RoPE + RMSNorm + fp16 plane emission. y=0: q (scale folded), y=1: k,
// y=2: v (from v_out).
// ===========================================================================
__global__ void rope_norm_kernel(float* __restrict__ k_out,
                                 const float* __restrict__ v_out)
{
    const int lane = threadIdx.x & 31;
    const int vec  = blockIdx.x * 8 + (threadIdx.x >> 5);
    const int t  = vec & (T_DIM - 1);
    const int bh = vec >> 10;
    const int b  = bh / H_NUM;
    const int h  = bh - b * H_NUM;
    const int iy = blockIdx.y;
    const size_t doff = ((size_t)bh * T_DIM + t) * HD;

    if (iy == 2) {
        g_vp[doff + lane]      = __float2half_rn(v_out[doff + lane]);
        g_vp[doff + lane + 32] = __float2half_rn(v_out[doff + lane + 32]);
        return;
    }

    const bool is_q = (iy == 0);
    const float* src = (is_q ? g_q : g_k) +
                       ((size_t)(b * T_DIM + t)) * C_DIM + h * HD;
    const float x1 = src[lane];
    const float x2 = src[lane + 32];

    const float inv = (float)exp((double)lane * -0.28782313662425575);
    const float f = (float)t * inv;
    float s, c;
    sincosf(f, &s, &c);
    const float o1 = x1 * c - x2 * s;
    const float o2 = x1 * s + x2 * c;

    float ss = o1 * o1 + o2 * o2;
#pragma unroll
    for (int off = 16; off; off >>= 1)
        ss += __shfl_xor_sync(0xffffffffu, ss, off);
    const float rn = rsqrtf(ss * (1.0f / 64.0f) + 1e-6f);

    if (is_q) {
        const float QSC = 0.125f * 1.4426950408889634f;
        g_qp[doff + lane]      = __float2half_rn(o1 * rn * QSC);
        g_qp[doff + lane + 32] = __float2half_rn(o2 * rn * QSC);
    } else {
        float k1 = o1 * rn, k2 = o2 * rn;
        k_out[doff + lane]      = k1;
        k_out[doff + lane + 32] = k2;
        g_kp[doff + lane]      = __float2half_rn(k1);
        g_kp[doff + lane + 32] = __float2half_rn(k2);
    }
}

// ===========================================================================
// fp16 single flash attention. QK 1 MMA, PV 1 MMA. cp.async K/V double buffer.
// smem: Q 16KB + 2 KV stages x 32KB = 80KB.
// ===========================================================================
#define APLANE  16384
#define KVSTAGE (2 * APLANE)
#define ASMEM   (APLANE + 2 * KVSTAGE)

__device__ __forceinline__ uint32_t aswz(int row, int seg) {
    return (uint32_t)(row * 128 + ((seg ^ (row & 7)) << 4));
}

__global__ __launch_bounds__(256, 1)
void attn_mma(void)
{
    extern __shared__ __align__(1024) unsigned char sm8[];
    const uint32_t base = smem_u32(sm8);
    const uint32_t Qs = base;
    const uint32_t kvbase = base + APLANE;

    const int tid  = threadIdx.x;
    const int lane = tid & 31;
    const int wid  = tid >> 5;
    const int qt   = 7 - blockIdx.x;
    const int bh   = blockIdx.y;
    const int b    = bh / H_NUM;
    const int h    = bh - b * H_NUM;
    const int q0   = qt * 128;
    const int wr0  = wid * 16;

    const __half* q_g = g_qp + (size_t)bh * T_DIM * HD;
    const __half* k_g = g_kp + (size_t)bh * T_DIM * HD;
    const __half* v_g = g_vp + (size_t)bh * T_DIM * HD;

    auto copy_kv = [&](int kt, uint32_t st) {
        const int k0 = kt * 128;
#pragma unroll
        for (int i = 0; i < 4; i++) {
            int idx = tid + i * 256;
            int r = idx >> 3, sg = idx & 7;
            uint32_t so = aswz(r, sg);
            size_t go = (size_t)(k0 + r) * HD + sg * 8;
            cpa16(st + so,          k_g + go);
            cpa16(st + APLANE + so, v_g + go);
        }
    };

#pragma unroll
    for (int i = 0; i < 4; i++) {
        int idx = tid + i * 256;
        int r = idx >> 3, sg = idx & 7;
        uint32_t so = aswz(r, sg);
        cpa16(Qs + so, q_g + (size_t)(q0 + r) * HD + sg * 8);
    }
    copy_kv(0, kvbase);
    CP_COMMIT();

    float o[8][4];
#pragma unroll
    for (int i = 0; i < 8; i++)
#pragma unroll
        for (int j = 0; j < 4; j++) o[i][j] = 0.0f;
    float m_a = -INFINITY, m_b = -INFINITY, l_a = 0.0f, l_b = 0.0f;

    for (int kt = 0; kt <= qt; kt++) {
        const uint32_t st = kvbase + (uint32_t)(kt & 1) * KVSTAGE;
        if (kt < qt) {
            copy_kv(kt + 1, kvbase + (uint32_t)((kt + 1) & 1) * KVSTAGE);
            CP_COMMIT();
            CP_WAIT(1);
        } else {
            CP_WAIT(0);
        }
        __syncthreads();
        const uint32_t sK = st, sV = st + APLANE;

        // ---- S = Q @ K^T ----
        float s[16][4];
#pragma unroll
        for (int i = 0; i < 16; i++)
#pragma unroll
            for (int j = 0; j < 4; j++) s[i][j] = 0.0f;

#pragma unroll
        for (int ks = 0; ks < 4; ks++) {
            int arow = wr0 + (lane & 15);
            int aseg = ks * 2 + (lane >> 4);
            uint32_t aoff = aswz(arow, aseg);
            uint32_t af[4];
            ldmx4(af[0], af[1], af[2], af[3], Qs + aoff);
#pragma unroll
            for (int np = 0; np < 8; np++) {
                int brow = np * 16 + (lane & 15);
                uint32_t boff = aswz(brow, aseg);
                uint32_t r0, r1, r2, r3;
                uint32_t bf[2][2];
                ldmx4(r0, r1, r2, r3, sK + boff);
                bf[0][0] = r0; bf[0][1] = r2; bf[1][0] = r1; bf[1][1] = r3;
#pragma unroll
                for (int g = 0; g < 2; g++)
                    mma_f16(s[np * 2 + g], af, bf[g]);
            }
        }

        // ---- causal mask on diagonal tile ----
        if (kt == qt) {
            const int ra = (lane >> 2), cb = ((lane & 3) << 1);
#pragma unroll
            for (int nt = 0; nt < 16; nt++) {
#pragma unroll
                for (int j = 0; j < 4; j++) {
                    int col = nt * 8 + cb + (j & 1);
                    int row = wr0 + ra + ((j >> 1) << 3);
                    if (col > row) s[nt][j] = -INFINITY;
                }
            }
        }

        // ---- online softmax ----
        float mx_a = -INFINITY, mx_b = -INFINITY;
#pragma unroll
        for (int nt = 0; nt < 16; nt++) {
            mx_a = fmaxf(mx_a, fmaxf(s[nt][0], s[nt][1]));
            mx_b = fmaxf(mx_b, fmaxf(s[nt][2], s[nt][3]));
        }
        mx_a = fmaxf(mx_a, __shfl_xor_sync(0xffffffffu, mx_a, 1));
        mx_a = fmaxf(mx_a, __shfl_xor_sync(0xffffffffu, mx_a, 2));
        mx_b = fmaxf(mx_b, __shfl_xor_sync(0xffffffffu, mx_b, 1));
        mx_b = fmaxf(mx_b, __shfl_xor_sync(0xffffffffu, mx_b, 2));

        const float mn_a = fmaxf(m_a, mx_a);
        const float mn_b = fmaxf(m_b, mx_b);
        const float ca = ex2f(m_a - mn_a);
        const float cbf = ex2f(m_b - mn_b);
        m_a = mn_a; m_b = mn_b;

        float sa = 0.0f, sb = 0.0f;
#pragma unroll
        for (int nt = 0; nt < 16; nt++) {
            s[nt][0] = ex2f(s[nt][0] - mn_a);
            s[nt][1] = ex2f(s[nt][1] - mn_a);
            s[nt][2] = ex2f(s[nt][2] - mn_b);
            s[nt][3] = ex2f(s[nt][3] - mn_b);
            sa += s[nt][0] + s[nt][1];
            sb += s[nt][2] + s[nt][3];
        }
        sa += __shfl_xor_sync(0xffffffffu, sa, 1);
        sa += __shfl_xor_sync(0xffffffffu, sa, 2);
        sb += __shfl_xor_sync(0xffffffffu, sb, 1);
        sb += __shfl_xor_sync(0xffffffffu, sb, 2);
        l_a = l_a * ca + sa;
        l_b = l_b * cbf + sb;
#pragma unroll
        for (int i = 0; i < 8; i++) {
            o[i][0] *= ca; o[i][1] *= ca; o[i][2] *= cbf; o[i][3] *= cbf;
        }

        // ---- O += P @ V ----
#pragma unroll
        for (int kc = 0; kc < 8; kc++) {
            uint32_t pa[4];
            pa[0] = pack_h2(s[2*kc][0],   s[2*kc][1]);
            pa[1] = pack_h2(s[2*kc][2],   s[2*kc][3]);
            pa[2] = pack_h2(s[2*kc+1][0], s[2*kc+1][1]);
            pa[3] = pack_h2(s[2*kc+1][2], s[2*kc+1][3]);

            int vrow = kc * 16 + (lane & 15);
#pragma unroll
            for (int s2 = 0; s2 < 4; s2++) {
                int vseg = s2 * 2 + (lane >> 4);
                uint32_t voff = aswz(vrow, vseg);
                uint32_t r0, r1, r2, r3;
                uint32_t vf[2][2];
                ldmx4t(r0, r1, r2, r3, sV + voff);
                vf[0][0] = r0; vf[0][1] = r1; vf[1][0] = r2; vf[1][1] = r3;
#pragma unroll
                for (int g = 0; g < 2; g++)
                    mma_f16(o[s2 * 2 + g], pa, vf[g]);
            }
        }
        __syncthreads();
    }

    // ---- normalize + write y fp16 plane (B,T,C) ----
    const float ia = 1.0f / l_a, ib = 1.0f / l_b;
    const int ra = lane >> 2, cb = (lane & 3) << 1;
    const size_t ybase = ((size_t)(b * T_DIM + q0 + wr0 + ra)) * C_DIM + h * HD;
#pragma unroll
    for (int nt = 0; nt < 8; nt++) {
        int col = nt * 8 + cb;
        *(uint32_t*)(g_yp + ybase + col) = pack_h2(o[nt][0] * ia, o[nt][1] * ia);
        *(uint32_t*)(g_yp + ybase + 8 * C_DIM + col) =
            pack_h2(o[nt][2] * ib, o[nt][3] * ib);
    }
}

// ---------------------------------------------------------------------------
extern "C" void kernel_launch(void* const* d_in, const int* in_sizes, int n_in,
                              void* d_out, int out_size)
{
    const float* x  = (const float*)d_in[0];
    const float* Wq = (const float*)d_in[1];
    const float* Wk = (const float*)d_in[2];
    const float* Wv = (const float*)d_in[3];
    const float* Wo = (const float*)d_in[4];

    float* out   = (float*)d_out;
    float* y_out = out;
    float* k_out = out + S_ELE;
    float* v_out = out + 2 * (size_t)S_ELE;

    cudaFuncSetAttribute(split_gemm2, cudaFuncAttributeMaxDynamicSharedMemorySize,
                         GSMEM);
    cudaFuncSetAttribute(attn_mma, cudaFuncAttributeMaxDynamicSharedMemorySize,
                         ASMEM);

    prep_convert<<<(PREP_F4 + 255) / 256, 256>>>(x, Wq, Wk, Wv, Wo);

    split_gemm2<<<dim3(C_DIM / 128, M_TOT / 128, 3), 256, GSMEM>>>(v_out, 1);

    rope_norm_kernel<<<dim3((B_DIM * H_NUM * T_DIM) / 8, 3), 256>>>(k_out, v_out);

    attn_mma<<<dim3(T_DIM / 128, B_DIM * H_NUM), 256, ASMEM>>>();

    split_gemm2<<<dim3(C_DIM / 128, M_TOT / 128, 1), 256, GSMEM>>>(y_out, 0);
}

// round 11
// speedup vs baseline: 4.0911x; 1.0499x over previous
#include <cuda_runtime.h>
#include <cuda_fp16.h>
#include <math.h>
#include <stdint.h>

#define C_DIM 768
#define T_DIM 1024
#define B_DIM 8
#define H_NUM 12
#define HD    64
#define M_TOT 8192
#define S_ELE 6291456   /* 8*1024*768 */
#define X_ELE 6291456
#define W_ELE 589824    /* 768*768 */

// fp16 planes
static __device__ __align__(16) __half g_x[X_ELE];
static __device__ __align__(16) __half g_w[4 * W_ELE];
static __device__ __align__(16) __half g_qg[S_ELE];   // raw q (BTC, fp16)
static __device__ __align__(16) __half g_kg[S_ELE];   // raw k (BTC, fp16)
static __device__ __align__(16) __half g_qp[S_ELE];   // rope+norm q (BHTD)
static __device__ __align__(16) __half g_kp[S_ELE];   // rope+norm k (BHTD)
static __device__ __align__(16) __half g_vp[S_ELE];   // v (BHTD)
static __device__ __align__(16) __half g_yp[S_ELE];   // attn out (BTC)

__device__ __forceinline__ uint32_t smem_u32(const void* p) {
    uint32_t a;
    asm("{ .reg .u64 t; cvta.to.shared.u64 t, %1; cvt.u32.u64 %0, t; }"
        : "=r"(a) : "l"(p));
    return a;
}
__device__ __forceinline__ float ex2f(float x) {
    float r;
    asm("ex2.approx.ftz.f32 %0, %1;" : "=f"(r) : "f"(x));
    return r;
}
__device__ __forceinline__ uint32_t pack_h2(float lo, float hi) {
    uint32_t u;
    asm("cvt.rn.f16x2.f32 %0, %1, %2;" : "=r"(u) : "f"(hi), "f"(lo));
    return u;
}
__device__ __forceinline__ void cpa16(uint32_t dst, const void* src) {
    asm volatile("cp.async.cg.shared.global [%0], [%1], 16;"
                 :: "r"(dst), "l"(src) : "memory");
}
#define CP_COMMIT()  asm volatile("cp.async.commit_group;" ::: "memory")
#define CP_WAIT(n)   asm volatile("cp.async.wait_group %0;" :: "n"(n) : "memory")
__device__ __forceinline__ void ldmx4(uint32_t& r0, uint32_t& r1,
                                      uint32_t& r2, uint32_t& r3, uint32_t addr) {
    asm volatile("ldmatrix.sync.aligned.m8n8.x4.shared.b16 {%0,%1,%2,%3}, [%4];"
                 : "=r"(r0), "=r"(r1), "=r"(r2), "=r"(r3) : "r"(addr));
}
__device__ __forceinline__ void ldmx4t(uint32_t& r0, uint32_t& r1,
                                       uint32_t& r2, uint32_t& r3, uint32_t addr) {
    asm volatile("ldmatrix.sync.aligned.m8n8.x4.trans.shared.b16 {%0,%1,%2,%3}, [%4];"
                 : "=r"(r0), "=r"(r1), "=r"(r2), "=r"(r3) : "r"(addr));
}
__device__ __forceinline__ void mma_f16(float* c, const uint32_t* a,
                                        const uint32_t* b) {
    asm volatile(
        "mma.sync.aligned.m16n8k16.row.col.f32.f16.f16.f32 "
        "{%0,%1,%2,%3},{%4,%5,%6,%7},{%8,%9},{%0,%1,%2,%3};"
        : "+f"(c[0]), "+f"(c[1]), "+f"(c[2]), "+f"(c[3])
        : "r"(a[0]), "r"(a[1]), "r"(a[2]), "r"(a[3]), "r"(b[0]), "r"(b[1]));
}

// 128B-row swizzle (64 fp16 per row): seg 0..7 (16B units)
__device__ __forceinline__ uint32_t aswz(int row, int seg) {
    return (uint32_t)(row * 128 + ((seg ^ (row & 7)) << 4));
}

// ===========================================================================
// prep: x and weights -> single fp16 planes
// ===========================================================================
#define PREP_F4 ((X_ELE + 4 * W_ELE) / 4)
__global__ void prep_convert(const float* __restrict__ x,
                             const float* __restrict__ Wq,
                             const float* __restrict__ Wk,
                             const float* __restrict__ Wv,
                             const float* __restrict__ Wo)
{
    size_t i4 = (size_t)blockIdx.x * 256 + threadIdx.x;
    if (i4 >= PREP_F4) return;
    size_t e = i4 * 4;
    if (e < X_ELE) {
        float4 v = *(const float4*)(x + e);
        *(uint2*)(g_x + e) = make_uint2(pack_h2(v.x, v.y), pack_h2(v.z, v.w));
    } else {
        size_t r = e - X_ELE;
        int w = (int)(r / W_ELE);
        size_t off = r - (size_t)w * W_ELE;
        const float* src = (w == 0) ? Wq : (w == 1) ? Wk : (w == 2) ? Wv : Wo;
        float4 v = *(const float4*)(src + off);
        *(uint2*)(g_w + (size_t)w * W_ELE + off) =
            make_uint2(pack_h2(v.x, v.y), pack_h2(v.z, v.w));
    }
}

// ===========================================================================
// fp16 GEMM: 128x128 CTA tile, 8 warps, K chunks of 64, 3-stage cp.async,
// 2 CTAs/SM. modes: 0 -> g_qg (fp16), 1 -> g_kg (fp16),
// 2 -> v_out fp32 + g_vp fp16 (BHTD), 3 -> dst fp32 (BTC)
// ===========================================================================
#define NCHUNK 12            /* 768 / 64 */
#define GPLANE 16384         /* 128 rows x 128 B */
#define GSTAGE (2 * GPLANE)
#define GSMEM  (3 * GSTAGE)  /* 96 KB */

__global__ __launch_bounds__(256, 2)
void split_gemm2(float* __restrict__ dst, int is_qkv)
{
    extern __shared__ __align__(1024) unsigned char sm8[];
    const uint32_t base = smem_u32(sm8);
    const int tid  = threadIdx.x;
    const int lane = tid & 31;
    const int wid  = tid >> 5;
    const int wm   = wid >> 2;
    const int wn   = wid & 3;
    const int n0 = blockIdx.x * 128;
    const int m0 = blockIdx.y * 128;

    int mode;
    const __half *As, *Bs;
    if (is_qkv) {
        mode = blockIdx.z;
        As = g_x;
        Bs = g_w + (size_t)mode * W_ELE;
    } else {
        mode = 3;
        As = g_yp;
        Bs = g_w + 3 * (size_t)W_ELE;
    }
    As += (size_t)m0 * C_DIM;
    Bs += (size_t)n0 * C_DIM;

    float acc[16][4];
#pragma unroll
    for (int i = 0; i < 16; i++)
#pragma unroll
        for (int j = 0; j < 4; j++) acc[i][j] = 0.0f;

    auto copy_chunk = [&](int c, uint32_t st) {
        const int k0 = c * 64;
#pragma unroll
        for (int i = 0; i < 4; i++) {
            int idx = tid + i * 256;
            int r = idx >> 3, sg = idx & 7;
            uint32_t so = aswz(r, sg);
            size_t go = (size_t)r * C_DIM + k0 + sg * 8;
            cpa16(st + so,          As + go);
            cpa16(st + GPLANE + so, Bs + go);
        }
    };

    copy_chunk(0, base);
    CP_COMMIT();
    copy_chunk(1, base + GSTAGE);
    CP_COMMIT();

    for (int c = 0; c < NCHUNK; c++) {
        const uint32_t st = base + (uint32_t)(c % 3) * GSTAGE;
        if (c + 2 < NCHUNK) {
            copy_chunk(c + 2, base + (uint32_t)((c + 2) % 3) * GSTAGE);
            CP_COMMIT();
            CP_WAIT(2);
        } else if (c + 1 < NCHUNK) {
            CP_WAIT(1);
        } else {
            CP_WAIT(0);
        }
        __syncthreads();

#pragma unroll
        for (int ks = 0; ks < 4; ks++) {
            const int sg = 2 * ks + (lane >> 4);
            uint32_t bf[4][2];
#pragma unroll
            for (int g = 0; g < 2; g++) {
                int row = wn * 32 + g * 16 + (lane & 15);
                uint32_t off = aswz(row, sg);
                uint32_t r0, r1, r2, r3;
                ldmx4(r0, r1, r2, r3, st + GPLANE + off);
                bf[2 * g][0] = r0; bf[2 * g + 1][0] = r1;
                bf[2 * g][1] = r2; bf[2 * g + 1][1] = r3;
            }
#pragma unroll
            for (int mt = 0; mt < 4; mt++) {
                int row = wm * 64 + mt * 16 + (lane & 15);
                uint32_t off = aswz(row, sg);
                uint32_t af[4];
                ldmx4(af[0], af[1], af[2], af[3], st + off);
#pragma unroll
                for (int nt = 0; nt < 4; nt++)
                    mma_f16(acc[mt * 4 + nt], af, bf[nt]);
            }
        }
        __syncthreads();
    }

#pragma unroll
    for (int mt = 0; mt < 4; mt++) {
#pragma unroll
        for (int nt = 0; nt < 4; nt++) {
            const float* cc = acc[mt * 4 + nt];
            int r  = m0 + wm * 64 + mt * 16 + (lane >> 2);
            int cl = n0 + wn * 32 + nt * 8 + ((lane & 3) << 1);
#pragma unroll
            for (int h2 = 0; h2 < 2; h2++) {
                int rr = r + h2 * 8;
                float v0 = cc[h2 * 2], v1 = cc[h2 * 2 + 1];
                if (mode == 0) {
                    *(uint32_t*)(g_qg + (size_t)rr * C_DIM + cl) = pack_h2(v0, v1);
                } else if (mode == 1) {
                    *(uint32_t*)(g_kg + (size_t)rr * C_DIM + cl) = pack_h2(v0, v1);
                } else if (mode == 3) {
                    *(float2*)(dst + (size_t)rr * C_DIM + cl) = make_float2(v0, v1);
                } else {
                    const int bb = rr >> 10, t = rr & (T_DIM - 1);
                    const int h = cl >> 6, hd0 = cl & (HD - 1);
                    size_t o = (((size_t)(bb * H_NUM + h)) * T_DIM + t) * HD + hd0;
                    *(float2*)(dst + o) = make_float2(v0, v1);
                    *(uint32_t*)(g_vp + o) = pack_h2(v0, v1);
                }
            }
        }
    }
}

// ===========================================================================
// RoPE + RMSNorm. y=0: q (scale folded) -> g_qp, y=1: k -> k_out fp32 + g_kp.
// ===========================================================================
__global__ void rope_norm_kernel(float* __restrict__ k_out)
{
    const int lane = threadIdx.x & 31;
    const int vec  = blockIdx.x * 8 + (threadIdx.x >> 5);
    const int t  = vec & (T_DIM - 1);
    const int bh = vec >> 10;
    const int b  = bh / H_NUM;
    const int h  = bh - b * H_NUM;
    const bool is_q = (blockIdx.y == 0);
    const size_t doff = ((size_t)bh * T_DIM + t) * HD;

    const __half* src = (is_q ? g_qg : g_kg) +
                        ((size_t)(b * T_DIM + t)) * C_DIM + h * HD;
    const float x1 = __half2float(src[lane]);
    const float x2 = __half2float(src[lane + 32]);

    const float inv = (float)exp((double)lane * -0.28782313662425575);
    const float f = (float)t * inv;
    float s, c;
    sincosf(f, &s, &c);
    const float o1 = x1 * c - x2 * s;
    const float o2 = x1 * s + x2 * c;

    float ss = o1 * o1 + o2 * o2;
#pragma unroll
    for (int off = 16; off; off >>= 1)
        ss += __shfl_xor_sync(0xffffffffu, ss, off);
    const float rn = rsqrtf(ss * (1.0f / 64.0f) + 1e-6f);

    if (is_q) {
        const float QSC = 0.125f * 1.4426950408889634f;
        g_qp[doff + lane]      = __float2half_rn(o1 * rn * QSC);
        g_qp[doff + lane + 32] = __float2half_rn(o2 * rn * QSC);
    } else {
        float k1 = o1 * rn, k2 = o2 * rn;
        k_out[doff + lane]      = k1;
        k_out[doff + lane + 32] = k2;
        g_kp[doff + lane]      = __float2half_rn(k1);
        g_kp[doff + lane + 32] = __float2half_rn(k2);
    }
}

// ===========================================================================
// fp16 flash attention (unchanged from R10).
// ===========================================================================
#define APLANE  16384
#define KVSTAGE (2 * APLANE)
#define ASMEM   (APLANE + 2 * KVSTAGE)

__global__ __launch_bounds__(256, 1)
void attn_mma(void)
{
    extern __shared__ __align__(1024) unsigned char sm8[];
    const uint32_t base = smem_u32(sm8);
    const uint32_t Qs = base;
    const uint32_t kvbase = base + APLANE;

    const int tid  = threadIdx.x;
    const int lane = tid & 31;
    const int wid  = tid >> 5;
    const int qt   = 7 - blockIdx.x;
    const int bh   = blockIdx.y;
    const int b    = bh / H_NUM;
    const int h    = bh - b * H_NUM;
    const int q0   = qt * 128;
    const int wr0  = wid * 16;

    const __half* q_g = g_qp + (size_t)bh * T_DIM * HD;
    const __half* k_g = g_kp + (size_t)bh * T_DIM * HD;
    const __half* v_g = g_vp + (size_t)bh * T_DIM * HD;

    auto copy_kv = [&](int kt, uint32_t st) {
        const int k0 = kt * 128;
#pragma unroll
        for (int i = 0; i < 4; i++) {
            int idx = tid + i * 256;
            int r = idx >> 3, sg = idx & 7;
            uint32_t so = aswz(r, sg);
            size_t go = (size_t)(k0 + r) * HD + sg * 8;
            cpa16(st + so,          k_g + go);
            cpa16(st + APLANE + so, v_g + go);
        }
    };

#pragma unroll
    for (int i = 0; i < 4; i++) {
        int idx = tid + i * 256;
        int r = idx >> 3, sg = idx & 7;
        uint32_t so = aswz(r, sg);
        cpa16(Qs + so, q_g + (size_t)(q0 + r) * HD + sg * 8);
    }
    copy_kv(0, kvbase);
    CP_COMMIT();

    float o[8][4];
#pragma unroll
    for (int i = 0; i < 8; i++)
#pragma unroll
        for (int j = 0; j < 4; j++) o[i][j] = 0.0f;
    float m_a = -INFINITY, m_b = -INFINITY, l_a = 0.0f, l_b = 0.0f;

    for (int kt = 0; kt <= qt; kt++) {
        const uint32_t st = kvbase + (uint32_t)(kt & 1) * KVSTAGE;
        if (kt < qt) {
            copy_kv(kt + 1, kvbase + (uint32_t)((kt + 1) & 1) * KVSTAGE);
            CP_COMMIT();
            CP_WAIT(1);
        } else {
            CP_WAIT(0);
        }
        __syncthreads();
        const uint32_t sK = st, sV = st + APLANE;

        float s[16][4];
#pragma unroll
        for (int i = 0; i < 16; i++)
#pragma unroll
            for (int j = 0; j < 4; j++) s[i][j] = 0.0f;

#pragma unroll
        for (int ks = 0; ks < 4; ks++) {
            int arow = wr0 + (lane & 15);
            int aseg = ks * 2 + (lane >> 4);
            uint32_t aoff = aswz(arow, aseg);
            uint32_t af[4];
            ldmx4(af[0], af[1], af[2], af[3], Qs + aoff);
#pragma unroll
            for (int np = 0; np < 8; np++) {
                int brow = np * 16 + (lane & 15);
                uint32_t boff = aswz(brow, aseg);
                uint32_t r0, r1, r2, r3;
                uint32_t bf[2][2];
                ldmx4(r0, r1, r2, r3, sK + boff);
                bf[0][0] = r0; bf[0][1] = r2; bf[1][0] = r1; bf[1][1] = r3;
#pragma unroll
                for (int g = 0; g < 2; g++)
                    mma_f16(s[np * 2 + g], af, bf[g]);
            }
        }

        if (kt == qt) {
            const int ra = (lane >> 2), cb = ((lane & 3) << 1);
#pragma unroll
            for (int nt = 0; nt < 16; nt++) {
#pragma unroll
                for (int j = 0; j < 4; j++) {
                    int col = nt * 8 + cb + (j & 1);
                    int row = wr0 + ra + ((j >> 1) << 3);
                    if (col > row) s[nt][j] = -INFINITY;
                }
            }
        }

        float mx_a = -INFINITY, mx_b = -INFINITY;
#pragma unroll
        for (int nt = 0; nt < 16; nt++) {
            mx_a = fmaxf(mx_a, fmaxf(s[nt][0], s[nt][1]));
            mx_b = fmaxf(mx_b, fmaxf(s[nt][2], s[nt][3]));
        }
        mx_a = fmaxf(mx_a, __shfl_xor_sync(0xffffffffu, mx_a, 1));
        mx_a = fmaxf(mx_a, __shfl_xor_sync(0xffffffffu, mx_a, 2));
        mx_b = fmaxf(mx_b, __shfl_xor_sync(0xffffffffu, mx_b, 1));
        mx_b = fmaxf(mx_b, __shfl_xor_sync(0xffffffffu, mx_b, 2));

        const float mn_a = fmaxf(m_a, mx_a);
        const float mn_b = fmaxf(m_b, mx_b);
        const float ca = ex2f(m_a - mn_a);
        const float cbf = ex2f(m_b - mn_b);
        m_a = mn_a; m_b = mn_b;

        float sa = 0.0f, sb = 0.0f;
#pragma unroll
        for (int nt = 0; nt < 16; nt++) {
            s[nt][0] = ex2f(s[nt][0] - mn_a);
            s[nt][1] = ex2f(s[nt][1] - mn_a);
            s[nt][2] = ex2f(s[nt][2] - mn_b);
            s[nt][3] = ex2f(s[nt][3] - mn_b);
            sa += s[nt][0] + s[nt][1];
            sb += s[nt][2] + s[nt][3];
        }
        sa += __shfl_xor_sync(0xffffffffu, sa, 1);
        sa += __shfl_xor_sync(0xffffffffu, sa, 2);
        sb += __shfl_xor_sync(0xffffffffu, sb, 1);
        sb += __shfl_xor_sync(0xffffffffu, sb, 2);
        l_a = l_a * ca + sa;
        l_b = l_b * cbf + sb;
#pragma unroll
        for (int i = 0; i < 8; i++) {
            o[i][0] *= ca; o[i][1] *= ca; o[i][2] *= cbf; o[i][3] *= cbf;
        }

#pragma unroll
        for (int kc = 0; kc < 8; kc++) {
            uint32_t pa[4];
            pa[0] = pack_h2(s[2*kc][0],   s[2*kc][1]);
            pa[1] = pack_h2(s[2*kc][2],   s[2*kc][3]);
            pa[2] = pack_h2(s[2*kc+1][0], s[2*kc+1][1]);
            pa[3] = pack_h2(s[2*kc+1][2], s[2*kc+1][3]);

            int vrow = kc * 16 + (lane & 15);
#pragma unroll
            for (int s2 = 0; s2 < 4; s2++) {
                int vseg = s2 * 2 + (lane >> 4);
                uint32_t voff = aswz(vrow, vseg);
                uint32_t r0, r1, r2, r3;
                uint32_t vf[2][2];
                ldmx4t(r0, r1, r2, r3, sV + voff);
                vf[0][0] = r0; vf[0][1] = r1; vf[1][0] = r2; vf[1][1] = r3;
#pragma unroll
                for (int g = 0; g < 2; g++)
                    mma_f16(o[s2 * 2 + g], pa, vf[g]);
            }
        }
        __syncthreads();
    }

    const float ia = 1.0f / l_a, ib = 1.0f / l_b;
    const int ra = lane >> 2, cb = (lane & 3) << 1;
    const size_t ybase = ((size_t)(b * T_DIM + q0 + wr0 + ra)) * C_DIM + h * HD;
#pragma unroll
    for (int nt = 0; nt < 8; nt++) {
        int col = nt * 8 + cb;
        *(uint32_t*)(g_yp + ybase + col) = pack_h2(o[nt][0] * ia, o[nt][1] * ia);
        *(uint32_t*)(g_yp + ybase + 8 * C_DIM + col) =
            pack_h2(o[nt][2] * ib, o[nt][3] * ib);
    }
}

// ---------------------------------------------------------------------------
extern "C" void kernel_launch(void* const* d_in, const int* in_sizes, int n_in,
                              void* d_out, int out_size)
{
    const float* x  = (const float*)d_in[0];
    const float* Wq = (const float*)d_in[1];
    const float* Wk = (const float*)d_in[2];
    const float* Wv = (const float*)d_in[3];
    const float* Wo = (const float*)d_in[4];

    float* out   = (float*)d_out;
    float* y_out = out;
    float* k_out = out + S_ELE;
    float* v_out = out + 2 * (size_t)S_ELE;

    cudaFuncSetAttribute(split_gemm2, cudaFuncAttributeMaxDynamicSharedMemorySize,
                         GSMEM);
    cudaFuncSetAttribute(attn_mma, cudaFuncAttributeMaxDynamicSharedMemorySize,
                         ASMEM);

    prep_convert<<<(PREP_F4 + 255) / 256, 256>>>(x, Wq, Wk, Wv, Wo);

    split_gemm2<<<dim3(C_DIM / 128, M_TOT / 128, 3), 256, GSMEM>>>(v_out, 1);

    rope_norm_kernel<<<dim3((B_DIM * H_NUM * T_DIM) / 8, 2), 256>>>(k_out);

    attn_mma<<<dim3(T_DIM / 128, B_DIM * H_NUM), 256, ASMEM>>>();

    split_gemm2<<<dim3(C_DIM / 128, M_TOT / 128, 1), 256, GSMEM>>>(y_out, 0);
}

// round 12
// speedup vs baseline: 7.5940x; 1.8562x over previous
#include <cuda_runtime.h>
#include <cuda_fp16.h>
#include <math.h>
#include <stdint.h>

#define C_DIM 768
#define T_DIM 1024
#define B_DIM 8
#define H_NUM 12
#define HD    64
#define M_TOT 8192
#define S_ELE 6291456   /* 8*1024*768 */
#define X_ELE 6291456
#define W_ELE 589824    /* 768*768 */

static __device__ __align__(16) __half g_x[X_ELE];
static __device__ __align__(16) __half g_w[4 * W_ELE];
static __device__ __align__(16) __half g_qp[S_ELE];
static __device__ __align__(16) __half g_kp[S_ELE];
static __device__ __align__(16) __half g_vp[S_ELE];
static __device__ __align__(16) __half g_yp[S_ELE];
static __device__ float g_inv[32];

__device__ __forceinline__ uint32_t smem_u32(const void* p) {
    uint32_t a;
    asm("{ .reg .u64 t; cvta.to.shared.u64 t, %1; cvt.u32.u64 %0, t; }"
        : "=r"(a) : "l"(p));
    return a;
}
__device__ __forceinline__ float ex2f(float x) {
    float r;
    asm("ex2.approx.ftz.f32 %0, %1;" : "=f"(r) : "f"(x));
    return r;
}
__device__ __forceinline__ uint32_t pack_h2(float lo, float hi) {
    uint32_t u;
    asm("cvt.rn.f16x2.f32 %0, %1, %2;" : "=r"(u) : "f"(hi), "f"(lo));
    return u;
}
__device__ __forceinline__ void cpa16(uint32_t dst, const void* src) {
    asm volatile("cp.async.cg.shared.global [%0], [%1], 16;"
                 :: "r"(dst), "l"(src) : "memory");
}
#define CP_COMMIT()  asm volatile("cp.async.commit_group;" ::: "memory")
#define CP_WAIT(n)   asm volatile("cp.async.wait_group %0;" :: "n"(n) : "memory")
__device__ __forceinline__ void ldmx4(uint32_t& r0, uint32_t& r1,
                                      uint32_t& r2, uint32_t& r3, uint32_t addr) {
    asm volatile("ldmatrix.sync.aligned.m8n8.x4.shared.b16 {%0,%1,%2,%3}, [%4];"
                 : "=r"(r0), "=r"(r1), "=r"(r2), "=r"(r3) : "r"(addr));
}
__device__ __forceinline__ void ldmx4t(uint32_t& r0, uint32_t& r1,
                                       uint32_t& r2, uint32_t& r3, uint32_t addr) {
    asm volatile("ldmatrix.sync.aligned.m8n8.x4.trans.shared.b16 {%0,%1,%2,%3}, [%4];"
                 : "=r"(r0), "=r"(r1), "=r"(r2), "=r"(r3) : "r"(addr));
}
__device__ __forceinline__ void mma_f16(float* c, const uint32_t* a,
                                        const uint32_t* b) {
    asm volatile(
        "mma.sync.aligned.m16n8k16.row.col.f32.f16.f16.f32 "
        "{%0,%1,%2,%3},{%4,%5,%6,%7},{%8,%9},{%0,%1,%2,%3};"
        : "+f"(c[0]), "+f"(c[1]), "+f"(c[2]), "+f"(c[3])
        : "r"(a[0]), "r"(a[1]), "r"(a[2]), "r"(a[3]), "r"(b[0]), "r"(b[1]));
}

__device__ __forceinline__ uint32_t aswz(int row, int seg) {
    return (uint32_t)(row * 128 + ((seg ^ (row & 7)) << 4));
}

// ===========================================================================
#define PREP_F4 ((X_ELE + 4 * W_ELE) / 4)
__global__ void prep_convert(const float* __restrict__ x,
                             const float* __restrict__ Wq,
                             const float* __restrict__ Wk,
                             const float* __restrict__ Wv,
                             const float* __restrict__ Wo)
{
    if (blockIdx.x == 0 && threadIdx.x < 32)
        g_inv[threadIdx.x] =
            (float)exp((double)threadIdx.x * -0.28782313662425575);

    size_t i4 = (size_t)blockIdx.x * 256 + threadIdx.x;
    if (i4 >= PREP_F4) return;
    size_t e = i4 * 4;
    if (e < X_ELE) {
        float4 v = *(const float4*)(x + e);
        *(uint2*)(g_x + e) = make_uint2(pack_h2(v.x, v.y), pack_h2(v.z, v.w));
    } else {
        size_t r = e - X_ELE;
        int w = (int)(r / W_ELE);
        size_t off = r - (size_t)w * W_ELE;
        const float* src = (w == 0) ? Wq : (w == 1) ? Wk : (w == 2) ? Wv : Wo;
        float4 v = *(const float4*)(src + off);
        *(uint2*)(g_w + (size_t)w * W_ELE + off) =
            make_uint2(pack_h2(v.x, v.y), pack_h2(v.z, v.w));
    }
}

// ===========================================================================
// fp16 GEMM + fused epilogues.
// is_qkv=1: z=0 q (rope->g_qp), z=1 k (rope->dst fp32 + g_kp), z=2 v
//           (dst+S_ELE fp32 + g_vp).  is_qkv=0: y -> dst fp32 (BTC).
// ===========================================================================
#define NCHUNK 12
#define GPLANE 16384
#define GSTAGE (2 * GPLANE)
#define GSMEM  (3 * GSTAGE)
#define EPAD   132

__global__ __launch_bounds__(256, 2)
void split_gemm2(float* __restrict__ dst, int is_qkv)
{
    extern __shared__ __align__(1024) unsigned char sm8[];
    const uint32_t base = smem_u32(sm8);
    const int tid  = threadIdx.x;
    const int lane = tid & 31;
    const int wid  = tid >> 5;
    const int wm   = wid >> 2;
    const int wn   = wid & 3;
    const int n0 = blockIdx.x * 128;
    const int m0 = blockIdx.y * 128;

    int mode;
    const __half *As, *Bs;
    if (is_qkv) {
        mode = blockIdx.z;
        As = g_x;
        Bs = g_w + (size_t)mode * W_ELE;
    } else {
        mode = 3;
        As = g_yp;
        Bs = g_w + 3 * (size_t)W_ELE;
    }
    As += (size_t)m0 * C_DIM;
    Bs += (size_t)n0 * C_DIM;

    float acc[16][4];
#pragma unroll
    for (int i = 0; i < 16; i++)
#pragma unroll
        for (int j = 0; j < 4; j++) acc[i][j] = 0.0f;

    auto copy_chunk = [&](int c, uint32_t st) {
        const int k0 = c * 64;
#pragma unroll
        for (int i = 0; i < 4; i++) {
            int idx = tid + i * 256;
            int r = idx >> 3, sg = idx & 7;
            uint32_t so = aswz(r, sg);
            size_t go = (size_t)r * C_DIM + k0 + sg * 8;
            cpa16(st + so,          As + go);
            cpa16(st + GPLANE + so, Bs + go);
        }
    };

    copy_chunk(0, base);
    CP_COMMIT();
    copy_chunk(1, base + GSTAGE);
    CP_COMMIT();

    for (int c = 0; c < NCHUNK; c++) {
        const uint32_t st = base + (uint32_t)(c % 3) * GSTAGE;
        if (c + 2 < NCHUNK) {
            copy_chunk(c + 2, base + (uint32_t)((c + 2) % 3) * GSTAGE);
            CP_COMMIT();
            CP_WAIT(2);
        } else if (c + 1 < NCHUNK) {
            CP_WAIT(1);
        } else {
            CP_WAIT(0);
        }
        __syncthreads();

#pragma unroll
        for (int ks = 0; ks < 4; ks++) {
            const int sg = 2 * ks + (lane >> 4);
            uint32_t bf[4][2];
#pragma unroll
            for (int g = 0; g < 2; g++) {
                int row = wn * 32 + g * 16 + (lane & 15);
                uint32_t off = aswz(row, sg);
                uint32_t r0, r1, r2, r3;
                ldmx4(r0, r1, r2, r3, st + GPLANE + off);
                bf[2 * g][0] = r0; bf[2 * g + 1][0] = r1;
                bf[2 * g][1] = r2; bf[2 * g + 1][1] = r3;
            }
#pragma unroll
            for (int mt = 0; mt < 4; mt++) {
                int row = wm * 64 + mt * 16 + (lane & 15);
                uint32_t off = aswz(row, sg);
                uint32_t af[4];
                ldmx4(af[0], af[1], af[2], af[3], st + off);
#pragma unroll
                for (int nt = 0; nt < 4; nt++)
                    mma_f16(acc[mt * 4 + nt], af, bf[nt]);
            }
        }
        __syncthreads();
    }

    if (mode <= 1) {
        // ---- fused rope+norm epilogue ----
        float* sp = (float*)sm8;
#pragma unroll
        for (int mt = 0; mt < 4; mt++) {
#pragma unroll
            for (int nt = 0; nt < 4; nt++) {
                const float* cc = acc[mt * 4 + nt];
                int col = wn * 32 + nt * 8 + ((lane & 3) << 1);
                int coff = col + ((col >> 6) << 1);
#pragma unroll
                for (int h2 = 0; h2 < 2; h2++) {
                    int row = wm * 64 + mt * 16 + (lane >> 2) + h2 * 8;
                    *(float2*)(sp + row * EPAD + coff) =
                        make_float2(cc[h2 * 2], cc[h2 * 2 + 1]);
                }
            }
        }
        __syncthreads();

        const int row = tid >> 1;
        const int hh  = tid & 1;
        const int m   = m0 + row;
        const int bb  = m >> 10, t = m & (T_DIM - 1);
        const int bh  = bb * H_NUM + (n0 >> 6) + hh;
        float* v = sp + row * EPAD + hh * 66;
        const float tf = (float)t;

        float ssum = 0.0f;
#pragma unroll
        for (int d = 0; d < 32; d++) {
            float sn, cs;
            sincosf(tf * g_inv[d], &sn, &cs);
            float a = v[d], b2 = v[d + 32];
            float o1 = a * cs - b2 * sn;
            float o2 = a * sn + b2 * cs;
            v[d] = o1; v[d + 32] = o2;
            ssum += o1 * o1 + o2 * o2;
        }
        const float rn = rsqrtf(ssum * (1.0f / 64.0f) + 1e-6f);
        const size_t doff = ((size_t)bh * T_DIM + t) * HD;

        if (mode == 0) {
            const float sc = rn * (0.125f * 1.4426950408889634f);
#pragma unroll
            for (int j = 0; j < 32; j++)
                *(uint32_t*)(g_qp + doff + 2 * j) =
                    pack_h2(v[2 * j] * sc, v[2 * j + 1] * sc);
        } else {
#pragma unroll
            for (int j = 0; j < 32; j++) {
                float a = v[2 * j] * rn, b2 = v[2 * j + 1] * rn;
                *(float2*)(dst + doff + 2 * j) = make_float2(a, b2);
                *(uint32_t*)(g_kp + doff + 2 * j) = pack_h2(a, b2);
            }
        }
        return;
    }

#pragma unroll
    for (int mt = 0; mt < 4; mt++) {
#pragma unroll
        for (int nt = 0; nt < 4; nt++) {
            const float* cc = acc[mt * 4 + nt];
            int r  = m0 + wm * 64 + mt * 16 + (lane >> 2);
            int cl = n0 + wn * 32 + nt * 8 + ((lane & 3) << 1);
#pragma unroll
            for (int h2 = 0; h2 < 2; h2++) {
                int rr = r + h2 * 8;
                float v0 = cc[h2 * 2], v1 = cc[h2 * 2 + 1];
                if (mode == 3) {
                    *(float2*)(dst + (size_t)rr * C_DIM + cl) = make_float2(v0, v1);
                } else {
                    const int bb = rr >> 10, t = rr & (T_DIM - 1);
                    const int h = cl >> 6, hd0 = cl & (HD - 1);
                    size_t o = (((size_t)(bb * H_NUM + h)) * T_DIM + t) * HD + hd0;
                    *(float2*)(dst + S_ELE + o) = make_float2(v0, v1);  // v_out
                    *(uint32_t*)(g_vp + o) = pack_h2(v0, v1);
                }
            }
        }
    }
}

// ===========================================================================
// fp16 flash attention (unchanged).
// ===========================================================================
#define APLANE  16384
#define KVSTAGE (2 * APLANE)
#define ASMEM   (APLANE + 2 * KVSTAGE)

__global__ __launch_bounds__(256, 1)
void attn_mma(void)
{
    extern __shared__ __align__(1024) unsigned char sm8[];
    const uint32_t base = smem_u32(sm8);
    const uint32_t Qs = base;
    const uint32_t kvbase = base + APLANE;

    const int tid  = threadIdx.x;
    const int lane = tid & 31;
    const int wid  = tid >> 5;
    const int qt   = 7 - blockIdx.x;
    const int bh   = blockIdx.y;
    const int b    = bh / H_NUM;
    const int h    = bh - b * H_NUM;
    const int q0   = qt * 128;
    const int wr0  = wid * 16;

    const __half* q_g = g_qp + (size_t)bh * T_DIM * HD;
    const __half* k_g = g_kp + (size_t)bh * T_DIM * HD;
    const __half* v_g = g_vp + (size_t)bh * T_DIM * HD;

    auto copy_kv = [&](int kt, uint32_t st) {
        const int k0 = kt * 128;
#pragma unroll
        for (int i = 0; i < 4; i++) {
            int idx = tid + i * 256;
            int r = idx >> 3, sg = idx & 7;
            uint32_t so = aswz(r, sg);
            size_t go = (size_t)(k0 + r) * HD + sg * 8;
            cpa16(st + so,          k_g + go);
            cpa16(st + APLANE + so, v_g + go);
        }
    };

#pragma unroll
    for (int i = 0; i < 4; i++) {
        int idx = tid + i * 256;
        int r = idx >> 3, sg = idx & 7;
        uint32_t so = aswz(r, sg);
        cpa16(Qs + so, q_g + (size_t)(q0 + r) * HD + sg * 8);
    }
    copy_kv(0, kvbase);
    CP_COMMIT();

    float o[8][4];
#pragma unroll
    for (int i = 0; i < 8; i++)
#pragma unroll
        for (int j = 0; j < 4; j++) o[i][j] = 0.0f;
    float m_a = -INFINITY, m_b = -INFINITY, l_a = 0.0f, l_b = 0.0f;

    for (int kt = 0; kt <= qt; kt++) {
        const uint32_t st = kvbase + (uint32_t)(kt & 1) * KVSTAGE;
        if (kt < qt) {
            copy_kv(kt + 1, kvbase + (uint32_t)((kt + 1) & 1) * KVSTAGE);
            CP_COMMIT();
            CP_WAIT(1);
        } else {
            CP_WAIT(0);
        }
        __syncthreads();
        const uint32_t sK = st, sV = st + APLANE;

        float s[16][4];
#pragma unroll
        for (int i = 0; i < 16; i++)
#pragma unroll
            for (int j = 0; j < 4; j++) s[i][j] = 0.0f;

#pragma unroll
        for (int ks = 0; ks < 4; ks++) {
            int arow = wr0 + (lane & 15);
            int aseg = ks * 2 + (lane >> 4);
            uint32_t aoff = aswz(arow, aseg);
            uint32_t af[4];
            ldmx4(af[0], af[1], af[2], af[3], Qs + aoff);
#pragma unroll
            for (int np = 0; np < 8; np++) {
                int brow = np * 16 + (lane & 15);
                uint32_t boff = aswz(brow, aseg);
                uint32_t r0, r1, r2, r3;
                uint32_t bf[2][2];
                ldmx4(r0, r1, r2, r3, sK + boff);
                bf[0][0] = r0; bf[0][1] = r2; bf[1][0] = r1; bf[1][1] = r3;
#pragma unroll
                for (int g = 0; g < 2; g++)
                    mma_f16(s[np * 2 + g], af, bf[g]);
            }
        }

        if (kt == qt) {
            const int ra = (lane >> 2), cb = ((lane & 3) << 1);
#pragma unroll
            for (int nt = 0; nt < 16; nt++) {
#pragma unroll
                for (int j = 0; j < 4; j++) {
                    int col = nt * 8 + cb + (j & 1);
                    int row = wr0 + ra + ((j >> 1) << 3);
                    if (col > row) s[nt][j] = -INFINITY;
                }
            }
        }

        float mx_a = -INFINITY, mx_b = -INFINITY;
#pragma unroll
        for (int nt = 0; nt < 16; nt++) {
            mx_a = fmaxf(mx_a, fmaxf(s[nt][0], s[nt][1]));
            mx_b = fmaxf(mx_b, fmaxf(s[nt][2], s[nt][3]));
        }
        mx_a = fmaxf(mx_a, __shfl_xor_sync(0xffffffffu, mx_a, 1));
        mx_a = fmaxf(mx_a, __shfl_xor_sync(0xffffffffu, mx_a, 2));
        mx_b = fmaxf(mx_b, __shfl_xor_sync(0xffffffffu, mx_b, 1));
        mx_b = fmaxf(mx_b, __shfl_xor_sync(0xffffffffu, mx_b, 2));

        const float mn_a = fmaxf(m_a, mx_a);
        const float mn_b = fmaxf(m_b, mx_b);
        const float ca = ex2f(m_a - mn_a);
        const float cbf = ex2f(m_b - mn_b);
        m_a = mn_a; m_b = mn_b;

        float sa = 0.0f, sb = 0.0f;
#pragma unroll
        for (int nt = 0; nt < 16; nt++) {
            s[nt][0] = ex2f(s[nt][0] - mn_a);
            s[nt][1] = ex2f(s[nt][1] - mn_a);
            s[nt][2] = ex2f(s[nt][2] - mn_b);
            s[nt][3] = ex2f(s[nt][3] - mn_b);
            sa += s[nt][0] + s[nt][1];
            sb += s[nt][2] + s[nt][3];
        }
        sa += __shfl_xor_sync(0xffffffffu, sa, 1);
        sa += __shfl_xor_sync(0xffffffffu, sa, 2);
        sb += __shfl_xor_sync(0xffffffffu, sb, 1);
        sb += __shfl_xor_sync(0xffffffffu, sb, 2);
        l_a = l_a * ca + sa;
        l_b = l_b * cbf + sb;
#pragma unroll
        for (int i = 0; i < 8; i++) {
            o[i][0] *= ca; o[i][1] *= ca; o[i][2] *= cbf; o[i][3] *= cbf;
        }

#pragma unroll
        for (int kc = 0; kc < 8; kc++) {
            uint32_t pa[4];
            pa[0] = pack_h2(s[2*kc][0],   s[2*kc][1]);
            pa[1] = pack_h2(s[2*kc][2],   s[2*kc][3]);
            pa[2] = pack_h2(s[2*kc+1][0], s[2*kc+1][1]);
            pa[3] = pack_h2(s[2*kc+1][2], s[2*kc+1][3]);

            int vrow = kc * 16 + (lane & 15);
#pragma unroll
            for (int s2 = 0; s2 < 4; s2++) {
                int vseg = s2 * 2 + (lane >> 4);
                uint32_t voff = aswz(vrow, vseg);
                uint32_t r0, r1, r2, r3;
                uint32_t vf[2][2];
                ldmx4t(r0, r1, r2, r3, sV + voff);
                vf[0][0] = r0; vf[0][1] = r1; vf[1][0] = r2; vf[1][1] = r3;
#pragma unroll
                for (int g = 0; g < 2; g++)
                    mma_f16(o[s2 * 2 + g], pa, vf[g]);
            }
        }
        __syncthreads();
    }

    const float ia = 1.0f / l_a, ib = 1.0f / l_b;
    const int ra = lane >> 2, cb = (lane & 3) << 1;
    const size_t ybase = ((size_t)(b * T_DIM + q0 + wr0 + ra)) * C_DIM + h * HD;
#pragma unroll
    for (int nt = 0; nt < 8; nt++) {
        int col = nt * 8 + cb;
        *(uint32_t*)(g_yp + ybase + col) = pack_h2(o[nt][0] * ia, o[nt][1] * ia);
        *(uint32_t*)(g_yp + ybase + 8 * C_DIM + col) =
            pack_h2(o[nt][2] * ib, o[nt][3] * ib);
    }
}

// ---------------------------------------------------------------------------
extern "C" void kernel_launch(void* const* d_in, const int* in_sizes, int n_in,
                              void* d_out, int out_size)
{
    const float* x  = (const float*)d_in[0];
    const float* Wq = (const float*)d_in[1];
    const float* Wk = (const float*)d_in[2];
    const float* Wv = (const float*)d_in[3];
    const float* Wo = (const float*)d_in[4];

    float* out   = (float*)d_out;
    float* y_out = out;
    float* k_out = out + S_ELE;   // v_out = k_out + S_ELE (contiguous)

    cudaFuncSetAttribute(split_gemm2, cudaFuncAttributeMaxDynamicSharedMemorySize,
                         GSMEM);
    cudaFuncSetAttribute(attn_mma, cudaFuncAttributeMaxDynamicSharedMemorySize,
                         ASMEM);

    prep_convert<<<(PREP_F4 + 255) / 256, 256>>>(x, Wq, Wk, Wv, Wo);

    split_gemm2<<<dim3(C_DIM / 128, M_TOT / 128, 3), 256, GSMEM>>>(k_out, 1);

    attn_mma<<<dim3(T_DIM / 128, B_DIM * H_NUM), 256, ASMEM>>>();

    split_gemm2<<<dim3(C_DIM / 128, M_TOT / 128, 1), 256, GSMEM>>>(y_out, 0);
}